// round 5
// baseline (speedup 1.0000x reference)
#include <cuda_runtime.h>
#include <cuda_bf16.h>
#include <math.h>
#include <stdint.h>

// ---------------------------------------------------------------------------
// Problem constants
// ---------------------------------------------------------------------------
#define TT   256
#define PP   256
#define EE   300
#define HH   256
#define NPOS 65536            // T*P
#define G4   1024             // 4H
#define D2H  512              // 2H
#define NC   4608             // 9 * 512 feature columns
#define MM   50000
#define CC   16384
#define EP   320              // E padded to multiple of 32

// ---------------------------------------------------------------------------
// Device scratch (static allocations only)
// ---------------------------------------------------------------------------
__device__ float    g_GxF[(size_t)NPOS * G4];          // 268 MB (packed cols j*4+g)
__device__ float    g_GxB[(size_t)NPOS * G4];          // 268 MB
__device__ float    g_Feat[(size_t)NPOS * NC];         // 1.21 GB
__device__ float    g_cstate[2 * PP * HH];
__device__ unsigned g_pairKeys[(size_t)3 * CC * D2H];  // 100 MB
__device__ unsigned g_triKeys[(size_t)CC * D2H];       // 33 MB
__device__ float    g_pv[(size_t)3 * CC * D2H];        // 100 MB
__device__ float    g_tv[(size_t)CC * D2H];            // 33 MB
__device__ float    g_final[(size_t)CC * D2H];         // 33 MB
__device__ float    g_pbF[G4];                         // permuted biases
__device__ float    g_pbB[G4];

// bf16 split operand buffers
__device__ __nv_bfloat16 g_xHi[(size_t)NPOS * EP];     // 42 MB
__device__ __nv_bfloat16 g_xLo[(size_t)NPOS * EP];
__device__ __nv_bfloat16 g_wHiF[(size_t)G4 * EP];      // packed rows j*4+g
__device__ __nv_bfloat16 g_wLoF[(size_t)G4 * EP];
__device__ __nv_bfloat16 g_wHiB[(size_t)G4 * EP];
__device__ __nv_bfloat16 g_wLoB[(size_t)G4 * EP];
__device__ __nv_bfloat16 g_whhHiF[(size_t)G4 * HH];    // packed rows j*4+g
__device__ __nv_bfloat16 g_whhLoF[(size_t)G4 * HH];
__device__ __nv_bfloat16 g_whhHiB[(size_t)G4 * HH];
__device__ __nv_bfloat16 g_whhLoB[(size_t)G4 * HH];
__device__ __nv_bfloat16 g_flatHi[(size_t)NPOS * D2H]; // 67 MB
__device__ __nv_bfloat16 g_flatLo[(size_t)NPOS * D2H];
__device__ __nv_bfloat16 g_BcHi[(size_t)NC * D2H];
__device__ __nv_bfloat16 g_BcLo[(size_t)NC * D2H];
__device__ __nv_bfloat16 g_aWHi[(size_t)D2H * 2048];
__device__ __nv_bfloat16 g_aWLo[(size_t)D2H * 2048];
__device__ __nv_bfloat16 g_ftHi[(size_t)CC * 2048];    // 67 MB
__device__ __nv_bfloat16 g_ftLo[(size_t)CC * 2048];

// ---------------------------------------------------------------------------
// Helpers
// ---------------------------------------------------------------------------
__device__ __forceinline__ uint32_t smem_u32(const void* p) {
    uint32_t a;
    asm("{ .reg .u64 t; cvta.to.shared.u64 t, %1; cvt.u32.u64 %0, t; }"
        : "=r"(a) : "l"(p));
    return a;
}

#define LDSM_X4(r, addr) \
    asm volatile("ldmatrix.sync.aligned.m8n8.x4.shared.b16 {%0,%1,%2,%3}, [%4];" \
        : "=r"((r)[0]), "=r"((r)[1]), "=r"((r)[2]), "=r"((r)[3]) : "r"(addr))

#define MMA_BF16(d, a, b) \
    asm volatile("mma.sync.aligned.m16n8k16.row.col.f32.bf16.bf16.f32 " \
        "{%0,%1,%2,%3}, {%4,%5,%6,%7}, {%8,%9}, {%0,%1,%2,%3};" \
        : "+f"((d)[0]), "+f"((d)[1]), "+f"((d)[2]), "+f"((d)[3]) \
        : "r"((a)[0]), "r"((a)[1]), "r"((a)[2]), "r"((a)[3]), \
          "r"((b)[0]), "r"((b)[1]))

#define CP_ASYNC16(dst, src) \
    asm volatile("cp.async.cg.shared.global [%0], [%1], 16;" \
                 :: "r"(dst), "l"(src))
#define CP_COMMIT() asm volatile("cp.async.commit_group;" ::: "memory")
#define CP_WAIT(n)  asm volatile("cp.async.wait_group %0;" :: "n"(n) : "memory")

__device__ __forceinline__ float sigmoidf_(float x) { return 1.0f / (1.0f + expf(-x)); }

__device__ __forceinline__ unsigned fmap(float f) {
    unsigned b = __float_as_uint(f);
    return (b & 0x80000000u) ? ~b : (b | 0x80000000u);
}
__device__ __forceinline__ float funmap(unsigned u) {
    return (u & 0x80000000u) ? __uint_as_float(u & 0x7FFFFFFFu)
                             : __uint_as_float(~u);
}
__device__ __forceinline__ float warpReduceSum(float v) {
    #pragma unroll
    for (int o = 16; o > 0; o >>= 1) v += __shfl_down_sync(0xffffffffu, v, o);
    return v;
}
__device__ __forceinline__ float blockReduceSum256(float v) {
    __shared__ float sh[8];
    int lane = threadIdx.x & 31, wid = threadIdx.x >> 5;
    v = warpReduceSum(v);
    if (lane == 0) sh[wid] = v;
    __syncthreads();
    v = (threadIdx.x < 8) ? sh[threadIdx.x] : 0.0f;
    if (wid == 0) v = warpReduceSum(v);
    return v;
}
__device__ __forceinline__ void splitbf(float f, __nv_bfloat16& h, __nv_bfloat16& l) {
    h = __float2bfloat16(f);
    l = __float2bfloat16(f - __bfloat162float(h));
}

// ---------------------------------------------------------------------------
// bf16 3-term split GEMM: C[M,N] = A[M,K] @ B[N,K]^T + bias
// CTA tile 128x256, 512 threads (16 warps as 2m x 8n; warp tile 64x32).
// 3-stage cp.async pipeline, K-chunk = 32. RSZ=80 (conflict-free ldmatrix).
// ---------------------------------------------------------------------------
#define RSZ     80
#define ST_AHI  0
#define ST_ALO  10240               // 128*80
#define ST_BHI  20480
#define ST_BLO  40960
#define STAGE_B 61440
#define SMEM_GEMM (3 * STAGE_B)     // 184320

__global__ __launch_bounds__(512, 1)
void gemm_bf16x3_kernel(const __nv_bfloat16* __restrict__ Ahi,
                        const __nv_bfloat16* __restrict__ Alo,
                        const __nv_bfloat16* __restrict__ Bhi,
                        const __nv_bfloat16* __restrict__ Blo,
                        const float* __restrict__ bias,
                        float* __restrict__ C, int K) {
    extern __shared__ char smem[];
    const uint32_t sb = smem_u32(smem);
    const int tid = threadIdx.x, lane = tid & 31, wid = tid >> 5;
    const int m0 = blockIdx.y * 128, n0 = blockIdx.x * 256;
    const int ldc = gridDim.x * 256;
    const int wm = wid & 1, wn = wid >> 1;

    float acc[4][4][4];
    #pragma unroll
    for (int i = 0; i < 4; ++i)
        #pragma unroll
        for (int j = 0; j < 4; ++j)
            #pragma unroll
            for (int q = 0; q < 4; ++q) acc[i][j][q] = 0.0f;

    const int nch = K >> 5;
    const int rA = tid >> 2, chA = tid & 3;
    const int rB0 = tid >> 2, cB0 = tid & 3;
    const int rB1 = (tid + 512) >> 2, cB1 = tid & 3;

    #define LOAD_STAGE(cc, st)                                                  \
    do {                                                                        \
        const int kb = (cc) << 5;                                               \
        const uint32_t dst = sb + (uint32_t)(st) * STAGE_B;                     \
        CP_ASYNC16(dst + ST_AHI + rA * RSZ + chA * 16,                          \
                   Ahi + (size_t)(m0 + rA) * K + kb + chA * 8);                 \
        CP_ASYNC16(dst + ST_ALO + rA * RSZ + chA * 16,                          \
                   Alo + (size_t)(m0 + rA) * K + kb + chA * 8);                 \
        CP_ASYNC16(dst + ST_BHI + rB0 * RSZ + cB0 * 16,                         \
                   Bhi + (size_t)(n0 + rB0) * K + kb + cB0 * 8);                \
        CP_ASYNC16(dst + ST_BHI + rB1 * RSZ + cB1 * 16,                         \
                   Bhi + (size_t)(n0 + rB1) * K + kb + cB1 * 8);                \
        CP_ASYNC16(dst + ST_BLO + rB0 * RSZ + cB0 * 16,                         \
                   Blo + (size_t)(n0 + rB0) * K + kb + cB0 * 8);                \
        CP_ASYNC16(dst + ST_BLO + rB1 * RSZ + cB1 * 16,                         \
                   Blo + (size_t)(n0 + rB1) * K + kb + cB1 * 8);                \
        CP_COMMIT();                                                            \
    } while (0)

    LOAD_STAGE(0, 0);
    if (nch > 1) LOAD_STAGE(1, 1);

    int st = 0;
    for (int c = 0; c < nch; ++c) {
        if (c + 2 < nch) {
            int st2 = st + 2; if (st2 >= 3) st2 -= 3;
            LOAD_STAGE(c + 2, st2);
            CP_WAIT(2);
        } else if (c + 1 < nch) {
            CP_WAIT(1);
        } else {
            CP_WAIT(0);
        }
        __syncthreads();

        const uint32_t s = sb + (uint32_t)st * STAGE_B;

        #pragma unroll
        for (int ks = 0; ks < 2; ++ks) {
            const uint32_t colOff = (uint32_t)(ks * 2 + (lane >> 4)) * 16;
            uint32_t aHi[4][4], bHi[4][2];
            #pragma unroll
            for (int mt = 0; mt < 4; ++mt) {
                uint32_t ad = (uint32_t)(wm * 64 + mt * 16 + (lane & 15)) * RSZ + colOff;
                LDSM_X4(aHi[mt], s + ST_AHI + ad);
            }
            #pragma unroll
            for (int nh = 0; nh < 2; ++nh) {
                uint32_t bd = (uint32_t)(wn * 32 + nh * 16 + (lane & 15)) * RSZ + colOff;
                uint32_t t[4];
                LDSM_X4(t, s + ST_BHI + bd);
                bHi[nh * 2 + 0][0] = t[0]; bHi[nh * 2 + 0][1] = t[2];
                bHi[nh * 2 + 1][0] = t[1]; bHi[nh * 2 + 1][1] = t[3];
            }
            #pragma unroll
            for (int mt = 0; mt < 4; ++mt)
                #pragma unroll
                for (int nt = 0; nt < 4; ++nt)
                    MMA_BF16(acc[mt][nt], aHi[mt], bHi[nt]);
            {
                uint32_t aLo[4][4];
                #pragma unroll
                for (int mt = 0; mt < 4; ++mt) {
                    uint32_t ad = (uint32_t)(wm * 64 + mt * 16 + (lane & 15)) * RSZ + colOff;
                    LDSM_X4(aLo[mt], s + ST_ALO + ad);
                }
                #pragma unroll
                for (int mt = 0; mt < 4; ++mt)
                    #pragma unroll
                    for (int nt = 0; nt < 4; ++nt)
                        MMA_BF16(acc[mt][nt], aLo[mt], bHi[nt]);
            }
            {
                uint32_t bLo[4][2];
                #pragma unroll
                for (int nh = 0; nh < 2; ++nh) {
                    uint32_t bd = (uint32_t)(wn * 32 + nh * 16 + (lane & 15)) * RSZ + colOff;
                    uint32_t t[4];
                    LDSM_X4(t, s + ST_BLO + bd);
                    bLo[nh * 2 + 0][0] = t[0]; bLo[nh * 2 + 0][1] = t[2];
                    bLo[nh * 2 + 1][0] = t[1]; bLo[nh * 2 + 1][1] = t[3];
                }
                #pragma unroll
                for (int mt = 0; mt < 4; ++mt)
                    #pragma unroll
                    for (int nt = 0; nt < 4; ++nt)
                        MMA_BF16(acc[mt][nt], aHi[mt], bLo[nt]);
            }
        }
        __syncthreads();
        if (++st >= 3) st -= 3;
    }

    const int rr = lane >> 2, cc2 = (lane & 3) * 2;
    #pragma unroll
    for (int mt = 0; mt < 4; ++mt) {
        #pragma unroll
        for (int nt = 0; nt < 4; ++nt) {
            int row = m0 + wm * 64 + mt * 16 + rr;
            int col = n0 + wn * 32 + nt * 8 + cc2;
            float b0 = 0.f, b1 = 0.f;
            if (bias) { b0 = bias[col]; b1 = bias[col + 1]; }
            float2 v0 = make_float2(acc[mt][nt][0] + b0, acc[mt][nt][1] + b1);
            float2 v1 = make_float2(acc[mt][nt][2] + b0, acc[mt][nt][3] + b1);
            *(float2*)&C[(size_t)row * ldc + col] = v0;
            *(float2*)&C[(size_t)(row + 8) * ldc + col] = v1;
        }
    }
    #undef LOAD_STAGE
}

// ---------------------------------------------------------------------------
// Pack kernels
// ---------------------------------------------------------------------------
// split/pad x
__global__ void split_pad_kernel(const float* __restrict__ src,
                                 __nv_bfloat16* __restrict__ hi,
                                 __nv_bfloat16* __restrict__ lo,
                                 int rows, int sk, int dk) {
    size_t total = (size_t)rows * dk;
    for (size_t idx = blockIdx.x * (size_t)blockDim.x + threadIdx.x; idx < total;
         idx += (size_t)gridDim.x * blockDim.x) {
        int r = (int)(idx / dk), c = (int)(idx % dk);
        float f = (c < sk) ? src[(size_t)r * sk + c] : 0.0f;
        __nv_bfloat16 h, l; splitbf(f, h, l);
        hi[idx] = h; lo[idx] = l;
    }
}

// wih: src row g*256+j -> dst row j*4+g, pad K to EP; also permute bias
__global__ void pack_wih_kernel(const float* __restrict__ wih,
                                const float* __restrict__ b,
                                __nv_bfloat16* __restrict__ hi,
                                __nv_bfloat16* __restrict__ lo,
                                float* __restrict__ pb) {
    const int total = G4 * EP;
    for (int idx = blockIdx.x * blockDim.x + threadIdx.x; idx < total;
         idx += gridDim.x * blockDim.x) {
        int rp = idx / EP, k = idx % EP;
        int j = rp >> 2, g = rp & 3;
        float f = (k < EE) ? wih[(size_t)(g * 256 + j) * EE + k] : 0.0f;
        __nv_bfloat16 h, l; splitbf(f, h, l);
        hi[idx] = h; lo[idx] = l;
        if (k == 0) pb[rp] = b[g * 256 + j];
    }
}

// whh: src row g*256+j -> dst row j*4+g, K=256
__global__ void pack_whh_kernel(const float* __restrict__ whh,
                                __nv_bfloat16* __restrict__ hi,
                                __nv_bfloat16* __restrict__ lo) {
    const int total = G4 * HH;
    for (int idx = blockIdx.x * blockDim.x + threadIdx.x; idx < total;
         idx += gridDim.x * blockDim.x) {
        int rp = idx >> 8, k = idx & 255;
        int j = rp >> 2, g = rp & 3;
        float v = whh[(size_t)(g * 256 + j) * HH + k];
        __nv_bfloat16 h, l; splitbf(v, h, l);
        hi[idx] = h; lo[idx] = l;
    }
}

__global__ void pack_bcatT_kernel(const float* __restrict__ pair_hW,
                                  const float* __restrict__ tri_hW,
                                  __nv_bfloat16* __restrict__ hi,
                                  __nv_bfloat16* __restrict__ lo) {
    const int total = NC * D2H;
    for (int idx = blockIdx.x * blockDim.x + threadIdx.x; idx < total;
         idx += gridDim.x * blockDim.x) {
        int n = idx >> 9, d = idx & 511;
        int q = n >> 9, c = n & 511;
        float v;
        if (q < 6) {
            int k = q >> 1, h = q & 1;
            v = pair_hW[(size_t)k * (G4 * D2H) + (size_t)(h * 512 + d) * D2H + c];
        } else {
            v = tri_hW[(size_t)((q - 6) * 512 + d) * D2H + c];
        }
        __nv_bfloat16 hh, ll; splitbf(v, hh, ll);
        hi[idx] = hh; lo[idx] = ll;
    }
}

__global__ void pack_allWT_kernel(const float* __restrict__ all_hW,
                                  __nv_bfloat16* __restrict__ hi,
                                  __nv_bfloat16* __restrict__ lo) {
    const int total = D2H * 2048;
    for (int idx = blockIdx.x * blockDim.x + threadIdx.x; idx < total;
         idx += gridDim.x * blockDim.x) {
        int n = idx >> 11, k = idx & 2047;
        float v = all_hW[(size_t)k * D2H + n];
        __nv_bfloat16 hh, ll; splitbf(v, hh, ll);
        hi[idx] = hh; lo[idx] = ll;
    }
}

__global__ void zero_keys_kernel(unsigned* __restrict__ pk, unsigned* __restrict__ tk) {
    const size_t np = (size_t)3 * CC * D2H;
    const size_t nt = (size_t)CC * D2H;
    for (size_t i = blockIdx.x * (size_t)blockDim.x + threadIdx.x; i < np + nt;
         i += (size_t)gridDim.x * blockDim.x) {
        if (i < np) pk[i] = 0u; else tk[i - np] = 0u;
    }
}

// ---------------------------------------------------------------------------
// HMMA LSTM step: per step, per dir: G = h_prev @ whhPk^T (+Gx), gates fused.
// Packed col layout: col = j*4 + g. grid (4 pTiles, 8 nTiles, 2 dirs), 256 thr
// (8 warps 2m x 4n; warp tile 32x32). 3-stage cp.async pipeline, KC=32.
// ---------------------------------------------------------------------------
#define LSA_HI 0
#define LSA_LO 5120
#define LSB_HI 10240
#define LSB_LO 20480
#define LSTAGE 30720
#define SMEM_LSTM (3 * LSTAGE)    // 92160

__global__ __launch_bounds__(256, 2)
void lstm_step2_kernel(const float* __restrict__ GxF, const float* __restrict__ GxB,
                       const __nv_bfloat16* __restrict__ whhHiF,
                       const __nv_bfloat16* __restrict__ whhLoF,
                       const __nv_bfloat16* __restrict__ whhHiB,
                       const __nv_bfloat16* __restrict__ whhLoB,
                       __nv_bfloat16* __restrict__ flatHi,
                       __nv_bfloat16* __restrict__ flatLo,
                       float* __restrict__ cstate, int s) {
    extern __shared__ char smem[];
    const uint32_t sb = smem_u32(smem);
    const int tid = threadIdx.x, lane = tid & 31, wid = tid >> 5;
    const int dir = blockIdx.z;
    const int tcur = dir ? (TT - 1 - s) : s;
    const int nprev = dir ? (tcur + 1) : (tcur - 1);
    const int p0 = blockIdx.x * 64;
    const int c0 = blockIdx.y * 128;
    const int hcol = dir * HH;
    const float* Gx = dir ? GxB : GxF;
    const __nv_bfloat16* Whi = dir ? whhHiB : whhHiF;
    const __nv_bfloat16* Wlo = dir ? whhLoB : whhLoF;
    const int wm = wid & 1, wn = wid >> 1;

    float acc[2][4][4];
    #pragma unroll
    for (int i = 0; i < 2; ++i)
        #pragma unroll
        for (int j = 0; j < 4; ++j)
            #pragma unroll
            for (int q = 0; q < 4; ++q) acc[i][j][q] = 0.0f;

    if (s > 0) {
        const int rA = tid >> 2, chA = tid & 3;      // A: 64 rows x 4 chunks
        const int rB = tid >> 1, cB = (tid & 1) * 2; // B: 128 rows x 2x2 chunks

        #define LLOAD(cc, st)                                                   \
        do {                                                                    \
            const int kb = (cc) << 5;                                           \
            const uint32_t dst = sb + (uint32_t)(st) * LSTAGE;                  \
            size_t asrc = (size_t)(nprev * PP + p0 + rA) * D2H + hcol + kb + chA * 8; \
            CP_ASYNC16(dst + LSA_HI + rA * RSZ + chA * 16, flatHi + asrc);      \
            CP_ASYNC16(dst + LSA_LO + rA * RSZ + chA * 16, flatLo + asrc);      \
            size_t bsrc = (size_t)(c0 + rB) * HH + kb + cB * 8;                 \
            CP_ASYNC16(dst + LSB_HI + rB * RSZ + cB * 16, Whi + bsrc);          \
            CP_ASYNC16(dst + LSB_HI + rB * RSZ + cB * 16 + 16, Whi + bsrc + 8); \
            CP_ASYNC16(dst + LSB_LO + rB * RSZ + cB * 16, Wlo + bsrc);          \
            CP_ASYNC16(dst + LSB_LO + rB * RSZ + cB * 16 + 16, Wlo + bsrc + 8); \
            CP_COMMIT();                                                        \
        } while (0)

        LLOAD(0, 0);
        LLOAD(1, 1);

        int st = 0;
        for (int c = 0; c < 8; ++c) {
            if (c + 2 < 8) {
                int st2 = st + 2; if (st2 >= 3) st2 -= 3;
                LLOAD(c + 2, st2);
                CP_WAIT(2);
            } else if (c + 1 < 8) {
                CP_WAIT(1);
            } else {
                CP_WAIT(0);
            }
            __syncthreads();

            const uint32_t sp = sb + (uint32_t)st * LSTAGE;
            #pragma unroll
            for (int ks = 0; ks < 2; ++ks) {
                const uint32_t colOff = (uint32_t)(ks * 2 + (lane >> 4)) * 16;
                uint32_t aHi[2][4], bHi[4][2];
                #pragma unroll
                for (int mt = 0; mt < 2; ++mt) {
                    uint32_t ad = (uint32_t)(wm * 32 + mt * 16 + (lane & 15)) * RSZ + colOff;
                    LDSM_X4(aHi[mt], sp + LSA_HI + ad);
                }
                #pragma unroll
                for (int nh = 0; nh < 2; ++nh) {
                    uint32_t bd = (uint32_t)(wn * 32 + nh * 16 + (lane & 15)) * RSZ + colOff;
                    uint32_t t[4];
                    LDSM_X4(t, sp + LSB_HI + bd);
                    bHi[nh * 2 + 0][0] = t[0]; bHi[nh * 2 + 0][1] = t[2];
                    bHi[nh * 2 + 1][0] = t[1]; bHi[nh * 2 + 1][1] = t[3];
                }
                #pragma unroll
                for (int mt = 0; mt < 2; ++mt)
                    #pragma unroll
                    for (int nt = 0; nt < 4; ++nt)
                        MMA_BF16(acc[mt][nt], aHi[mt], bHi[nt]);
                {
                    uint32_t aLo[2][4];
                    #pragma unroll
                    for (int mt = 0; mt < 2; ++mt) {
                        uint32_t ad = (uint32_t)(wm * 32 + mt * 16 + (lane & 15)) * RSZ + colOff;
                        LDSM_X4(aLo[mt], sp + LSA_LO + ad);
                    }
                    #pragma unroll
                    for (int mt = 0; mt < 2; ++mt)
                        #pragma unroll
                        for (int nt = 0; nt < 4; ++nt)
                            MMA_BF16(acc[mt][nt], aLo[mt], bHi[nt]);
                }
                {
                    uint32_t bLo[4][2];
                    #pragma unroll
                    for (int nh = 0; nh < 2; ++nh) {
                        uint32_t bd = (uint32_t)(wn * 32 + nh * 16 + (lane & 15)) * RSZ + colOff;
                        uint32_t t[4];
                        LDSM_X4(t, sp + LSB_LO + bd);
                        bLo[nh * 2 + 0][0] = t[0]; bLo[nh * 2 + 0][1] = t[2];
                        bLo[nh * 2 + 1][0] = t[1]; bLo[nh * 2 + 1][1] = t[3];
                    }
                    #pragma unroll
                    for (int mt = 0; mt < 2; ++mt)
                        #pragma unroll
                        for (int nt = 0; nt < 4; ++nt)
                            MMA_BF16(acc[mt][nt], aHi[mt], bLo[nt]);
                }
            }
            __syncthreads();
            if (++st >= 3) st -= 3;
        }
        #undef LLOAD
    }

    // ---- epilogue: +Gx, gate exchange via shfl_xor(1), LSTM cell, split h ----
    const int rr = lane >> 2, cpair = (lane & 3) * 2;
    const bool evenT = ((cpair & 3) == 0);
    #pragma unroll
    for (int mt = 0; mt < 2; ++mt) {
        #pragma unroll
        for (int nt = 0; nt < 4; ++nt) {
            int prow = p0 + wm * 32 + mt * 16 + rr;
            int col = c0 + wn * 32 + nt * 8 + cpair;
            int j = col >> 2;
            size_t n0i = (size_t)tcur * PP + prow;
            size_t n1i = n0i + 8;
            float2 g0 = *(const float2*)&Gx[n0i * G4 + col];
            float2 g1 = *(const float2*)&Gx[n1i * G4 + col];
            float v0 = acc[mt][nt][0] + g0.x;
            float v1 = acc[mt][nt][1] + g0.y;
            float v2 = acc[mt][nt][2] + g1.x;
            float v3 = acc[mt][nt][3] + g1.y;
            float w0 = __shfl_xor_sync(0xffffffffu, v0, 1);
            float w1 = __shfl_xor_sync(0xffffffffu, v1, 1);
            float w2 = __shfl_xor_sync(0xffffffffu, v2, 1);
            float w3 = __shfl_xor_sync(0xffffffffu, v3, 1);
            // even lane holds (i,f); odd holds (g,o). Even handles row prow,
            // odd handles row prow+8.
            float I, F, G, O;
            int p;
            if (evenT) { I = v0; F = v1; G = w0; O = w1; p = prow; }
            else       { I = w2; F = w3; G = v2; O = v3; p = prow + 8; }
            size_t ci = (size_t)dir * (PP * HH) + (size_t)p * HH + j;
            float cold = (s == 0) ? 0.0f : cstate[ci];
            float cn = sigmoidf_(F) * cold + sigmoidf_(I) * tanhf(G);
            float h = sigmoidf_(O) * tanhf(cn);
            cstate[ci] = cn;
            size_t nn = (size_t)tcur * PP + p;
            __nv_bfloat16 hh, hl; splitbf(h, hh, hl);
            flatHi[nn * D2H + hcol + j] = hh;
            flatLo[nn * D2H + hcol + j] = hl;
        }
    }
}

// ---------------------------------------------------------------------------
// Scatter-max kernels
// ---------------------------------------------------------------------------
__global__ void pair_scatter_kernel(const float* __restrict__ Feat,
                                    const int* __restrict__ occ1,
                                    const int* __restrict__ occ2,
                                    const int* __restrict__ seg,
                                    unsigned* __restrict__ keys) {
    const int b = blockIdx.x;
    const int k = b / MM, m = b % MM;
    const int o1 = occ1[k * MM + m];
    const int o2 = occ2[k * MM + m];
    const int sg = seg[k * MM + m];
    const float* f1 = Feat + (size_t)o1 * NC + (size_t)(2 * k) * 512;
    const float* f2 = Feat + (size_t)o2 * NC + (size_t)(2 * k + 1) * 512;
    unsigned* dst = keys + ((size_t)k * CC + sg) * D2H;
    const int c = threadIdx.x;
    float r = f1[c] + f2[c];
    atomicMax(&dst[c], fmap(r));
}

__global__ void tri_scatter_kernel(const float* __restrict__ Feat,
                                   const int* __restrict__ o1,
                                   const int* __restrict__ o2,
                                   const int* __restrict__ o3,
                                   const int* __restrict__ tseg,
                                   unsigned* __restrict__ keys) {
    const int m = blockIdx.x;
    const int a = o1[m], bb = o2[m], d = o3[m];
    const int sg = tseg[m];
    const float* f1 = Feat + (size_t)a * NC + 6 * 512;
    const float* f2 = Feat + (size_t)bb * NC + 7 * 512;
    const float* f3 = Feat + (size_t)d * NC + 8 * 512;
    unsigned* dst = keys + (size_t)sg * D2H;
    const int c = threadIdx.x;
    float r = f1[c] + f2[c] + f3[c];
    atomicMax(&dst[c], fmap(r));
}

// ---------------------------------------------------------------------------
// Finalize kernels
// ---------------------------------------------------------------------------
__global__ __launch_bounds__(256)
void pair_final_kernel(const unsigned* __restrict__ keys,
                       const float* __restrict__ hb,
                       const float* __restrict__ backoff,
                       const float* __restrict__ oW,
                       const float* __restrict__ ob,
                       float* __restrict__ pv, float* __restrict__ out) {
    const int b = blockIdx.x;
    const int k = b >> 14;
    const unsigned* src = keys + (size_t)b * D2H;
    float partial = 0.0f;
    #pragma unroll
    for (int it = 0; it < 2; ++it) {
        int c = threadIdx.x + it * 256;
        unsigned u = src[c];
        float val = u ? (funmap(u) + hb[k * D2H + c]) : backoff[k * D2H + c];
        float t = tanhf(val);
        pv[(size_t)b * D2H + c] = t;
        partial += t * oW[k * D2H + c];
    }
    float tot = blockReduceSum256(partial);
    if (threadIdx.x == 0) out[CC + b] = tot + ob[k];
}

__global__ __launch_bounds__(256)
void tri_final_kernel(const unsigned* __restrict__ keys,
                      const float* __restrict__ hb,
                      const float* __restrict__ backoff,
                      float* __restrict__ tv) {
    const int s = blockIdx.x;
    const unsigned* src = keys + (size_t)s * D2H;
    #pragma unroll
    for (int it = 0; it < 2; ++it) {
        int c = threadIdx.x + it * 256;
        unsigned u = src[c];
        float val = u ? (funmap(u) + hb[c]) : backoff[c];
        tv[(size_t)s * D2H + c] = tanhf(val);
    }
}

__global__ void gather_feats_kernel(const float* __restrict__ pv,
                                    const float* __restrict__ tv,
                                    const int* __restrict__ tpi,
                                    __nv_bfloat16* __restrict__ fhi,
                                    __nv_bfloat16* __restrict__ flo) {
    const int s = blockIdx.x;
    const int i0 = tpi[s * 3 + 0];
    const int i1 = tpi[s * 3 + 1];
    const int i2 = tpi[s * 3 + 2];
    for (int j = threadIdx.x; j < 2048; j += blockDim.x) {
        int q = j >> 9, c = j & 511;
        float v;
        if (q == 0)      v = pv[((size_t)2 * CC + i0) * D2H + c];
        else if (q == 1) v = pv[((size_t)1 * CC + i1) * D2H + c];
        else if (q == 2) v = pv[(size_t)i2 * D2H + c];
        else             v = tv[(size_t)s * D2H + c];
        __nv_bfloat16 h, l; splitbf(v, h, l);
        fhi[(size_t)s * 2048 + j] = h;
        flo[(size_t)s * 2048 + j] = l;
    }
}

__global__ __launch_bounds__(256)
void triple_logit_kernel(const float* __restrict__ fin,
                         const float* __restrict__ tW,
                         const float* __restrict__ tb,
                         float* __restrict__ out) {
    const int s = blockIdx.x;
    float partial = 0.0f;
    #pragma unroll
    for (int it = 0; it < 2; ++it) {
        int c = threadIdx.x + it * 256;
        float v = fin[(size_t)s * D2H + c];
        v = v > 0.0f ? v : 0.0f;
        partial += v * tW[c];
    }
    float tot = blockReduceSum256(partial);
    if (threadIdx.x == 0) out[s] = tot + tb[0];
}

// ---------------------------------------------------------------------------
// Launcher
// ---------------------------------------------------------------------------
extern "C" void kernel_launch(void* const* d_in, const int* in_sizes, int n_in,
                              void* d_out, int out_size) {
    const float* x        = (const float*)d_in[0];
    const float* wih_f    = (const float*)d_in[1];
    const float* whh_f    = (const float*)d_in[2];
    const float* b_f      = (const float*)d_in[3];
    const float* wih_b    = (const float*)d_in[4];
    const float* whh_b    = (const float*)d_in[5];
    const float* b_b      = (const float*)d_in[6];
    const float* pair_hW  = (const float*)d_in[7];
    const float* pair_hb  = (const float*)d_in[8];
    const float* pair_oW  = (const float*)d_in[9];
    const float* pair_ob  = (const float*)d_in[10];
    const float* pair_bo  = (const float*)d_in[11];
    const float* tri_hW   = (const float*)d_in[12];
    const float* tri_hb   = (const float*)d_in[13];
    const float* tri_bo   = (const float*)d_in[14];
    const float* all_hW   = (const float*)d_in[15];
    const float* all_hb   = (const float*)d_in[16];
    const float* out_tW   = (const float*)d_in[17];
    const float* out_tb   = (const float*)d_in[18];
    const int*   occ1     = (const int*)d_in[19];
    const int*   occ2     = (const int*)d_in[20];
    const int*   seg      = (const int*)d_in[21];
    const int*   tri_o1   = (const int*)d_in[22];
    const int*   tri_o2   = (const int*)d_in[23];
    const int*   tri_o3   = (const int*)d_in[24];
    const int*   tri_seg  = (const int*)d_in[25];
    const int*   tri_pi   = (const int*)d_in[26];
    float* out = (float*)d_out;

    float *GxF, *GxB, *Feat, *cst, *pv, *tv, *fin, *pbF, *pbB;
    unsigned *pk, *tk;
    __nv_bfloat16 *xHi, *xLo, *wHiF, *wLoF, *wHiB, *wLoB, *flHi, *flLo;
    __nv_bfloat16 *whF, *wlF, *whB, *wlB;
    __nv_bfloat16 *bcHi, *bcLo, *awHi, *awLo, *ftHi, *ftLo;
    cudaGetSymbolAddress((void**)&GxF,  g_GxF);
    cudaGetSymbolAddress((void**)&GxB,  g_GxB);
    cudaGetSymbolAddress((void**)&Feat, g_Feat);
    cudaGetSymbolAddress((void**)&cst,  g_cstate);
    cudaGetSymbolAddress((void**)&pk,   g_pairKeys);
    cudaGetSymbolAddress((void**)&tk,   g_triKeys);
    cudaGetSymbolAddress((void**)&pv,   g_pv);
    cudaGetSymbolAddress((void**)&tv,   g_tv);
    cudaGetSymbolAddress((void**)&fin,  g_final);
    cudaGetSymbolAddress((void**)&pbF,  g_pbF);
    cudaGetSymbolAddress((void**)&pbB,  g_pbB);
    cudaGetSymbolAddress((void**)&xHi,  g_xHi);
    cudaGetSymbolAddress((void**)&xLo,  g_xLo);
    cudaGetSymbolAddress((void**)&wHiF, g_wHiF);
    cudaGetSymbolAddress((void**)&wLoF, g_wLoF);
    cudaGetSymbolAddress((void**)&wHiB, g_wHiB);
    cudaGetSymbolAddress((void**)&wLoB, g_wLoB);
    cudaGetSymbolAddress((void**)&whF,  g_whhHiF);
    cudaGetSymbolAddress((void**)&wlF,  g_whhLoF);
    cudaGetSymbolAddress((void**)&whB,  g_whhHiB);
    cudaGetSymbolAddress((void**)&wlB,  g_whhLoB);
    cudaGetSymbolAddress((void**)&flHi, g_flatHi);
    cudaGetSymbolAddress((void**)&flLo, g_flatLo);
    cudaGetSymbolAddress((void**)&bcHi, g_BcHi);
    cudaGetSymbolAddress((void**)&bcLo, g_BcLo);
    cudaGetSymbolAddress((void**)&awHi, g_aWHi);
    cudaGetSymbolAddress((void**)&awLo, g_aWLo);
    cudaGetSymbolAddress((void**)&ftHi, g_ftHi);
    cudaGetSymbolAddress((void**)&ftLo, g_ftLo);

    cudaFuncSetAttribute(gemm_bf16x3_kernel,
                         cudaFuncAttributeMaxDynamicSharedMemorySize, SMEM_GEMM);
    cudaFuncSetAttribute(lstm_step2_kernel,
                         cudaFuncAttributeMaxDynamicSharedMemorySize, SMEM_LSTM);

    // idx0-2: split x, pack wih F/B (+ permuted biases)
    split_pad_kernel<<<4096, 256>>>(x, xHi, xLo, NPOS, EE, EP);
    pack_wih_kernel<<<512, 256>>>(wih_f, b_f, wHiF, wLoF, pbF);
    pack_wih_kernel<<<512, 256>>>(wih_b, b_b, wHiB, wLoB, pbB);

    // idx3-4: input projections (packed col layout j*4+g)
    gemm_bf16x3_kernel<<<dim3(4, 512), 512, SMEM_GEMM>>>(xHi, xLo, wHiF, wLoF, pbF, GxF, EP);
    gemm_bf16x3_kernel<<<dim3(4, 512), 512, SMEM_GEMM>>>(xHi, xLo, wHiB, wLoB, pbB, GxB, EP);

    // idx5-8: remaining packs + zero
    pack_whh_kernel<<<512, 256>>>(whh_f, whF, wlF);
    pack_whh_kernel<<<512, 256>>>(whh_b, whB, wlB);
    pack_bcatT_kernel<<<2304, 256>>>(pair_hW, tri_hW, bcHi, bcLo);
    pack_allWT_kernel<<<1024, 256>>>(all_hW, awHi, awLo);
    zero_keys_kernel<<<32768, 256>>>(pk, tk);

    // BiLSTM recurrence: 256 HMMA steps, gates fused
    for (int s = 0; s < TT; ++s)
        lstm_step2_kernel<<<dim3(4, 8, 2), 256, SMEM_LSTM>>>(
            GxF, GxB, whF, wlF, whB, wlB, flHi, flLo, cst, s);

    // dense feature transform: Feat = flat @ BcatT^T
    gemm_bf16x3_kernel<<<dim3(NC / 256, NPOS / 128), 512, SMEM_GEMM>>>(
        flHi, flLo, bcHi, bcLo, nullptr, Feat, D2H);

    // segment max pooling
    pair_scatter_kernel<<<3 * MM, 512>>>(Feat, occ1, occ2, seg, pk);
    tri_scatter_kernel<<<MM, 512>>>(Feat, tri_o1, tri_o2, tri_o3, tri_seg, tk);

    // finalize pooled vectors (+ pair logits)
    pair_final_kernel<<<3 * CC, 256>>>(pk, pair_hb, pair_bo, pair_oW, pair_ob, pv, out);
    tri_final_kernel<<<CC, 256>>>(tk, tri_hb, tri_bo, tv);

    // final MLP + triple logits
    gather_feats_kernel<<<CC, 256>>>(pv, tv, tri_pi, ftHi, ftLo);
    gemm_bf16x3_kernel<<<dim3(D2H / 256, CC / 128), 512, SMEM_GEMM>>>(
        ftHi, ftLo, awHi, awLo, all_hb, fin, 2048);
    triple_logit_kernel<<<CC, 256>>>(fin, out_tW, out_tb, out);
}

// round 6
// speedup vs baseline: 1.1593x; 1.1593x over previous
#include <cuda_runtime.h>
#include <cuda_bf16.h>
#include <math.h>
#include <stdint.h>

// ---------------------------------------------------------------------------
// Problem constants
// ---------------------------------------------------------------------------
#define TT   256
#define PP   256
#define EE   300
#define HH   256
#define NPOS 65536            // T*P
#define G4   1024             // 4H
#define D2H  512              // 2H
#define NC   4608             // 9 * 512 feature columns
#define MM   50000
#define CC   16384
#define EP   320              // E padded to multiple of 32

// ---------------------------------------------------------------------------
// Device scratch (static allocations only)
// ---------------------------------------------------------------------------
__device__ float    g_GxF[(size_t)NPOS * G4];          // 268 MB
__device__ float    g_GxB[(size_t)NPOS * G4];          // 268 MB
__device__ float    g_flat[(size_t)NPOS * D2H];        // 134 MB [hf | hb]
__device__ float    g_Feat[(size_t)NPOS * NC];         // 1.21 GB
__device__ float    g_cstate[2 * PP * HH];
__device__ unsigned g_pairKeys[(size_t)3 * CC * D2H];  // 100 MB
__device__ unsigned g_triKeys[(size_t)CC * D2H];       // 33 MB
__device__ float    g_pv[(size_t)3 * CC * D2H];        // 100 MB
__device__ float    g_tv[(size_t)CC * D2H];            // 33 MB
__device__ float    g_final[(size_t)CC * D2H];         // 33 MB

// bf16 split operand buffers
__device__ __nv_bfloat16 g_xHi[(size_t)NPOS * EP];     // 42 MB
__device__ __nv_bfloat16 g_xLo[(size_t)NPOS * EP];
__device__ __nv_bfloat16 g_wHiF[(size_t)G4 * EP];
__device__ __nv_bfloat16 g_wLoF[(size_t)G4 * EP];
__device__ __nv_bfloat16 g_wHiB[(size_t)G4 * EP];
__device__ __nv_bfloat16 g_wLoB[(size_t)G4 * EP];
__device__ __nv_bfloat16 g_flatHi[(size_t)NPOS * D2H]; // 67 MB
__device__ __nv_bfloat16 g_flatLo[(size_t)NPOS * D2H];
__device__ __nv_bfloat16 g_BcHi[(size_t)NC * D2H];
__device__ __nv_bfloat16 g_BcLo[(size_t)NC * D2H];
__device__ __nv_bfloat16 g_aWHi[(size_t)D2H * 2048];
__device__ __nv_bfloat16 g_aWLo[(size_t)D2H * 2048];
__device__ __nv_bfloat16 g_ftHi[(size_t)CC * 2048];    // 67 MB
__device__ __nv_bfloat16 g_ftLo[(size_t)CC * 2048];

// ---------------------------------------------------------------------------
// Helpers
// ---------------------------------------------------------------------------
__device__ __forceinline__ uint32_t smem_u32(const void* p) {
    uint32_t a;
    asm("{ .reg .u64 t; cvta.to.shared.u64 t, %1; cvt.u32.u64 %0, t; }"
        : "=r"(a) : "l"(p));
    return a;
}

#define LDSM_X4(r, addr) \
    asm volatile("ldmatrix.sync.aligned.m8n8.x4.shared.b16 {%0,%1,%2,%3}, [%4];" \
        : "=r"((r)[0]), "=r"((r)[1]), "=r"((r)[2]), "=r"((r)[3]) : "r"(addr))

#define MMA_BF16(d, a, b) \
    asm volatile("mma.sync.aligned.m16n8k16.row.col.f32.bf16.bf16.f32 " \
        "{%0,%1,%2,%3}, {%4,%5,%6,%7}, {%8,%9}, {%0,%1,%2,%3};" \
        : "+f"((d)[0]), "+f"((d)[1]), "+f"((d)[2]), "+f"((d)[3]) \
        : "r"((a)[0]), "r"((a)[1]), "r"((a)[2]), "r"((a)[3]), \
          "r"((b)[0]), "r"((b)[1]))

#define CP_ASYNC16(dst, src) \
    asm volatile("cp.async.cg.shared.global [%0], [%1], 16;" \
                 :: "r"(dst), "l"(src))
#define CP_COMMIT() asm volatile("cp.async.commit_group;" ::: "memory")
#define CP_WAIT(n)  asm volatile("cp.async.wait_group %0;" :: "n"(n) : "memory")

__device__ __forceinline__ float sigmoidf_(float x) { return 1.0f / (1.0f + expf(-x)); }

__device__ __forceinline__ unsigned fmap(float f) {
    unsigned b = __float_as_uint(f);
    return (b & 0x80000000u) ? ~b : (b | 0x80000000u);
}
__device__ __forceinline__ float funmap(unsigned u) {
    return (u & 0x80000000u) ? __uint_as_float(u & 0x7FFFFFFFu)
                             : __uint_as_float(~u);
}
__device__ __forceinline__ float warpReduceSum(float v) {
    #pragma unroll
    for (int o = 16; o > 0; o >>= 1) v += __shfl_down_sync(0xffffffffu, v, o);
    return v;
}
__device__ __forceinline__ float blockReduceSum256(float v) {
    __shared__ float sh[8];
    int lane = threadIdx.x & 31, wid = threadIdx.x >> 5;
    v = warpReduceSum(v);
    if (lane == 0) sh[wid] = v;
    __syncthreads();
    v = (threadIdx.x < 8) ? sh[threadIdx.x] : 0.0f;
    if (wid == 0) v = warpReduceSum(v);
    return v;
}
__device__ __forceinline__ void splitbf(float f, __nv_bfloat16& h, __nv_bfloat16& l) {
    h = __float2bfloat16(f);
    l = __float2bfloat16(f - __bfloat162float(h));
}

// ---------------------------------------------------------------------------
// bf16 3-term split GEMM: C[M,N] = A[M,K] @ B[N,K]^T + bias
// CTA tile 128x128, 256 threads (8 warps: 2 M x 4 N; warp tile 64x32).
// 2-stage cp.async pipeline, K-chunk = 32. RSZ=80 (conflict-free ldmatrix).
// __launch_bounds__(256, 2): force regs<=128 so 2 CTAs co-reside per SM
// (smem 80KB/CTA -> 160KB/SM) and interleave MMA with load/sync phases.
// ---------------------------------------------------------------------------
#define RSZ   80
#define TILEB (128 * RSZ)     // 10240
#define STAGE (4 * TILEB)     // 40960
#define SMEM_GEMM (2 * STAGE) // 81920

__global__ __launch_bounds__(256, 2)
void gemm_bf16x3_kernel(const __nv_bfloat16* __restrict__ Ahi,
                        const __nv_bfloat16* __restrict__ Alo,
                        const __nv_bfloat16* __restrict__ Bhi,
                        const __nv_bfloat16* __restrict__ Blo,
                        const float* __restrict__ bias,
                        float* __restrict__ C, int K) {
    extern __shared__ char smem[];
    const uint32_t sb = smem_u32(smem);
    const int tid = threadIdx.x, lane = tid & 31, wid = tid >> 5;
    const int m0 = blockIdx.y * 128, n0 = blockIdx.x * 128;
    const int ldc = gridDim.x * 128;
    const int wm = wid & 1, wn = wid >> 1;

    float acc[4][4][4];
    #pragma unroll
    for (int i = 0; i < 4; ++i)
        #pragma unroll
        for (int j = 0; j < 4; ++j)
            #pragma unroll
            for (int q = 0; q < 4; ++q) acc[i][j][q] = 0.0f;

    const int nch = K >> 5;

    // per-thread cp.async coords: 2 chunks per array per thread
    const int r0c = (2 * tid) >> 2, ch0 = (2 * tid) & 3;
    const int r1c = (2 * tid + 1) >> 2, ch1 = (2 * tid + 1) & 3;

    const int rA = lane & 15;
    const int cA = lane >> 4;

    #define LOAD_STAGE(cc)                                                      \
    do {                                                                        \
        const int kb = (cc) << 5;                                               \
        const uint32_t dst = sb + ((cc) & 1) * STAGE;                           \
        CP_ASYNC16(dst + 0 * TILEB + r0c * RSZ + ch0 * 16,                      \
                   Ahi + (size_t)(m0 + r0c) * K + kb + ch0 * 8);                \
        CP_ASYNC16(dst + 0 * TILEB + r1c * RSZ + ch1 * 16,                      \
                   Ahi + (size_t)(m0 + r1c) * K + kb + ch1 * 8);                \
        CP_ASYNC16(dst + 1 * TILEB + r0c * RSZ + ch0 * 16,                      \
                   Alo + (size_t)(m0 + r0c) * K + kb + ch0 * 8);                \
        CP_ASYNC16(dst + 1 * TILEB + r1c * RSZ + ch1 * 16,                      \
                   Alo + (size_t)(m0 + r1c) * K + kb + ch1 * 8);                \
        CP_ASYNC16(dst + 2 * TILEB + r0c * RSZ + ch0 * 16,                      \
                   Bhi + (size_t)(n0 + r0c) * K + kb + ch0 * 8);                \
        CP_ASYNC16(dst + 2 * TILEB + r1c * RSZ + ch1 * 16,                      \
                   Bhi + (size_t)(n0 + r1c) * K + kb + ch1 * 8);                \
        CP_ASYNC16(dst + 3 * TILEB + r0c * RSZ + ch0 * 16,                      \
                   Blo + (size_t)(n0 + r0c) * K + kb + ch0 * 8);                \
        CP_ASYNC16(dst + 3 * TILEB + r1c * RSZ + ch1 * 16,                      \
                   Blo + (size_t)(n0 + r1c) * K + kb + ch1 * 8);                \
        CP_COMMIT();                                                            \
    } while (0)

    LOAD_STAGE(0);

    for (int c = 0; c < nch; ++c) {
        if (c + 1 < nch) {
            LOAD_STAGE(c + 1);
            CP_WAIT(1);
        } else {
            CP_WAIT(0);
        }
        __syncthreads();

        const uint32_t s = sb + (c & 1) * STAGE;
        const uint32_t aHiB = s, aLoB = s + TILEB;
        const uint32_t bHiB = s + 2 * TILEB, bLoB = s + 3 * TILEB;

        #pragma unroll
        for (int ks = 0; ks < 2; ++ks) {
            const uint32_t colOff = (uint32_t)(ks * 2 + cA) * 16;
            uint32_t aHi[4][4], bHi[4][2];
            #pragma unroll
            for (int mt = 0; mt < 4; ++mt) {
                uint32_t ad = (uint32_t)(wm * 64 + mt * 16 + rA) * RSZ + colOff;
                LDSM_X4(aHi[mt], aHiB + ad);
            }
            #pragma unroll
            for (int nh = 0; nh < 2; ++nh) {
                uint32_t bd = (uint32_t)(wn * 32 + nh * 16 + rA) * RSZ + colOff;
                uint32_t t[4];
                LDSM_X4(t, bHiB + bd);
                bHi[nh * 2 + 0][0] = t[0]; bHi[nh * 2 + 0][1] = t[2];
                bHi[nh * 2 + 1][0] = t[1]; bHi[nh * 2 + 1][1] = t[3];
            }
            #pragma unroll
            for (int mt = 0; mt < 4; ++mt)
                #pragma unroll
                for (int nt = 0; nt < 4; ++nt)
                    MMA_BF16(acc[mt][nt], aHi[mt], bHi[nt]);
            {
                uint32_t aLo[4][4];
                #pragma unroll
                for (int mt = 0; mt < 4; ++mt) {
                    uint32_t ad = (uint32_t)(wm * 64 + mt * 16 + rA) * RSZ + colOff;
                    LDSM_X4(aLo[mt], aLoB + ad);
                }
                #pragma unroll
                for (int mt = 0; mt < 4; ++mt)
                    #pragma unroll
                    for (int nt = 0; nt < 4; ++nt)
                        MMA_BF16(acc[mt][nt], aLo[mt], bHi[nt]);
            }
            {
                uint32_t bLo[4][2];
                #pragma unroll
                for (int nh = 0; nh < 2; ++nh) {
                    uint32_t bd = (uint32_t)(wn * 32 + nh * 16 + rA) * RSZ + colOff;
                    uint32_t t[4];
                    LDSM_X4(t, bLoB + bd);
                    bLo[nh * 2 + 0][0] = t[0]; bLo[nh * 2 + 0][1] = t[2];
                    bLo[nh * 2 + 1][0] = t[1]; bLo[nh * 2 + 1][1] = t[3];
                }
                #pragma unroll
                for (int mt = 0; mt < 4; ++mt)
                    #pragma unroll
                    for (int nt = 0; nt < 4; ++nt)
                        MMA_BF16(acc[mt][nt], aHi[mt], bLo[nt]);
            }
        }
        __syncthreads();
    }

    // ---- epilogue ----
    const int rr = lane >> 2, cc2 = (lane & 3) * 2;
    #pragma unroll
    for (int mt = 0; mt < 4; ++mt) {
        #pragma unroll
        for (int nt = 0; nt < 4; ++nt) {
            int row = m0 + wm * 64 + mt * 16 + rr;
            int col = n0 + wn * 32 + nt * 8 + cc2;
            float b0 = 0.f, b1 = 0.f;
            if (bias) { b0 = bias[col]; b1 = bias[col + 1]; }
            float2 v0 = make_float2(acc[mt][nt][0] + b0, acc[mt][nt][1] + b1);
            float2 v1 = make_float2(acc[mt][nt][2] + b0, acc[mt][nt][3] + b1);
            *(float2*)&C[(size_t)row * ldc + col] = v0;
            *(float2*)&C[(size_t)(row + 8) * ldc + col] = v1;
        }
    }
    #undef LOAD_STAGE
}

// ---------------------------------------------------------------------------
// Split/pad fp32 -> bf16 hi/lo. dst rows x dk; src rows x sk (zero-pad c>=sk)
// ---------------------------------------------------------------------------
__global__ void split_pad_kernel(const float* __restrict__ src,
                                 __nv_bfloat16* __restrict__ hi,
                                 __nv_bfloat16* __restrict__ lo,
                                 int rows, int sk, int dk) {
    size_t total = (size_t)rows * dk;
    for (size_t idx = blockIdx.x * (size_t)blockDim.x + threadIdx.x; idx < total;
         idx += (size_t)gridDim.x * blockDim.x) {
        int r = (int)(idx / dk), c = (int)(idx % dk);
        float f = (c < sk) ? src[(size_t)r * sk + c] : 0.0f;
        __nv_bfloat16 h, l; splitbf(f, h, l);
        hi[idx] = h; lo[idx] = l;
    }
}

// ---------------------------------------------------------------------------
// Pack transposed concatenated pair/tri weights into bf16 hi/lo [NC,512]
// ---------------------------------------------------------------------------
__global__ void pack_bcatT_kernel(const float* __restrict__ pair_hW,
                                  const float* __restrict__ tri_hW,
                                  __nv_bfloat16* __restrict__ hi,
                                  __nv_bfloat16* __restrict__ lo) {
    const int total = NC * D2H;
    for (int idx = blockIdx.x * blockDim.x + threadIdx.x; idx < total;
         idx += gridDim.x * blockDim.x) {
        int n = idx >> 9, d = idx & 511;
        int q = n >> 9, c = n & 511;
        float v;
        if (q < 6) {
            int k = q >> 1, h = q & 1;
            v = pair_hW[(size_t)k * (G4 * D2H) + (size_t)(h * 512 + d) * D2H + c];
        } else {
            v = tri_hW[(size_t)((q - 6) * 512 + d) * D2H + c];
        }
        __nv_bfloat16 hh, ll; splitbf(v, hh, ll);
        hi[idx] = hh; lo[idx] = ll;
    }
}

// allWT [512,2048] bf16 hi/lo: allWT[n][k] = all_hW[k][n]
__global__ void pack_allWT_kernel(const float* __restrict__ all_hW,
                                  __nv_bfloat16* __restrict__ hi,
                                  __nv_bfloat16* __restrict__ lo) {
    const int total = D2H * 2048;
    for (int idx = blockIdx.x * blockDim.x + threadIdx.x; idx < total;
         idx += gridDim.x * blockDim.x) {
        int n = idx >> 11, k = idx & 2047;
        float v = all_hW[(size_t)k * D2H + n];
        __nv_bfloat16 hh, ll; splitbf(v, hh, ll);
        hi[idx] = hh; lo[idx] = ll;
    }
}

// ---------------------------------------------------------------------------
// Zero the segment-max key arrays
// ---------------------------------------------------------------------------
__global__ void zero_keys_kernel(unsigned* __restrict__ pk, unsigned* __restrict__ tk) {
    const size_t np = (size_t)3 * CC * D2H;
    const size_t nt = (size_t)CC * D2H;
    for (size_t i = blockIdx.x * (size_t)blockDim.x + threadIdx.x; i < np + nt;
         i += (size_t)gridDim.x * blockDim.x) {
        if (i < np) pk[i] = 0u; else tk[i - np] = 0u;
    }
}

// ---------------------------------------------------------------------------
// One recurrent step, both directions (fused GEMM + gates + bf16 split)
// ---------------------------------------------------------------------------
__global__ __launch_bounds__(256)
void lstm_step_kernel(const float* __restrict__ GxF, const float* __restrict__ GxB,
                      const float* __restrict__ whhF, const float* __restrict__ whhB,
                      float* __restrict__ flat,
                      __nv_bfloat16* __restrict__ flatHi,
                      __nv_bfloat16* __restrict__ flatLo,
                      float* __restrict__ cstate, int s) {
    const int dir = blockIdx.z;
    const int tcur = dir ? (TT - 1 - s) : s;
    const int p0 = blockIdx.x * 32;
    const int j0 = blockIdx.y * 32;
    const int tid = threadIdx.x, tx = tid & 31, tyy = tid >> 5;
    const float* Gx = dir ? GxB : GxF;
    const float* whh = dir ? whhB : whhF;
    const int hcol = dir * HH;
    const int nprevT = dir ? (tcur + 1) : (tcur - 1);

    __shared__ float Hs[32][36];
    __shared__ float Ws[4][32][33];

    float acc[4][4];
    #pragma unroll
    for (int i = 0; i < 4; ++i)
        #pragma unroll
        for (int g = 0; g < 4; ++g) acc[i][g] = 0.0f;

    for (int kt = 0; kt < 8; ++kt) {
        const int k0 = kt * 32;
        {
            int r = tid >> 3, c4 = (tid & 7) * 4;
            float4 v = make_float4(0.f, 0.f, 0.f, 0.f);
            if (s > 0)
                v = *(const float4*)&flat[(size_t)(nprevT * PP + p0 + r) * D2H + hcol + k0 + c4];
            *(float4*)&Hs[r][c4] = v;
        }
        #pragma unroll
        for (int i = 0; i < 4; ++i) {
            int lin = tid + i * 256;
            int g = lin >> 8, rest = lin & 255;
            int j = rest >> 3, c4 = (rest & 7) * 4;
            float4 w = *(const float4*)&whh[(size_t)(g * HH + j0 + j) * HH + k0 + c4];
            Ws[g][c4 + 0][j] = w.x;
            Ws[g][c4 + 1][j] = w.y;
            Ws[g][c4 + 2][j] = w.z;
            Ws[g][c4 + 3][j] = w.w;
        }
        __syncthreads();
        #pragma unroll
        for (int kk = 0; kk < 32; ++kk) {
            float b0 = Ws[0][kk][tx], b1 = Ws[1][kk][tx];
            float b2 = Ws[2][kk][tx], b3 = Ws[3][kk][tx];
            #pragma unroll
            for (int i = 0; i < 4; ++i) {
                float a = Hs[tyy + 8 * i][kk];
                acc[i][0] += a * b0;
                acc[i][1] += a * b1;
                acc[i][2] += a * b2;
                acc[i][3] += a * b3;
            }
        }
        __syncthreads();
    }

    const int j = j0 + tx;
    #pragma unroll
    for (int i = 0; i < 4; ++i) {
        const int p = p0 + tyy + 8 * i;
        const size_t n = (size_t)tcur * PP + p;
        float gi = acc[i][0] + Gx[n * G4 + 0 * HH + j];
        float gf = acc[i][1] + Gx[n * G4 + 1 * HH + j];
        float gg = acc[i][2] + Gx[n * G4 + 2 * HH + j];
        float go = acc[i][3] + Gx[n * G4 + 3 * HH + j];
        const size_t ci = (size_t)dir * (PP * HH) + (size_t)p * HH + j;
        float c = (s == 0) ? 0.0f : cstate[ci];
        float cn = sigmoidf_(gf) * c + sigmoidf_(gi) * tanhf(gg);
        float h = sigmoidf_(go) * tanhf(cn);
        cstate[ci] = cn;
        flat[n * D2H + hcol + j] = h;
        __nv_bfloat16 hh, hl; splitbf(h, hh, hl);
        flatHi[n * D2H + hcol + j] = hh;
        flatLo[n * D2H + hcol + j] = hl;
    }
}

// ---------------------------------------------------------------------------
// Scatter-max kernels
// ---------------------------------------------------------------------------
__global__ void pair_scatter_kernel(const float* __restrict__ Feat,
                                    const int* __restrict__ occ1,
                                    const int* __restrict__ occ2,
                                    const int* __restrict__ seg,
                                    unsigned* __restrict__ keys) {
    const int b = blockIdx.x;
    const int k = b / MM, m = b % MM;
    const int o1 = occ1[k * MM + m];
    const int o2 = occ2[k * MM + m];
    const int sg = seg[k * MM + m];
    const float* f1 = Feat + (size_t)o1 * NC + (size_t)(2 * k) * 512;
    const float* f2 = Feat + (size_t)o2 * NC + (size_t)(2 * k + 1) * 512;
    unsigned* dst = keys + ((size_t)k * CC + sg) * D2H;
    const int c = threadIdx.x;
    float r = f1[c] + f2[c];
    atomicMax(&dst[c], fmap(r));
}

__global__ void tri_scatter_kernel(const float* __restrict__ Feat,
                                   const int* __restrict__ o1,
                                   const int* __restrict__ o2,
                                   const int* __restrict__ o3,
                                   const int* __restrict__ tseg,
                                   unsigned* __restrict__ keys) {
    const int m = blockIdx.x;
    const int a = o1[m], bb = o2[m], d = o3[m];
    const int sg = tseg[m];
    const float* f1 = Feat + (size_t)a * NC + 6 * 512;
    const float* f2 = Feat + (size_t)bb * NC + 7 * 512;
    const float* f3 = Feat + (size_t)d * NC + 8 * 512;
    unsigned* dst = keys + (size_t)sg * D2H;
    const int c = threadIdx.x;
    float r = f1[c] + f2[c] + f3[c];
    atomicMax(&dst[c], fmap(r));
}

// ---------------------------------------------------------------------------
// Finalize kernels
// ---------------------------------------------------------------------------
__global__ __launch_bounds__(256)
void pair_final_kernel(const unsigned* __restrict__ keys,
                       const float* __restrict__ hb,
                       const float* __restrict__ backoff,
                       const float* __restrict__ oW,
                       const float* __restrict__ ob,
                       float* __restrict__ pv, float* __restrict__ out) {
    const int b = blockIdx.x;
    const int k = b >> 14;
    const unsigned* src = keys + (size_t)b * D2H;
    float partial = 0.0f;
    #pragma unroll
    for (int it = 0; it < 2; ++it) {
        int c = threadIdx.x + it * 256;
        unsigned u = src[c];
        float val = u ? (funmap(u) + hb[k * D2H + c]) : backoff[k * D2H + c];
        float t = tanhf(val);
        pv[(size_t)b * D2H + c] = t;
        partial += t * oW[k * D2H + c];
    }
    float tot = blockReduceSum256(partial);
    if (threadIdx.x == 0) out[CC + b] = tot + ob[k];
}

__global__ __launch_bounds__(256)
void tri_final_kernel(const unsigned* __restrict__ keys,
                      const float* __restrict__ hb,
                      const float* __restrict__ backoff,
                      float* __restrict__ tv) {
    const int s = blockIdx.x;
    const unsigned* src = keys + (size_t)s * D2H;
    #pragma unroll
    for (int it = 0; it < 2; ++it) {
        int c = threadIdx.x + it * 256;
        unsigned u = src[c];
        float val = u ? (funmap(u) + hb[c]) : backoff[c];
        tv[(size_t)s * D2H + c] = tanhf(val);
    }
}

// gather 8H features and split to bf16 hi/lo
__global__ void gather_feats_kernel(const float* __restrict__ pv,
                                    const float* __restrict__ tv,
                                    const int* __restrict__ tpi,
                                    __nv_bfloat16* __restrict__ fhi,
                                    __nv_bfloat16* __restrict__ flo) {
    const int s = blockIdx.x;
    const int i0 = tpi[s * 3 + 0];
    const int i1 = tpi[s * 3 + 1];
    const int i2 = tpi[s * 3 + 2];
    for (int j = threadIdx.x; j < 2048; j += blockDim.x) {
        int q = j >> 9, c = j & 511;
        float v;
        if (q == 0)      v = pv[((size_t)2 * CC + i0) * D2H + c];
        else if (q == 1) v = pv[((size_t)1 * CC + i1) * D2H + c];
        else if (q == 2) v = pv[(size_t)i2 * D2H + c];
        else             v = tv[(size_t)s * D2H + c];
        __nv_bfloat16 h, l; splitbf(v, h, l);
        fhi[(size_t)s * 2048 + j] = h;
        flo[(size_t)s * 2048 + j] = l;
    }
}

__global__ __launch_bounds__(256)
void triple_logit_kernel(const float* __restrict__ fin,
                         const float* __restrict__ tW,
                         const float* __restrict__ tb,
                         float* __restrict__ out) {
    const int s = blockIdx.x;
    float partial = 0.0f;
    #pragma unroll
    for (int it = 0; it < 2; ++it) {
        int c = threadIdx.x + it * 256;
        float v = fin[(size_t)s * D2H + c];
        v = v > 0.0f ? v : 0.0f;
        partial += v * tW[c];
    }
    float tot = blockReduceSum256(partial);
    if (threadIdx.x == 0) out[s] = tot + tb[0];
}

// ---------------------------------------------------------------------------
// Launcher
// ---------------------------------------------------------------------------
extern "C" void kernel_launch(void* const* d_in, const int* in_sizes, int n_in,
                              void* d_out, int out_size) {
    const float* x        = (const float*)d_in[0];
    const float* wih_f    = (const float*)d_in[1];
    const float* whh_f    = (const float*)d_in[2];
    const float* b_f      = (const float*)d_in[3];
    const float* wih_b    = (const float*)d_in[4];
    const float* whh_b    = (const float*)d_in[5];
    const float* b_b      = (const float*)d_in[6];
    const float* pair_hW  = (const float*)d_in[7];
    const float* pair_hb  = (const float*)d_in[8];
    const float* pair_oW  = (const float*)d_in[9];
    const float* pair_ob  = (const float*)d_in[10];
    const float* pair_bo  = (const float*)d_in[11];
    const float* tri_hW   = (const float*)d_in[12];
    const float* tri_hb   = (const float*)d_in[13];
    const float* tri_bo   = (const float*)d_in[14];
    const float* all_hW   = (const float*)d_in[15];
    const float* all_hb   = (const float*)d_in[16];
    const float* out_tW   = (const float*)d_in[17];
    const float* out_tb   = (const float*)d_in[18];
    const int*   occ1     = (const int*)d_in[19];
    const int*   occ2     = (const int*)d_in[20];
    const int*   seg      = (const int*)d_in[21];
    const int*   tri_o1   = (const int*)d_in[22];
    const int*   tri_o2   = (const int*)d_in[23];
    const int*   tri_o3   = (const int*)d_in[24];
    const int*   tri_seg  = (const int*)d_in[25];
    const int*   tri_pi   = (const int*)d_in[26];
    float* out = (float*)d_out;

    float *GxF, *GxB, *flat, *Feat, *cst, *pv, *tv, *fin;
    unsigned *pk, *tk;
    __nv_bfloat16 *xHi, *xLo, *wHiF, *wLoF, *wHiB, *wLoB, *flHi, *flLo;
    __nv_bfloat16 *bcHi, *bcLo, *awHi, *awLo, *ftHi, *ftLo;
    cudaGetSymbolAddress((void**)&GxF,  g_GxF);
    cudaGetSymbolAddress((void**)&GxB,  g_GxB);
    cudaGetSymbolAddress((void**)&flat, g_flat);
    cudaGetSymbolAddress((void**)&Feat, g_Feat);
    cudaGetSymbolAddress((void**)&cst,  g_cstate);
    cudaGetSymbolAddress((void**)&pk,   g_pairKeys);
    cudaGetSymbolAddress((void**)&tk,   g_triKeys);
    cudaGetSymbolAddress((void**)&pv,   g_pv);
    cudaGetSymbolAddress((void**)&tv,   g_tv);
    cudaGetSymbolAddress((void**)&fin,  g_final);
    cudaGetSymbolAddress((void**)&xHi,  g_xHi);
    cudaGetSymbolAddress((void**)&xLo,  g_xLo);
    cudaGetSymbolAddress((void**)&wHiF, g_wHiF);
    cudaGetSymbolAddress((void**)&wLoF, g_wLoF);
    cudaGetSymbolAddress((void**)&wHiB, g_wHiB);
    cudaGetSymbolAddress((void**)&wLoB, g_wLoB);
    cudaGetSymbolAddress((void**)&flHi, g_flatHi);
    cudaGetSymbolAddress((void**)&flLo, g_flatLo);
    cudaGetSymbolAddress((void**)&bcHi, g_BcHi);
    cudaGetSymbolAddress((void**)&bcLo, g_BcLo);
    cudaGetSymbolAddress((void**)&awHi, g_aWHi);
    cudaGetSymbolAddress((void**)&awLo, g_aWLo);
    cudaGetSymbolAddress((void**)&ftHi, g_ftHi);
    cudaGetSymbolAddress((void**)&ftLo, g_ftLo);

    cudaFuncSetAttribute(gemm_bf16x3_kernel,
                         cudaFuncAttributeMaxDynamicSharedMemorySize, SMEM_GEMM);

    // 1) split/pack operands to bf16 hi/lo
    split_pad_kernel<<<4096, 256>>>(x, xHi, xLo, NPOS, EE, EP);
    pack_bcatT_kernel<<<2304, 256>>>(pair_hW, tri_hW, bcHi, bcLo);
    split_pad_kernel<<<512, 256>>>(wih_f, wHiF, wLoF, G4, EE, EP);
    split_pad_kernel<<<512, 256>>>(wih_b, wHiB, wLoB, G4, EE, EP);
    pack_allWT_kernel<<<1024, 256>>>(all_hW, awHi, awLo);

    // 2) input projections: Gx = x @ wih^T + b   (N=1024 -> 8 col tiles)
    gemm_bf16x3_kernel<<<dim3(8, 512), 256, SMEM_GEMM>>>(xHi, xLo, wHiF, wLoF, b_f, GxF, EP);
    gemm_bf16x3_kernel<<<dim3(8, 512), 256, SMEM_GEMM>>>(xHi, xLo, wHiB, wLoB, b_b, GxB, EP);

    // 3) zero segment-max keys
    zero_keys_kernel<<<32768, 256>>>(pk, tk);

    // 4) BiLSTM recurrence (256 fused steps, bf16 split fused in epilogue)
    for (int s = 0; s < TT; ++s)
        lstm_step_kernel<<<dim3(PP / 32, HH / 32, 2), 256>>>(
            GxF, GxB, whh_f, whh_b, flat, flHi, flLo, cst, s);

    // 5) dense feature transform: Feat = flat @ BcatT^T  (N=4608 -> 36 tiles)
    gemm_bf16x3_kernel<<<dim3(NC / 128, NPOS / 128), 256, SMEM_GEMM>>>(
        flHi, flLo, bcHi, bcLo, nullptr, Feat, D2H);

    // 6) segment max pooling
    pair_scatter_kernel<<<3 * MM, 512>>>(Feat, occ1, occ2, seg, pk);
    tri_scatter_kernel<<<MM, 512>>>(Feat, tri_o1, tri_o2, tri_o3, tri_seg, tk);

    // 7) finalize pooled vectors (+ pair logits)
    pair_final_kernel<<<3 * CC, 256>>>(pk, pair_hb, pair_bo, pair_oW, pair_ob, pv, out);
    tri_final_kernel<<<CC, 256>>>(tk, tri_hb, tri_bo, tv);

    // 8) final MLP + triple logits   (N=512 -> 4 col tiles)
    gather_feats_kernel<<<CC, 256>>>(pv, tv, tri_pi, ftHi, ftLo);
    gemm_bf16x3_kernel<<<dim3(D2H / 128, CC / 128), 256, SMEM_GEMM>>>(
        ftHi, ftLo, awHi, awLo, all_hb, fin, 2048);
    triple_logit_kernel<<<CC, 256>>>(fin, out_tW, out_tb, out);
}

// round 7
// speedup vs baseline: 1.4938x; 1.2886x over previous
#include <cuda_runtime.h>
#include <cuda_bf16.h>
#include <math.h>
#include <stdint.h>

// ---------------------------------------------------------------------------
// Problem constants
// ---------------------------------------------------------------------------
#define TT   256
#define PP   256
#define EE   300
#define HH   256
#define NPOS 65536            // T*P
#define G4   1024             // 4H
#define D2H  512              // 2H
#define NC   4608             // 9 * 512 feature columns
#define MM   50000
#define CC   16384
#define EP   320              // E padded to multiple of 32

// ---------------------------------------------------------------------------
// Device scratch (static allocations only)
// ---------------------------------------------------------------------------
__device__ float    g_GxF[(size_t)NPOS * G4];          // 268 MB (cols j*4+g)
__device__ float    g_GxB[(size_t)NPOS * G4];          // 268 MB
__device__ float    g_Feat[(size_t)NPOS * NC];         // 1.21 GB
__device__ unsigned g_pairKeys[(size_t)3 * CC * D2H];  // 100 MB
__device__ unsigned g_triKeys[(size_t)CC * D2H];       // 33 MB
__device__ float    g_pv[(size_t)3 * CC * D2H];        // 100 MB
__device__ float    g_tv[(size_t)CC * D2H];            // 33 MB
__device__ float    g_final[(size_t)CC * D2H];         // 33 MB
__device__ float    g_pbF[G4];                         // permuted biases
__device__ float    g_pbB[G4];
__device__ unsigned g_barCnt[2];                       // global barrier state
__device__ unsigned g_barGen[2];

// bf16 split operand buffers
__device__ __nv_bfloat16 g_xHi[(size_t)NPOS * EP];     // 42 MB
__device__ __nv_bfloat16 g_xLo[(size_t)NPOS * EP];
__device__ __nv_bfloat16 g_wHiF[(size_t)G4 * EP];      // packed rows j*4+g
__device__ __nv_bfloat16 g_wLoF[(size_t)G4 * EP];
__device__ __nv_bfloat16 g_wHiB[(size_t)G4 * EP];
__device__ __nv_bfloat16 g_wLoB[(size_t)G4 * EP];
__device__ __nv_bfloat16 g_whhHiF[(size_t)G4 * HH];    // packed rows j*4+g
__device__ __nv_bfloat16 g_whhLoF[(size_t)G4 * HH];
__device__ __nv_bfloat16 g_whhHiB[(size_t)G4 * HH];
__device__ __nv_bfloat16 g_whhLoB[(size_t)G4 * HH];
__device__ __nv_bfloat16 g_flatHi[(size_t)NPOS * D2H]; // 67 MB
__device__ __nv_bfloat16 g_flatLo[(size_t)NPOS * D2H];
__device__ __nv_bfloat16 g_BcHi[(size_t)NC * D2H];
__device__ __nv_bfloat16 g_BcLo[(size_t)NC * D2H];
__device__ __nv_bfloat16 g_aWHi[(size_t)D2H * 2048];
__device__ __nv_bfloat16 g_aWLo[(size_t)D2H * 2048];
__device__ __nv_bfloat16 g_ftHi[(size_t)CC * 2048];    // 67 MB
__device__ __nv_bfloat16 g_ftLo[(size_t)CC * 2048];

// ---------------------------------------------------------------------------
// Helpers
// ---------------------------------------------------------------------------
__device__ __forceinline__ uint32_t smem_u32(const void* p) {
    uint32_t a;
    asm("{ .reg .u64 t; cvta.to.shared.u64 t, %1; cvt.u32.u64 %0, t; }"
        : "=r"(a) : "l"(p));
    return a;
}

#define LDSM_X4(r, addr) \
    asm volatile("ldmatrix.sync.aligned.m8n8.x4.shared.b16 {%0,%1,%2,%3}, [%4];" \
        : "=r"((r)[0]), "=r"((r)[1]), "=r"((r)[2]), "=r"((r)[3]) : "r"(addr))

#define MMA_BF16(d, a, b) \
    asm volatile("mma.sync.aligned.m16n8k16.row.col.f32.bf16.bf16.f32 " \
        "{%0,%1,%2,%3}, {%4,%5,%6,%7}, {%8,%9}, {%0,%1,%2,%3};" \
        : "+f"((d)[0]), "+f"((d)[1]), "+f"((d)[2]), "+f"((d)[3]) \
        : "r"((a)[0]), "r"((a)[1]), "r"((a)[2]), "r"((a)[3]), \
          "r"((b)[0]), "r"((b)[1]))

#define CP_ASYNC16(dst, src) \
    asm volatile("cp.async.cg.shared.global [%0], [%1], 16;" \
                 :: "r"(dst), "l"(src))
#define CP_COMMIT() asm volatile("cp.async.commit_group;" ::: "memory")
#define CP_WAIT(n)  asm volatile("cp.async.wait_group %0;" :: "n"(n) : "memory")

__device__ __forceinline__ float sigmoidf_(float x) { return 1.0f / (1.0f + expf(-x)); }

__device__ __forceinline__ unsigned fmap(float f) {
    unsigned b = __float_as_uint(f);
    return (b & 0x80000000u) ? ~b : (b | 0x80000000u);
}
__device__ __forceinline__ float funmap(unsigned u) {
    return (u & 0x80000000u) ? __uint_as_float(u & 0x7FFFFFFFu)
                             : __uint_as_float(~u);
}
__device__ __forceinline__ float warpReduceSum(float v) {
    #pragma unroll
    for (int o = 16; o > 0; o >>= 1) v += __shfl_down_sync(0xffffffffu, v, o);
    return v;
}
__device__ __forceinline__ float blockReduceSum256(float v) {
    __shared__ float sh[8];
    int lane = threadIdx.x & 31, wid = threadIdx.x >> 5;
    v = warpReduceSum(v);
    if (lane == 0) sh[wid] = v;
    __syncthreads();
    v = (threadIdx.x < 8) ? sh[threadIdx.x] : 0.0f;
    if (wid == 0) v = warpReduceSum(v);
    return v;
}
__device__ __forceinline__ void splitbf(float f, __nv_bfloat16& h, __nv_bfloat16& l) {
    h = __float2bfloat16(f);
    l = __float2bfloat16(f - __bfloat162float(h));
}

// per-direction grid barrier (sense via monotonically increasing generation)
__device__ __forceinline__ void dir_barrier(int dir, int tid, unsigned nCTA) {
    __syncthreads();
    if (tid == 0) {
        __threadfence();
        unsigned gen = atomicAdd(&g_barGen[dir], 0u);
        unsigned prev = atomicAdd(&g_barCnt[dir], 1u);
        if (prev == nCTA - 1u) {
            atomicExch(&g_barCnt[dir], 0u);
            __threadfence();
            atomicAdd(&g_barGen[dir], 1u);
        } else {
            while (atomicAdd(&g_barGen[dir], 0u) == gen) { __nanosleep(32); }
        }
        __threadfence();
    }
    __syncthreads();
}

// ---------------------------------------------------------------------------
// bf16 3-term split GEMM: C[M,N] = A[M,K] @ B[N,K]^T + bias
// CTA tile 128x128, 256 threads (8 warps: 2 M x 4 N; warp tile 64x32).
// 2-stage cp.async pipeline, K-chunk = 32. RSZ=80 (conflict-free ldmatrix).
// ---------------------------------------------------------------------------
#define RSZ   80
#define TILEB (128 * RSZ)     // 10240
#define STAGE (4 * TILEB)     // 40960
#define SMEM_GEMM (2 * STAGE) // 81920

__global__ __launch_bounds__(256, 2)
void gemm_bf16x3_kernel(const __nv_bfloat16* __restrict__ Ahi,
                        const __nv_bfloat16* __restrict__ Alo,
                        const __nv_bfloat16* __restrict__ Bhi,
                        const __nv_bfloat16* __restrict__ Blo,
                        const float* __restrict__ bias,
                        float* __restrict__ C, int K) {
    extern __shared__ char smem[];
    const uint32_t sb = smem_u32(smem);
    const int tid = threadIdx.x, lane = tid & 31, wid = tid >> 5;
    const int m0 = blockIdx.y * 128, n0 = blockIdx.x * 128;
    const int ldc = gridDim.x * 128;
    const int wm = wid & 1, wn = wid >> 1;

    float acc[4][4][4];
    #pragma unroll
    for (int i = 0; i < 4; ++i)
        #pragma unroll
        for (int j = 0; j < 4; ++j)
            #pragma unroll
            for (int q = 0; q < 4; ++q) acc[i][j][q] = 0.0f;

    const int nch = K >> 5;
    const int r0c = (2 * tid) >> 2, ch0 = (2 * tid) & 3;
    const int r1c = (2 * tid + 1) >> 2, ch1 = (2 * tid + 1) & 3;
    const int rA = lane & 15;
    const int cA = lane >> 4;

    #define LOAD_STAGE(cc)                                                      \
    do {                                                                        \
        const int kb = (cc) << 5;                                               \
        const uint32_t dst = sb + ((cc) & 1) * STAGE;                           \
        CP_ASYNC16(dst + 0 * TILEB + r0c * RSZ + ch0 * 16,                      \
                   Ahi + (size_t)(m0 + r0c) * K + kb + ch0 * 8);                \
        CP_ASYNC16(dst + 0 * TILEB + r1c * RSZ + ch1 * 16,                      \
                   Ahi + (size_t)(m0 + r1c) * K + kb + ch1 * 8);                \
        CP_ASYNC16(dst + 1 * TILEB + r0c * RSZ + ch0 * 16,                      \
                   Alo + (size_t)(m0 + r0c) * K + kb + ch0 * 8);                \
        CP_ASYNC16(dst + 1 * TILEB + r1c * RSZ + ch1 * 16,                      \
                   Alo + (size_t)(m0 + r1c) * K + kb + ch1 * 8);                \
        CP_ASYNC16(dst + 2 * TILEB + r0c * RSZ + ch0 * 16,                      \
                   Bhi + (size_t)(n0 + r0c) * K + kb + ch0 * 8);                \
        CP_ASYNC16(dst + 2 * TILEB + r1c * RSZ + ch1 * 16,                      \
                   Bhi + (size_t)(n0 + r1c) * K + kb + ch1 * 8);                \
        CP_ASYNC16(dst + 3 * TILEB + r0c * RSZ + ch0 * 16,                      \
                   Blo + (size_t)(n0 + r0c) * K + kb + ch0 * 8);                \
        CP_ASYNC16(dst + 3 * TILEB + r1c * RSZ + ch1 * 16,                      \
                   Blo + (size_t)(n0 + r1c) * K + kb + ch1 * 8);                \
        CP_COMMIT();                                                            \
    } while (0)

    LOAD_STAGE(0);

    for (int c = 0; c < nch; ++c) {
        if (c + 1 < nch) {
            LOAD_STAGE(c + 1);
            CP_WAIT(1);
        } else {
            CP_WAIT(0);
        }
        __syncthreads();

        const uint32_t s = sb + (c & 1) * STAGE;
        const uint32_t aHiB = s, aLoB = s + TILEB;
        const uint32_t bHiB = s + 2 * TILEB, bLoB = s + 3 * TILEB;

        #pragma unroll
        for (int ks = 0; ks < 2; ++ks) {
            const uint32_t colOff = (uint32_t)(ks * 2 + cA) * 16;
            uint32_t aHi[4][4], bHi[4][2];
            #pragma unroll
            for (int mt = 0; mt < 4; ++mt) {
                uint32_t ad = (uint32_t)(wm * 64 + mt * 16 + rA) * RSZ + colOff;
                LDSM_X4(aHi[mt], aHiB + ad);
            }
            #pragma unroll
            for (int nh = 0; nh < 2; ++nh) {
                uint32_t bd = (uint32_t)(wn * 32 + nh * 16 + rA) * RSZ + colOff;
                uint32_t t[4];
                LDSM_X4(t, bHiB + bd);
                bHi[nh * 2 + 0][0] = t[0]; bHi[nh * 2 + 0][1] = t[2];
                bHi[nh * 2 + 1][0] = t[1]; bHi[nh * 2 + 1][1] = t[3];
            }
            #pragma unroll
            for (int mt = 0; mt < 4; ++mt)
                #pragma unroll
                for (int nt = 0; nt < 4; ++nt)
                    MMA_BF16(acc[mt][nt], aHi[mt], bHi[nt]);
            {
                uint32_t aLo[4][4];
                #pragma unroll
                for (int mt = 0; mt < 4; ++mt) {
                    uint32_t ad = (uint32_t)(wm * 64 + mt * 16 + rA) * RSZ + colOff;
                    LDSM_X4(aLo[mt], aLoB + ad);
                }
                #pragma unroll
                for (int mt = 0; mt < 4; ++mt)
                    #pragma unroll
                    for (int nt = 0; nt < 4; ++nt)
                        MMA_BF16(acc[mt][nt], aLo[mt], bHi[nt]);
            }
            {
                uint32_t bLo[4][2];
                #pragma unroll
                for (int nh = 0; nh < 2; ++nh) {
                    uint32_t bd = (uint32_t)(wn * 32 + nh * 16 + rA) * RSZ + colOff;
                    uint32_t t[4];
                    LDSM_X4(t, bLoB + bd);
                    bLo[nh * 2 + 0][0] = t[0]; bLo[nh * 2 + 0][1] = t[2];
                    bLo[nh * 2 + 1][0] = t[1]; bLo[nh * 2 + 1][1] = t[3];
                }
                #pragma unroll
                for (int mt = 0; mt < 4; ++mt)
                    #pragma unroll
                    for (int nt = 0; nt < 4; ++nt)
                        MMA_BF16(acc[mt][nt], aHi[mt], bLo[nt]);
            }
        }
        __syncthreads();
    }

    const int rr = lane >> 2, cc2 = (lane & 3) * 2;
    #pragma unroll
    for (int mt = 0; mt < 4; ++mt) {
        #pragma unroll
        for (int nt = 0; nt < 4; ++nt) {
            int row = m0 + wm * 64 + mt * 16 + rr;
            int col = n0 + wn * 32 + nt * 8 + cc2;
            float b0 = 0.f, b1 = 0.f;
            if (bias) { b0 = bias[col]; b1 = bias[col + 1]; }
            float2 v0 = make_float2(acc[mt][nt][0] + b0, acc[mt][nt][1] + b1);
            float2 v1 = make_float2(acc[mt][nt][2] + b0, acc[mt][nt][3] + b1);
            *(float2*)&C[(size_t)row * ldc + col] = v0;
            *(float2*)&C[(size_t)(row + 8) * ldc + col] = v1;
        }
    }
    #undef LOAD_STAGE
}

// ---------------------------------------------------------------------------
// Pack kernels
// ---------------------------------------------------------------------------
__global__ void split_pad_kernel(const float* __restrict__ src,
                                 __nv_bfloat16* __restrict__ hi,
                                 __nv_bfloat16* __restrict__ lo,
                                 int rows, int sk, int dk) {
    size_t total = (size_t)rows * dk;
    for (size_t idx = blockIdx.x * (size_t)blockDim.x + threadIdx.x; idx < total;
         idx += (size_t)gridDim.x * blockDim.x) {
        int r = (int)(idx / dk), c = (int)(idx % dk);
        float f = (c < sk) ? src[(size_t)r * sk + c] : 0.0f;
        __nv_bfloat16 h, l; splitbf(f, h, l);
        hi[idx] = h; lo[idx] = l;
    }
}

// wih: src row g*256+j -> dst row j*4+g, pad K to EP; also permute bias
__global__ void pack_wih_kernel(const float* __restrict__ wih,
                                const float* __restrict__ b,
                                __nv_bfloat16* __restrict__ hi,
                                __nv_bfloat16* __restrict__ lo,
                                float* __restrict__ pb) {
    const int total = G4 * EP;
    for (int idx = blockIdx.x * blockDim.x + threadIdx.x; idx < total;
         idx += gridDim.x * blockDim.x) {
        int rp = idx / EP, k = idx % EP;
        int j = rp >> 2, g = rp & 3;
        float f = (k < EE) ? wih[(size_t)(g * 256 + j) * EE + k] : 0.0f;
        __nv_bfloat16 h, l; splitbf(f, h, l);
        hi[idx] = h; lo[idx] = l;
        if (k == 0) pb[rp] = b[g * 256 + j];
    }
}

// whh: src row g*256+j -> dst row j*4+g, K=256
__global__ void pack_whh_kernel(const float* __restrict__ whh,
                                __nv_bfloat16* __restrict__ hi,
                                __nv_bfloat16* __restrict__ lo) {
    const int total = G4 * HH;
    for (int idx = blockIdx.x * blockDim.x + threadIdx.x; idx < total;
         idx += gridDim.x * blockDim.x) {
        int rp = idx >> 8, k = idx & 255;
        int j = rp >> 2, g = rp & 3;
        float v = whh[(size_t)(g * 256 + j) * HH + k];
        __nv_bfloat16 h, l; splitbf(v, h, l);
        hi[idx] = h; lo[idx] = l;
    }
}

__global__ void pack_bcatT_kernel(const float* __restrict__ pair_hW,
                                  const float* __restrict__ tri_hW,
                                  __nv_bfloat16* __restrict__ hi,
                                  __nv_bfloat16* __restrict__ lo) {
    const int total = NC * D2H;
    for (int idx = blockIdx.x * blockDim.x + threadIdx.x; idx < total;
         idx += gridDim.x * blockDim.x) {
        int n = idx >> 9, d = idx & 511;
        int q = n >> 9, c = n & 511;
        float v;
        if (q < 6) {
            int k = q >> 1, h = q & 1;
            v = pair_hW[(size_t)k * (G4 * D2H) + (size_t)(h * 512 + d) * D2H + c];
        } else {
            v = tri_hW[(size_t)((q - 6) * 512 + d) * D2H + c];
        }
        __nv_bfloat16 hh, ll; splitbf(v, hh, ll);
        hi[idx] = hh; lo[idx] = ll;
    }
}

__global__ void pack_allWT_kernel(const float* __restrict__ all_hW,
                                  __nv_bfloat16* __restrict__ hi,
                                  __nv_bfloat16* __restrict__ lo) {
    const int total = D2H * 2048;
    for (int idx = blockIdx.x * blockDim.x + threadIdx.x; idx < total;
         idx += gridDim.x * blockDim.x) {
        int n = idx >> 11, k = idx & 2047;
        float v = all_hW[(size_t)k * D2H + n];
        __nv_bfloat16 hh, ll; splitbf(v, hh, ll);
        hi[idx] = hh; lo[idx] = ll;
    }
}

__global__ void zero_keys_kernel(unsigned* __restrict__ pk, unsigned* __restrict__ tk) {
    const size_t np = (size_t)3 * CC * D2H;
    const size_t nt = (size_t)CC * D2H;
    for (size_t i = blockIdx.x * (size_t)blockDim.x + threadIdx.x; i < np + nt;
         i += (size_t)gridDim.x * blockDim.x) {
        if (i < np) pk[i] = 0u; else tk[i - np] = 0u;
    }
}

// ---------------------------------------------------------------------------
// Persistent HMMA BiLSTM recurrence. grid (8 pTiles, 8 cTiles, 2 dirs) = 128
// CTAs, 256 threads, 1 CTA/SM (169KB smem). Weights resident in SMEM for all
// 256 steps; c-state in registers; per-dir global barrier between steps.
// Gate-col layout: col = j*4 + g (both Gx and whhPk rows permuted).
// ---------------------------------------------------------------------------
#define PRSZ   528            // padded row bytes for K=256 bf16 (conflict-free)
#define LP_AHI 0
#define LP_ALO 16896          // 32*528
#define LP_BHI 33792
#define LP_BLO 101376         // 33792 + 128*528
#define SMEM_LSTMP 168960     // 101376 + 128*528

__global__ __launch_bounds__(256, 1)
void lstm_persist_kernel(const float* __restrict__ GxF,
                         const float* __restrict__ GxB,
                         const __nv_bfloat16* __restrict__ whhHiF,
                         const __nv_bfloat16* __restrict__ whhLoF,
                         const __nv_bfloat16* __restrict__ whhHiB,
                         const __nv_bfloat16* __restrict__ whhLoB,
                         __nv_bfloat16* __restrict__ flatHi,
                         __nv_bfloat16* __restrict__ flatLo) {
    extern __shared__ char smem[];
    const uint32_t sb = smem_u32(smem);
    const int tid = threadIdx.x, lane = tid & 31, wid = tid >> 5;
    const int dir = blockIdx.z;
    const int p0 = blockIdx.x * 32;
    const int c0 = blockIdx.y * 128;      // gate-col tile (permuted layout)
    const int hcol = dir * HH;
    const float* Gx = dir ? GxB : GxF;
    const __nv_bfloat16* Whi = dir ? whhHiB : whhHiF;
    const __nv_bfloat16* Wlo = dir ? whhLoB : whhLoF;

    // ---- load B (whh tile, 128 rows x 256 k) once ----
    for (int ch = tid; ch < 128 * 32; ch += 256) {
        int row = ch >> 5, cb = ch & 31;
        size_t src = (size_t)(c0 + row) * HH + cb * 8;
        CP_ASYNC16(sb + LP_BHI + row * PRSZ + cb * 16, Whi + src);
        CP_ASYNC16(sb + LP_BLO + row * PRSZ + cb * 16, Wlo + src);
    }
    CP_COMMIT(); CP_WAIT(0);
    __syncthreads();

    float creg[2][2] = {{0.f, 0.f}, {0.f, 0.f}};
    const int rr = lane >> 2, cc2 = (lane & 3) * 2;
    const bool evenT = ((lane & 1) == 0);

    for (int s = 0; s < TT; ++s) {
        const int tcur = dir ? (TT - 1 - s) : s;

        float acc[2][2][4];
        #pragma unroll
        for (int i = 0; i < 2; ++i)
            #pragma unroll
            for (int j = 0; j < 2; ++j)
                #pragma unroll
                for (int q = 0; q < 4; ++q) acc[i][j][q] = 0.0f;

        if (s > 0) {
            dir_barrier(dir, tid, 64u);   // prev-step h visible chip-wide

            const int nprev = dir ? (tcur + 1) : (tcur - 1);
            for (int ch = tid; ch < 32 * 32; ch += 256) {
                int row = ch >> 5, cb = ch & 31;
                size_t src = (size_t)(nprev * PP + p0 + row) * D2H + hcol + cb * 8;
                CP_ASYNC16(sb + LP_AHI + row * PRSZ + cb * 16, flatHi + src);
                CP_ASYNC16(sb + LP_ALO + row * PRSZ + cb * 16, flatLo + src);
            }
            CP_COMMIT(); CP_WAIT(0);
            __syncthreads();

            #pragma unroll 4
            for (int kc = 0; kc < 16; ++kc) {
                const uint32_t colOff = (uint32_t)kc * 32 + (uint32_t)(lane >> 4) * 16;
                uint32_t aHi[2][4], bHi[2][2];
                #pragma unroll
                for (int mt = 0; mt < 2; ++mt) {
                    uint32_t ad = (uint32_t)(mt * 16 + (lane & 15)) * PRSZ + colOff;
                    LDSM_X4(aHi[mt], sb + LP_AHI + ad);
                }
                {
                    uint32_t bd = (uint32_t)(wid * 16 + (lane & 15)) * PRSZ + colOff;
                    uint32_t t[4];
                    LDSM_X4(t, sb + LP_BHI + bd);
                    bHi[0][0] = t[0]; bHi[0][1] = t[2];
                    bHi[1][0] = t[1]; bHi[1][1] = t[3];
                }
                #pragma unroll
                for (int mt = 0; mt < 2; ++mt)
                    #pragma unroll
                    for (int nt = 0; nt < 2; ++nt)
                        MMA_BF16(acc[mt][nt], aHi[mt], bHi[nt]);
                {
                    uint32_t aLo[2][4];
                    #pragma unroll
                    for (int mt = 0; mt < 2; ++mt) {
                        uint32_t ad = (uint32_t)(mt * 16 + (lane & 15)) * PRSZ + colOff;
                        LDSM_X4(aLo[mt], sb + LP_ALO + ad);
                    }
                    #pragma unroll
                    for (int mt = 0; mt < 2; ++mt)
                        #pragma unroll
                        for (int nt = 0; nt < 2; ++nt)
                            MMA_BF16(acc[mt][nt], aLo[mt], bHi[nt]);
                }
                {
                    uint32_t bLo[2][2];
                    uint32_t bd = (uint32_t)(wid * 16 + (lane & 15)) * PRSZ + colOff;
                    uint32_t t[4];
                    LDSM_X4(t, sb + LP_BLO + bd);
                    bLo[0][0] = t[0]; bLo[0][1] = t[2];
                    bLo[1][0] = t[1]; bLo[1][1] = t[3];
                    #pragma unroll
                    for (int mt = 0; mt < 2; ++mt)
                        #pragma unroll
                        for (int nt = 0; nt < 2; ++nt)
                            MMA_BF16(acc[mt][nt], aHi[mt], bLo[nt]);
                }
            }
        }

        // ---- epilogue: +Gx, gate exchange, LSTM cell, split h ----
        #pragma unroll
        for (int mt = 0; mt < 2; ++mt) {
            #pragma unroll
            for (int nt = 0; nt < 2; ++nt) {
                int prow = p0 + mt * 16 + rr;
                int col = c0 + wid * 16 + nt * 8 + cc2;
                int j = col >> 2;
                size_t n0i = (size_t)tcur * PP + prow;
                size_t n1i = n0i + 8;
                float2 g0 = *(const float2*)&Gx[n0i * G4 + col];
                float2 g1 = *(const float2*)&Gx[n1i * G4 + col];
                float v0 = acc[mt][nt][0] + g0.x;
                float v1 = acc[mt][nt][1] + g0.y;
                float v2 = acc[mt][nt][2] + g1.x;
                float v3 = acc[mt][nt][3] + g1.y;
                float w0 = __shfl_xor_sync(0xffffffffu, v0, 1);
                float w1 = __shfl_xor_sync(0xffffffffu, v1, 1);
                float w2 = __shfl_xor_sync(0xffffffffu, v2, 1);
                float w3 = __shfl_xor_sync(0xffffffffu, v3, 1);
                float I, F, G, O;
                int p;
                if (evenT) { I = v0; F = v1; G = w0; O = w1; p = prow; }
                else       { I = w2; F = w3; G = v2; O = v3; p = prow + 8; }
                float cold = creg[mt][nt];
                float cn = sigmoidf_(F) * cold + sigmoidf_(I) * tanhf(G);
                float h = sigmoidf_(O) * tanhf(cn);
                creg[mt][nt] = cn;
                size_t nn = (size_t)tcur * PP + p;
                __nv_bfloat16 hh, hl; splitbf(h, hh, hl);
                flatHi[nn * D2H + hcol + j] = hh;
                flatLo[nn * D2H + hcol + j] = hl;
            }
        }
        __syncthreads();   // protect smem A before next step's overwrite
    }
}

// ---------------------------------------------------------------------------
// Scatter-max kernels
// ---------------------------------------------------------------------------
__global__ void pair_scatter_kernel(const float* __restrict__ Feat,
                                    const int* __restrict__ occ1,
                                    const int* __restrict__ occ2,
                                    const int* __restrict__ seg,
                                    unsigned* __restrict__ keys) {
    const int b = blockIdx.x;
    const int k = b / MM, m = b % MM;
    const int o1 = occ1[k * MM + m];
    const int o2 = occ2[k * MM + m];
    const int sg = seg[k * MM + m];
    const float* f1 = Feat + (size_t)o1 * NC + (size_t)(2 * k) * 512;
    const float* f2 = Feat + (size_t)o2 * NC + (size_t)(2 * k + 1) * 512;
    unsigned* dst = keys + ((size_t)k * CC + sg) * D2H;
    const int c = threadIdx.x;
    float r = f1[c] + f2[c];
    atomicMax(&dst[c], fmap(r));
}

__global__ void tri_scatter_kernel(const float* __restrict__ Feat,
                                   const int* __restrict__ o1,
                                   const int* __restrict__ o2,
                                   const int* __restrict__ o3,
                                   const int* __restrict__ tseg,
                                   unsigned* __restrict__ keys) {
    const int m = blockIdx.x;
    const int a = o1[m], bb = o2[m], d = o3[m];
    const int sg = tseg[m];
    const float* f1 = Feat + (size_t)a * NC + 6 * 512;
    const float* f2 = Feat + (size_t)bb * NC + 7 * 512;
    const float* f3 = Feat + (size_t)d * NC + 8 * 512;
    unsigned* dst = keys + (size_t)sg * D2H;
    const int c = threadIdx.x;
    float r = f1[c] + f2[c] + f3[c];
    atomicMax(&dst[c], fmap(r));
}

// ---------------------------------------------------------------------------
// Finalize kernels
// ---------------------------------------------------------------------------
__global__ __launch_bounds__(256)
void pair_final_kernel(const unsigned* __restrict__ keys,
                       const float* __restrict__ hb,
                       const float* __restrict__ backoff,
                       const float* __restrict__ oW,
                       const float* __restrict__ ob,
                       float* __restrict__ pv, float* __restrict__ out) {
    const int b = blockIdx.x;
    const int k = b >> 14;
    const unsigned* src = keys + (size_t)b * D2H;
    float partial = 0.0f;
    #pragma unroll
    for (int it = 0; it < 2; ++it) {
        int c = threadIdx.x + it * 256;
        unsigned u = src[c];
        float val = u ? (funmap(u) + hb[k * D2H + c]) : backoff[k * D2H + c];
        float t = tanhf(val);
        pv[(size_t)b * D2H + c] = t;
        partial += t * oW[k * D2H + c];
    }
    float tot = blockReduceSum256(partial);
    if (threadIdx.x == 0) out[CC + b] = tot + ob[k];
}

__global__ __launch_bounds__(256)
void tri_final_kernel(const unsigned* __restrict__ keys,
                      const float* __restrict__ hb,
                      const float* __restrict__ backoff,
                      float* __restrict__ tv) {
    const int s = blockIdx.x;
    const unsigned* src = keys + (size_t)s * D2H;
    #pragma unroll
    for (int it = 0; it < 2; ++it) {
        int c = threadIdx.x + it * 256;
        unsigned u = src[c];
        float val = u ? (funmap(u) + hb[c]) : backoff[c];
        tv[(size_t)s * D2H + c] = tanhf(val);
    }
}

__global__ void gather_feats_kernel(const float* __restrict__ pv,
                                    const float* __restrict__ tv,
                                    const int* __restrict__ tpi,
                                    __nv_bfloat16* __restrict__ fhi,
                                    __nv_bfloat16* __restrict__ flo) {
    const int s = blockIdx.x;
    const int i0 = tpi[s * 3 + 0];
    const int i1 = tpi[s * 3 + 1];
    const int i2 = tpi[s * 3 + 2];
    for (int j = threadIdx.x; j < 2048; j += blockDim.x) {
        int q = j >> 9, c = j & 511;
        float v;
        if (q == 0)      v = pv[((size_t)2 * CC + i0) * D2H + c];
        else if (q == 1) v = pv[((size_t)1 * CC + i1) * D2H + c];
        else if (q == 2) v = pv[(size_t)i2 * D2H + c];
        else             v = tv[(size_t)s * D2H + c];
        __nv_bfloat16 h, l; splitbf(v, h, l);
        fhi[(size_t)s * 2048 + j] = h;
        flo[(size_t)s * 2048 + j] = l;
    }
}

__global__ __launch_bounds__(256)
void triple_logit_kernel(const float* __restrict__ fin,
                         const float* __restrict__ tW,
                         const float* __restrict__ tb,
                         float* __restrict__ out) {
    const int s = blockIdx.x;
    float partial = 0.0f;
    #pragma unroll
    for (int it = 0; it < 2; ++it) {
        int c = threadIdx.x + it * 256;
        float v = fin[(size_t)s * D2H + c];
        v = v > 0.0f ? v : 0.0f;
        partial += v * tW[c];
    }
    float tot = blockReduceSum256(partial);
    if (threadIdx.x == 0) out[s] = tot + tb[0];
}

// ---------------------------------------------------------------------------
// Launcher
// ---------------------------------------------------------------------------
extern "C" void kernel_launch(void* const* d_in, const int* in_sizes, int n_in,
                              void* d_out, int out_size) {
    const float* x        = (const float*)d_in[0];
    const float* wih_f    = (const float*)d_in[1];
    const float* whh_f    = (const float*)d_in[2];
    const float* b_f      = (const float*)d_in[3];
    const float* wih_b    = (const float*)d_in[4];
    const float* whh_b    = (const float*)d_in[5];
    const float* b_b      = (const float*)d_in[6];
    const float* pair_hW  = (const float*)d_in[7];
    const float* pair_hb  = (const float*)d_in[8];
    const float* pair_oW  = (const float*)d_in[9];
    const float* pair_ob  = (const float*)d_in[10];
    const float* pair_bo  = (const float*)d_in[11];
    const float* tri_hW   = (const float*)d_in[12];
    const float* tri_hb   = (const float*)d_in[13];
    const float* tri_bo   = (const float*)d_in[14];
    const float* all_hW   = (const float*)d_in[15];
    const float* all_hb   = (const float*)d_in[16];
    const float* out_tW   = (const float*)d_in[17];
    const float* out_tb   = (const float*)d_in[18];
    const int*   occ1     = (const int*)d_in[19];
    const int*   occ2     = (const int*)d_in[20];
    const int*   seg      = (const int*)d_in[21];
    const int*   tri_o1   = (const int*)d_in[22];
    const int*   tri_o2   = (const int*)d_in[23];
    const int*   tri_o3   = (const int*)d_in[24];
    const int*   tri_seg  = (const int*)d_in[25];
    const int*   tri_pi   = (const int*)d_in[26];
    float* out = (float*)d_out;

    float *GxF, *GxB, *Feat, *pv, *tv, *fin, *pbF, *pbB;
    unsigned *pk, *tk;
    __nv_bfloat16 *xHi, *xLo, *wHiF, *wLoF, *wHiB, *wLoB, *flHi, *flLo;
    __nv_bfloat16 *whF, *wlF, *whB, *wlB;
    __nv_bfloat16 *bcHi, *bcLo, *awHi, *awLo, *ftHi, *ftLo;
    cudaGetSymbolAddress((void**)&GxF,  g_GxF);
    cudaGetSymbolAddress((void**)&GxB,  g_GxB);
    cudaGetSymbolAddress((void**)&Feat, g_Feat);
    cudaGetSymbolAddress((void**)&pk,   g_pairKeys);
    cudaGetSymbolAddress((void**)&tk,   g_triKeys);
    cudaGetSymbolAddress((void**)&pv,   g_pv);
    cudaGetSymbolAddress((void**)&tv,   g_tv);
    cudaGetSymbolAddress((void**)&fin,  g_final);
    cudaGetSymbolAddress((void**)&pbF,  g_pbF);
    cudaGetSymbolAddress((void**)&pbB,  g_pbB);
    cudaGetSymbolAddress((void**)&xHi,  g_xHi);
    cudaGetSymbolAddress((void**)&xLo,  g_xLo);
    cudaGetSymbolAddress((void**)&wHiF, g_wHiF);
    cudaGetSymbolAddress((void**)&wLoF, g_wLoF);
    cudaGetSymbolAddress((void**)&wHiB, g_wHiB);
    cudaGetSymbolAddress((void**)&wLoB, g_wLoB);
    cudaGetSymbolAddress((void**)&whF,  g_whhHiF);
    cudaGetSymbolAddress((void**)&wlF,  g_whhLoF);
    cudaGetSymbolAddress((void**)&whB,  g_whhHiB);
    cudaGetSymbolAddress((void**)&wlB,  g_whhLoB);
    cudaGetSymbolAddress((void**)&flHi, g_flatHi);
    cudaGetSymbolAddress((void**)&flLo, g_flatLo);
    cudaGetSymbolAddress((void**)&bcHi, g_BcHi);
    cudaGetSymbolAddress((void**)&bcLo, g_BcLo);
    cudaGetSymbolAddress((void**)&awHi, g_aWHi);
    cudaGetSymbolAddress((void**)&awLo, g_aWLo);
    cudaGetSymbolAddress((void**)&ftHi, g_ftHi);
    cudaGetSymbolAddress((void**)&ftLo, g_ftLo);

    cudaFuncSetAttribute(gemm_bf16x3_kernel,
                         cudaFuncAttributeMaxDynamicSharedMemorySize, SMEM_GEMM);
    cudaFuncSetAttribute(lstm_persist_kernel,
                         cudaFuncAttributeMaxDynamicSharedMemorySize, SMEM_LSTMP);

    // 1) split/pack operands to bf16 hi/lo (permuted gate rows for LSTM path)
    split_pad_kernel<<<4096, 256>>>(x, xHi, xLo, NPOS, EE, EP);
    pack_wih_kernel<<<512, 256>>>(wih_f, b_f, wHiF, wLoF, pbF);
    pack_wih_kernel<<<512, 256>>>(wih_b, b_b, wHiB, wLoB, pbB);
    pack_whh_kernel<<<512, 256>>>(whh_f, whF, wlF);
    pack_whh_kernel<<<512, 256>>>(whh_b, whB, wlB);
    pack_bcatT_kernel<<<2304, 256>>>(pair_hW, tri_hW, bcHi, bcLo);
    pack_allWT_kernel<<<1024, 256>>>(all_hW, awHi, awLo);

    // 2) input projections (gate-permuted cols): Gx = x @ wihPk^T + pb
    gemm_bf16x3_kernel<<<dim3(8, 512), 256, SMEM_GEMM>>>(xHi, xLo, wHiF, wLoF, pbF, GxF, EP);
    gemm_bf16x3_kernel<<<dim3(8, 512), 256, SMEM_GEMM>>>(xHi, xLo, wHiB, wLoB, pbB, GxB, EP);

    // 3) zero segment-max keys
    zero_keys_kernel<<<32768, 256>>>(pk, tk);

    // 4) BiLSTM recurrence: ONE persistent HMMA kernel, 256 steps internal
    lstm_persist_kernel<<<dim3(8, 8, 2), 256, SMEM_LSTMP>>>(
        GxF, GxB, whF, wlF, whB, wlB, flHi, flLo);

    // 5) dense feature transform: Feat = flat @ BcatT^T
    gemm_bf16x3_kernel<<<dim3(NC / 128, NPOS / 128), 256, SMEM_GEMM>>>(
        flHi, flLo, bcHi, bcLo, nullptr, Feat, D2H);

    // 6) segment max pooling
    pair_scatter_kernel<<<3 * MM, 512>>>(Feat, occ1, occ2, seg, pk);
    tri_scatter_kernel<<<MM, 512>>>(Feat, tri_o1, tri_o2, tri_o3, tri_seg, tk);

    // 7) finalize pooled vectors (+ pair logits)
    pair_final_kernel<<<3 * CC, 256>>>(pk, pair_hb, pair_bo, pair_oW, pair_ob, pv, out);
    tri_final_kernel<<<CC, 256>>>(tk, tri_hb, tri_bo, tv);

    // 8) final MLP + triple logits
    gather_feats_kernel<<<CC, 256>>>(pv, tv, tri_pi, ftHi, ftLo);
    gemm_bf16x3_kernel<<<dim3(D2H / 128, CC / 128), 256, SMEM_GEMM>>>(
        ftHi, ftLo, awHi, awLo, all_hb, fin, 2048);
    triple_logit_kernel<<<CC, 256>>>(fin, out_tW, out_tb, out);
}

// round 8
// speedup vs baseline: 1.7335x; 1.1605x over previous
#include <cuda_runtime.h>
#include <cuda_bf16.h>
#include <math.h>
#include <stdint.h>

// ---------------------------------------------------------------------------
// Problem constants
// ---------------------------------------------------------------------------
#define TT   256
#define PP   256
#define EE   300
#define HH   256
#define NPOS 65536            // T*P
#define G4   1024             // 4H
#define D2H  512              // 2H
#define MM   50000
#define CC   16384
#define EP   320              // E padded to multiple of 32
#define MTILES ((MM + 127) / 128)   // 391

// ---------------------------------------------------------------------------
// Device scratch (static allocations only)
// ---------------------------------------------------------------------------
__device__ float    g_GxF[(size_t)NPOS * G4];          // 268 MB (cols j*4+g)
__device__ float    g_GxB[(size_t)NPOS * G4];          // 268 MB
__device__ unsigned g_pairKeys[(size_t)3 * CC * D2H];  // 100 MB
__device__ unsigned g_triKeys[(size_t)CC * D2H];       // 33 MB
__device__ float    g_pv[(size_t)3 * CC * D2H];        // 100 MB
__device__ float    g_tv[(size_t)CC * D2H];            // 33 MB
__device__ float    g_final[(size_t)CC * D2H];         // 33 MB
__device__ float    g_pbF[G4];                         // permuted biases
__device__ float    g_pbB[G4];
__device__ unsigned g_barCnt[2];                       // global barrier state
__device__ unsigned g_barGen[2];

// bf16 split operand buffers
__device__ __nv_bfloat16 g_xHi[(size_t)NPOS * EP];     // 42 MB
__device__ __nv_bfloat16 g_xLo[(size_t)NPOS * EP];
__device__ __nv_bfloat16 g_wHiF[(size_t)G4 * EP];      // packed rows j*4+g
__device__ __nv_bfloat16 g_wLoF[(size_t)G4 * EP];
__device__ __nv_bfloat16 g_wHiB[(size_t)G4 * EP];
__device__ __nv_bfloat16 g_wLoB[(size_t)G4 * EP];
__device__ __nv_bfloat16 g_whhHiF[(size_t)G4 * HH];    // packed rows j*4+g
__device__ __nv_bfloat16 g_whhLoF[(size_t)G4 * HH];
__device__ __nv_bfloat16 g_whhHiB[(size_t)G4 * HH];
__device__ __nv_bfloat16 g_whhLoB[(size_t)G4 * HH];
__device__ __nv_bfloat16 g_flatHi[(size_t)NPOS * D2H]; // 67 MB
__device__ __nv_bfloat16 g_flatLo[(size_t)NPOS * D2H];
__device__ __nv_bfloat16 g_pwHi[(size_t)3 * D2H * G4]; // pairWT [3][512][1024]
__device__ __nv_bfloat16 g_pwLo[(size_t)3 * D2H * G4];
__device__ __nv_bfloat16 g_twHi[(size_t)D2H * 1536];   // triWT [512][1536]
__device__ __nv_bfloat16 g_twLo[(size_t)D2H * 1536];
__device__ __nv_bfloat16 g_aWHi[(size_t)D2H * 2048];
__device__ __nv_bfloat16 g_aWLo[(size_t)D2H * 2048];
__device__ __nv_bfloat16 g_ftHi[(size_t)CC * 2048];    // 67 MB
__device__ __nv_bfloat16 g_ftLo[(size_t)CC * 2048];

// ---------------------------------------------------------------------------
// Helpers
// ---------------------------------------------------------------------------
__device__ __forceinline__ uint32_t smem_u32(const void* p) {
    uint32_t a;
    asm("{ .reg .u64 t; cvta.to.shared.u64 t, %1; cvt.u32.u64 %0, t; }"
        : "=r"(a) : "l"(p));
    return a;
}

#define LDSM_X4(r, addr) \
    asm volatile("ldmatrix.sync.aligned.m8n8.x4.shared.b16 {%0,%1,%2,%3}, [%4];" \
        : "=r"((r)[0]), "=r"((r)[1]), "=r"((r)[2]), "=r"((r)[3]) : "r"(addr))

#define MMA_BF16(d, a, b) \
    asm volatile("mma.sync.aligned.m16n8k16.row.col.f32.bf16.bf16.f32 " \
        "{%0,%1,%2,%3}, {%4,%5,%6,%7}, {%8,%9}, {%0,%1,%2,%3};" \
        : "+f"((d)[0]), "+f"((d)[1]), "+f"((d)[2]), "+f"((d)[3]) \
        : "r"((a)[0]), "r"((a)[1]), "r"((a)[2]), "r"((a)[3]), \
          "r"((b)[0]), "r"((b)[1]))

#define CP_ASYNC16(dst, src) \
    asm volatile("cp.async.cg.shared.global [%0], [%1], 16;" \
                 :: "r"(dst), "l"(src))
#define CP_COMMIT() asm volatile("cp.async.commit_group;" ::: "memory")
#define CP_WAIT(n)  asm volatile("cp.async.wait_group %0;" :: "n"(n) : "memory")

__device__ __forceinline__ float sigmoidf_(float x) { return 1.0f / (1.0f + expf(-x)); }

__device__ __forceinline__ unsigned fmap(float f) {
    unsigned b = __float_as_uint(f);
    return (b & 0x80000000u) ? ~b : (b | 0x80000000u);
}
__device__ __forceinline__ float funmap(unsigned u) {
    return (u & 0x80000000u) ? __uint_as_float(u & 0x7FFFFFFFu)
                             : __uint_as_float(~u);
}
__device__ __forceinline__ float warpReduceSum(float v) {
    #pragma unroll
    for (int o = 16; o > 0; o >>= 1) v += __shfl_down_sync(0xffffffffu, v, o);
    return v;
}
__device__ __forceinline__ float blockReduceSum256(float v) {
    __shared__ float sh[8];
    int lane = threadIdx.x & 31, wid = threadIdx.x >> 5;
    v = warpReduceSum(v);
    if (lane == 0) sh[wid] = v;
    __syncthreads();
    v = (threadIdx.x < 8) ? sh[threadIdx.x] : 0.0f;
    if (wid == 0) v = warpReduceSum(v);
    return v;
}
__device__ __forceinline__ void splitbf(float f, __nv_bfloat16& h, __nv_bfloat16& l) {
    h = __float2bfloat16(f);
    l = __float2bfloat16(f - __bfloat162float(h));
}

// per-direction grid barrier
__device__ __forceinline__ void dir_barrier(int dir, int tid, unsigned nCTA) {
    __syncthreads();
    if (tid == 0) {
        __threadfence();
        unsigned gen = atomicAdd(&g_barGen[dir], 0u);
        unsigned prev = atomicAdd(&g_barCnt[dir], 1u);
        if (prev == nCTA - 1u) {
            atomicExch(&g_barCnt[dir], 0u);
            __threadfence();
            atomicAdd(&g_barGen[dir], 1u);
        } else {
            while (atomicAdd(&g_barGen[dir], 0u) == gen) { __nanosleep(32); }
        }
        __threadfence();
    }
    __syncthreads();
}

// ---------------------------------------------------------------------------
// bf16 3-term split GEMM: C[M,N] = A[M,K] @ B[N,K]^T + bias
// CTA tile 128x128, 256 threads (8 warps: 2 M x 4 N; warp tile 64x32).
// ---------------------------------------------------------------------------
#define RSZ   80
#define TILEB (128 * RSZ)     // 10240
#define STAGE (4 * TILEB)     // 40960
#define SMEM_GEMM (2 * STAGE) // 81920

__global__ __launch_bounds__(256, 2)
void gemm_bf16x3_kernel(const __nv_bfloat16* __restrict__ Ahi,
                        const __nv_bfloat16* __restrict__ Alo,
                        const __nv_bfloat16* __restrict__ Bhi,
                        const __nv_bfloat16* __restrict__ Blo,
                        const float* __restrict__ bias,
                        float* __restrict__ C, int K) {
    extern __shared__ char smem[];
    const uint32_t sb = smem_u32(smem);
    const int tid = threadIdx.x, lane = tid & 31, wid = tid >> 5;
    const int m0 = blockIdx.y * 128, n0 = blockIdx.x * 128;
    const int ldc = gridDim.x * 128;
    const int wm = wid & 1, wn = wid >> 1;

    float acc[4][4][4];
    #pragma unroll
    for (int i = 0; i < 4; ++i)
        #pragma unroll
        for (int j = 0; j < 4; ++j)
            #pragma unroll
            for (int q = 0; q < 4; ++q) acc[i][j][q] = 0.0f;

    const int nch = K >> 5;
    const int r0c = (2 * tid) >> 2, ch0 = (2 * tid) & 3;
    const int r1c = (2 * tid + 1) >> 2, ch1 = (2 * tid + 1) & 3;
    const int rA = lane & 15;
    const int cA = lane >> 4;

    #define LOAD_STAGE(cc)                                                      \
    do {                                                                        \
        const int kb = (cc) << 5;                                               \
        const uint32_t dst = sb + ((cc) & 1) * STAGE;                           \
        CP_ASYNC16(dst + 0 * TILEB + r0c * RSZ + ch0 * 16,                      \
                   Ahi + (size_t)(m0 + r0c) * K + kb + ch0 * 8);                \
        CP_ASYNC16(dst + 0 * TILEB + r1c * RSZ + ch1 * 16,                      \
                   Ahi + (size_t)(m0 + r1c) * K + kb + ch1 * 8);                \
        CP_ASYNC16(dst + 1 * TILEB + r0c * RSZ + ch0 * 16,                      \
                   Alo + (size_t)(m0 + r0c) * K + kb + ch0 * 8);                \
        CP_ASYNC16(dst + 1 * TILEB + r1c * RSZ + ch1 * 16,                      \
                   Alo + (size_t)(m0 + r1c) * K + kb + ch1 * 8);                \
        CP_ASYNC16(dst + 2 * TILEB + r0c * RSZ + ch0 * 16,                      \
                   Bhi + (size_t)(n0 + r0c) * K + kb + ch0 * 8);                \
        CP_ASYNC16(dst + 2 * TILEB + r1c * RSZ + ch1 * 16,                      \
                   Bhi + (size_t)(n0 + r1c) * K + kb + ch1 * 8);                \
        CP_ASYNC16(dst + 3 * TILEB + r0c * RSZ + ch0 * 16,                      \
                   Blo + (size_t)(n0 + r0c) * K + kb + ch0 * 8);                \
        CP_ASYNC16(dst + 3 * TILEB + r1c * RSZ + ch1 * 16,                      \
                   Blo + (size_t)(n0 + r1c) * K + kb + ch1 * 8);                \
        CP_COMMIT();                                                            \
    } while (0)

    LOAD_STAGE(0);

    for (int c = 0; c < nch; ++c) {
        if (c + 1 < nch) { LOAD_STAGE(c + 1); CP_WAIT(1); }
        else             { CP_WAIT(0); }
        __syncthreads();

        const uint32_t s = sb + (c & 1) * STAGE;
        const uint32_t aHiB = s, aLoB = s + TILEB;
        const uint32_t bHiB = s + 2 * TILEB, bLoB = s + 3 * TILEB;

        #pragma unroll
        for (int ks = 0; ks < 2; ++ks) {
            const uint32_t colOff = (uint32_t)(ks * 2 + cA) * 16;
            uint32_t aHi[4][4], bHi[4][2];
            #pragma unroll
            for (int mt = 0; mt < 4; ++mt) {
                uint32_t ad = (uint32_t)(wm * 64 + mt * 16 + rA) * RSZ + colOff;
                LDSM_X4(aHi[mt], aHiB + ad);
            }
            #pragma unroll
            for (int nh = 0; nh < 2; ++nh) {
                uint32_t bd = (uint32_t)(wn * 32 + nh * 16 + rA) * RSZ + colOff;
                uint32_t t[4];
                LDSM_X4(t, bHiB + bd);
                bHi[nh * 2 + 0][0] = t[0]; bHi[nh * 2 + 0][1] = t[2];
                bHi[nh * 2 + 1][0] = t[1]; bHi[nh * 2 + 1][1] = t[3];
            }
            #pragma unroll
            for (int mt = 0; mt < 4; ++mt)
                #pragma unroll
                for (int nt = 0; nt < 4; ++nt)
                    MMA_BF16(acc[mt][nt], aHi[mt], bHi[nt]);
            {
                uint32_t aLo[4][4];
                #pragma unroll
                for (int mt = 0; mt < 4; ++mt) {
                    uint32_t ad = (uint32_t)(wm * 64 + mt * 16 + rA) * RSZ + colOff;
                    LDSM_X4(aLo[mt], aLoB + ad);
                }
                #pragma unroll
                for (int mt = 0; mt < 4; ++mt)
                    #pragma unroll
                    for (int nt = 0; nt < 4; ++nt)
                        MMA_BF16(acc[mt][nt], aLo[mt], bHi[nt]);
            }
            {
                uint32_t bLo[4][2];
                #pragma unroll
                for (int nh = 0; nh < 2; ++nh) {
                    uint32_t bd = (uint32_t)(wn * 32 + nh * 16 + rA) * RSZ + colOff;
                    uint32_t t[4];
                    LDSM_X4(t, bLoB + bd);
                    bLo[nh * 2 + 0][0] = t[0]; bLo[nh * 2 + 0][1] = t[2];
                    bLo[nh * 2 + 1][0] = t[1]; bLo[nh * 2 + 1][1] = t[3];
                }
                #pragma unroll
                for (int mt = 0; mt < 4; ++mt)
                    #pragma unroll
                    for (int nt = 0; nt < 4; ++nt)
                        MMA_BF16(acc[mt][nt], aHi[mt], bLo[nt]);
            }
        }
        __syncthreads();
    }

    const int rr = lane >> 2, cc2 = (lane & 3) * 2;
    #pragma unroll
    for (int mt = 0; mt < 4; ++mt) {
        #pragma unroll
        for (int nt = 0; nt < 4; ++nt) {
            int row = m0 + wm * 64 + mt * 16 + rr;
            int col = n0 + wn * 32 + nt * 8 + cc2;
            float b0 = 0.f, b1 = 0.f;
            if (bias) { b0 = bias[col]; b1 = bias[col + 1]; }
            float2 v0 = make_float2(acc[mt][nt][0] + b0, acc[mt][nt][1] + b1);
            float2 v1 = make_float2(acc[mt][nt][2] + b0, acc[mt][nt][3] + b1);
            *(float2*)&C[(size_t)row * ldc + col] = v0;
            *(float2*)&C[(size_t)(row + 8) * ldc + col] = v1;
        }
    }
    #undef LOAD_STAGE
}

// ---------------------------------------------------------------------------
// Gather-GEMM-scatter: rep[m] = concat(flat[occ1[m]],flat[occ2[m]][,flat[occ3]])
//                      @ B^T, then atomicMax into keys[seg[m]] (fmap-encoded).
// A rows gathered per occurrence; K = 1024 (pairs) or 1536 (triples); N = 512.
// Same tile/pipeline structure as gemm_bf16x3_kernel.
// ---------------------------------------------------------------------------
__global__ __launch_bounds__(256, 2)
void gemm_gsc_kernel(const __nv_bfloat16* __restrict__ flatHi,
                     const __nv_bfloat16* __restrict__ flatLo,
                     const __nv_bfloat16* __restrict__ Bhi,
                     const __nv_bfloat16* __restrict__ Blo,
                     const int* __restrict__ occ1,
                     const int* __restrict__ occ2,
                     const int* __restrict__ occ3,
                     const int* __restrict__ seg,
                     unsigned* __restrict__ keys, int K) {
    extern __shared__ char smem[];
    const uint32_t sb = smem_u32(smem);
    const int tid = threadIdx.x, lane = tid & 31, wid = tid >> 5;
    const int m0 = blockIdx.y * 128, n0 = blockIdx.x * 128;
    const int wm = wid & 1, wn = wid >> 1;

    float acc[4][4][4];
    #pragma unroll
    for (int i = 0; i < 4; ++i)
        #pragma unroll
        for (int j = 0; j < 4; ++j)
            #pragma unroll
            for (int q = 0; q < 4; ++q) acc[i][j][q] = 0.0f;

    const int nch = K >> 5;
    const int r0c = (2 * tid) >> 2, ch0 = (2 * tid) & 3;
    const int r1c = (2 * tid + 1) >> 2, ch1 = (2 * tid + 1) & 3;
    const int rA = lane & 15;
    const int cA = lane >> 4;

    // per-thread gathered A row indices for each K-segment (clamped tail)
    const int mC0 = (m0 + r0c < MM) ? (m0 + r0c) : (MM - 1);
    const int mC1 = (m0 + r1c < MM) ? (m0 + r1c) : (MM - 1);
    int ia0[3], ia1[3];
    ia0[0] = occ1[mC0]; ia1[0] = occ1[mC1];
    ia0[1] = occ2[mC0]; ia1[1] = occ2[mC1];
    ia0[2] = (K > 1024) ? occ3[mC0] : 0;
    ia1[2] = (K > 1024) ? occ3[mC1] : 0;

    #define LOAD_STAGE_G(cc)                                                    \
    do {                                                                        \
        const int kb = (cc) << 5;                                               \
        const int sg_ = kb >> 9;                                                \
        const int ck = kb & 511;                                                \
        const uint32_t dst = sb + ((cc) & 1) * STAGE;                           \
        CP_ASYNC16(dst + 0 * TILEB + r0c * RSZ + ch0 * 16,                      \
                   flatHi + (size_t)ia0[sg_] * D2H + ck + ch0 * 8);             \
        CP_ASYNC16(dst + 0 * TILEB + r1c * RSZ + ch1 * 16,                      \
                   flatHi + (size_t)ia1[sg_] * D2H + ck + ch1 * 8);             \
        CP_ASYNC16(dst + 1 * TILEB + r0c * RSZ + ch0 * 16,                      \
                   flatLo + (size_t)ia0[sg_] * D2H + ck + ch0 * 8);             \
        CP_ASYNC16(dst + 1 * TILEB + r1c * RSZ + ch1 * 16,                      \
                   flatLo + (size_t)ia1[sg_] * D2H + ck + ch1 * 8);             \
        CP_ASYNC16(dst + 2 * TILEB + r0c * RSZ + ch0 * 16,                      \
                   Bhi + (size_t)(n0 + r0c) * K + kb + ch0 * 8);                \
        CP_ASYNC16(dst + 2 * TILEB + r1c * RSZ + ch1 * 16,                      \
                   Bhi + (size_t)(n0 + r1c) * K + kb + ch1 * 8);                \
        CP_ASYNC16(dst + 3 * TILEB + r0c * RSZ + ch0 * 16,                      \
                   Blo + (size_t)(n0 + r0c) * K + kb + ch0 * 8);                \
        CP_ASYNC16(dst + 3 * TILEB + r1c * RSZ + ch1 * 16,                      \
                   Blo + (size_t)(n0 + r1c) * K + kb + ch1 * 8);                \
        CP_COMMIT();                                                            \
    } while (0)

    LOAD_STAGE_G(0);

    for (int c = 0; c < nch; ++c) {
        if (c + 1 < nch) { LOAD_STAGE_G(c + 1); CP_WAIT(1); }
        else             { CP_WAIT(0); }
        __syncthreads();

        const uint32_t s = sb + (c & 1) * STAGE;
        const uint32_t aHiB = s, aLoB = s + TILEB;
        const uint32_t bHiB = s + 2 * TILEB, bLoB = s + 3 * TILEB;

        #pragma unroll
        for (int ks = 0; ks < 2; ++ks) {
            const uint32_t colOff = (uint32_t)(ks * 2 + cA) * 16;
            uint32_t aHi[4][4], bHi[4][2];
            #pragma unroll
            for (int mt = 0; mt < 4; ++mt) {
                uint32_t ad = (uint32_t)(wm * 64 + mt * 16 + rA) * RSZ + colOff;
                LDSM_X4(aHi[mt], aHiB + ad);
            }
            #pragma unroll
            for (int nh = 0; nh < 2; ++nh) {
                uint32_t bd = (uint32_t)(wn * 32 + nh * 16 + rA) * RSZ + colOff;
                uint32_t t[4];
                LDSM_X4(t, bHiB + bd);
                bHi[nh * 2 + 0][0] = t[0]; bHi[nh * 2 + 0][1] = t[2];
                bHi[nh * 2 + 1][0] = t[1]; bHi[nh * 2 + 1][1] = t[3];
            }
            #pragma unroll
            for (int mt = 0; mt < 4; ++mt)
                #pragma unroll
                for (int nt = 0; nt < 4; ++nt)
                    MMA_BF16(acc[mt][nt], aHi[mt], bHi[nt]);
            {
                uint32_t aLo[4][4];
                #pragma unroll
                for (int mt = 0; mt < 4; ++mt) {
                    uint32_t ad = (uint32_t)(wm * 64 + mt * 16 + rA) * RSZ + colOff;
                    LDSM_X4(aLo[mt], aLoB + ad);
                }
                #pragma unroll
                for (int mt = 0; mt < 4; ++mt)
                    #pragma unroll
                    for (int nt = 0; nt < 4; ++nt)
                        MMA_BF16(acc[mt][nt], aLo[mt], bHi[nt]);
            }
            {
                uint32_t bLo[4][2];
                #pragma unroll
                for (int nh = 0; nh < 2; ++nh) {
                    uint32_t bd = (uint32_t)(wn * 32 + nh * 16 + rA) * RSZ + colOff;
                    uint32_t t[4];
                    LDSM_X4(t, bLoB + bd);
                    bLo[nh * 2 + 0][0] = t[0]; bLo[nh * 2 + 0][1] = t[2];
                    bLo[nh * 2 + 1][0] = t[1]; bLo[nh * 2 + 1][1] = t[3];
                }
                #pragma unroll
                for (int mt = 0; mt < 4; ++mt)
                    #pragma unroll
                    for (int nt = 0; nt < 4; ++nt)
                        MMA_BF16(acc[mt][nt], aHi[mt], bLo[nt]);
            }
        }
        __syncthreads();
    }

    // ---- epilogue: fmap + atomicMax scatter into segment keys ----
    const int rr = lane >> 2, cc2 = (lane & 3) * 2;
    #pragma unroll
    for (int mt = 0; mt < 4; ++mt) {
        int rowL = wm * 64 + mt * 16 + rr;
        int mA = m0 + rowL, mB = mA + 8;
        int sgA = (mA < MM) ? seg[mA] : -1;
        int sgB = (mB < MM) ? seg[mB] : -1;
        #pragma unroll
        for (int nt = 0; nt < 4; ++nt) {
            int col = n0 + wn * 32 + nt * 8 + cc2;
            if (sgA >= 0) {
                unsigned* d = keys + (size_t)sgA * D2H + col;
                atomicMax(d,     fmap(acc[mt][nt][0]));
                atomicMax(d + 1, fmap(acc[mt][nt][1]));
            }
            if (sgB >= 0) {
                unsigned* d = keys + (size_t)sgB * D2H + col;
                atomicMax(d,     fmap(acc[mt][nt][2]));
                atomicMax(d + 1, fmap(acc[mt][nt][3]));
            }
        }
    }
    #undef LOAD_STAGE_G
}

// ---------------------------------------------------------------------------
// Pack kernels
// ---------------------------------------------------------------------------
__global__ void split_pad_kernel(const float* __restrict__ src,
                                 __nv_bfloat16* __restrict__ hi,
                                 __nv_bfloat16* __restrict__ lo,
                                 int rows, int sk, int dk) {
    size_t total = (size_t)rows * dk;
    for (size_t idx = blockIdx.x * (size_t)blockDim.x + threadIdx.x; idx < total;
         idx += (size_t)gridDim.x * blockDim.x) {
        int r = (int)(idx / dk), c = (int)(idx % dk);
        float f = (c < sk) ? src[(size_t)r * sk + c] : 0.0f;
        __nv_bfloat16 h, l; splitbf(f, h, l);
        hi[idx] = h; lo[idx] = l;
    }
}

__global__ void pack_wih_kernel(const float* __restrict__ wih,
                                const float* __restrict__ b,
                                __nv_bfloat16* __restrict__ hi,
                                __nv_bfloat16* __restrict__ lo,
                                float* __restrict__ pb) {
    const int total = G4 * EP;
    for (int idx = blockIdx.x * blockDim.x + threadIdx.x; idx < total;
         idx += gridDim.x * blockDim.x) {
        int rp = idx / EP, k = idx % EP;
        int j = rp >> 2, g = rp & 3;
        float f = (k < EE) ? wih[(size_t)(g * 256 + j) * EE + k] : 0.0f;
        __nv_bfloat16 h, l; splitbf(f, h, l);
        hi[idx] = h; lo[idx] = l;
        if (k == 0) pb[rp] = b[g * 256 + j];
    }
}

__global__ void pack_whh_kernel(const float* __restrict__ whh,
                                __nv_bfloat16* __restrict__ hi,
                                __nv_bfloat16* __restrict__ lo) {
    const int total = G4 * HH;
    for (int idx = blockIdx.x * blockDim.x + threadIdx.x; idx < total;
         idx += gridDim.x * blockDim.x) {
        int rp = idx >> 8, k = idx & 255;
        int j = rp >> 2, g = rp & 3;
        float v = whh[(size_t)(g * 256 + j) * HH + k];
        __nv_bfloat16 h, l; splitbf(v, h, l);
        hi[idx] = h; lo[idx] = l;
    }
}

// pairWT [3][512 n][1024 kk] = pair_hW[k][kk][n]
__global__ void pack_pairWT_kernel(const float* __restrict__ pair_hW,
                                   __nv_bfloat16* __restrict__ hi,
                                   __nv_bfloat16* __restrict__ lo) {
    const int total = 3 * D2H * G4;
    for (int idx = blockIdx.x * blockDim.x + threadIdx.x; idx < total;
         idx += gridDim.x * blockDim.x) {
        int k = idx / (D2H * G4);
        int rem = idx - k * (D2H * G4);
        int n = rem >> 10, kk = rem & 1023;
        float v = pair_hW[(size_t)k * (G4 * D2H) + (size_t)kk * D2H + n];
        __nv_bfloat16 hh, ll; splitbf(v, hh, ll);
        hi[idx] = hh; lo[idx] = ll;
    }
}

// triWT [512 n][1536 kk] = tri_hW[kk][n]
__global__ void pack_triWT_kernel(const float* __restrict__ tri_hW,
                                  __nv_bfloat16* __restrict__ hi,
                                  __nv_bfloat16* __restrict__ lo) {
    const int total = D2H * 1536;
    for (int idx = blockIdx.x * blockDim.x + threadIdx.x; idx < total;
         idx += gridDim.x * blockDim.x) {
        int n = idx / 1536, kk = idx % 1536;
        float v = tri_hW[(size_t)kk * D2H + n];
        __nv_bfloat16 hh, ll; splitbf(v, hh, ll);
        hi[idx] = hh; lo[idx] = ll;
    }
}

__global__ void pack_allWT_kernel(const float* __restrict__ all_hW,
                                  __nv_bfloat16* __restrict__ hi,
                                  __nv_bfloat16* __restrict__ lo) {
    const int total = D2H * 2048;
    for (int idx = blockIdx.x * blockDim.x + threadIdx.x; idx < total;
         idx += gridDim.x * blockDim.x) {
        int n = idx >> 11, k = idx & 2047;
        float v = all_hW[(size_t)k * D2H + n];
        __nv_bfloat16 hh, ll; splitbf(v, hh, ll);
        hi[idx] = hh; lo[idx] = ll;
    }
}

__global__ void zero_keys_kernel(unsigned* __restrict__ pk, unsigned* __restrict__ tk) {
    const size_t np = (size_t)3 * CC * D2H;
    const size_t nt = (size_t)CC * D2H;
    for (size_t i = blockIdx.x * (size_t)blockDim.x + threadIdx.x; i < np + nt;
         i += (size_t)gridDim.x * blockDim.x) {
        if (i < np) pk[i] = 0u; else tk[i - np] = 0u;
    }
}

// ---------------------------------------------------------------------------
// Persistent HMMA BiLSTM recurrence (R7 winner, unchanged)
// ---------------------------------------------------------------------------
#define PRSZ   528
#define LP_AHI 0
#define LP_ALO 16896
#define LP_BHI 33792
#define LP_BLO 101376
#define SMEM_LSTMP 168960

__global__ __launch_bounds__(256, 1)
void lstm_persist_kernel(const float* __restrict__ GxF,
                         const float* __restrict__ GxB,
                         const __nv_bfloat16* __restrict__ whhHiF,
                         const __nv_bfloat16* __restrict__ whhLoF,
                         const __nv_bfloat16* __restrict__ whhHiB,
                         const __nv_bfloat16* __restrict__ whhLoB,
                         __nv_bfloat16* __restrict__ flatHi,
                         __nv_bfloat16* __restrict__ flatLo) {
    extern __shared__ char smem[];
    const uint32_t sb = smem_u32(smem);
    const int tid = threadIdx.x, lane = tid & 31, wid = tid >> 5;
    const int dir = blockIdx.z;
    const int p0 = blockIdx.x * 32;
    const int c0 = blockIdx.y * 128;
    const int hcol = dir * HH;
    const float* Gx = dir ? GxB : GxF;
    const __nv_bfloat16* Whi = dir ? whhHiB : whhHiF;
    const __nv_bfloat16* Wlo = dir ? whhLoB : whhLoF;

    for (int ch = tid; ch < 128 * 32; ch += 256) {
        int row = ch >> 5, cb = ch & 31;
        size_t src = (size_t)(c0 + row) * HH + cb * 8;
        CP_ASYNC16(sb + LP_BHI + row * PRSZ + cb * 16, Whi + src);
        CP_ASYNC16(sb + LP_BLO + row * PRSZ + cb * 16, Wlo + src);
    }
    CP_COMMIT(); CP_WAIT(0);
    __syncthreads();

    float creg[2][2] = {{0.f, 0.f}, {0.f, 0.f}};
    const int rr = lane >> 2, cc2 = (lane & 3) * 2;
    const bool evenT = ((lane & 1) == 0);

    for (int s = 0; s < TT; ++s) {
        const int tcur = dir ? (TT - 1 - s) : s;

        float acc[2][2][4];
        #pragma unroll
        for (int i = 0; i < 2; ++i)
            #pragma unroll
            for (int j = 0; j < 2; ++j)
                #pragma unroll
                for (int q = 0; q < 4; ++q) acc[i][j][q] = 0.0f;

        if (s > 0) {
            dir_barrier(dir, tid, 64u);

            const int nprev = dir ? (tcur + 1) : (tcur - 1);
            for (int ch = tid; ch < 32 * 32; ch += 256) {
                int row = ch >> 5, cb = ch & 31;
                size_t src = (size_t)(nprev * PP + p0 + row) * D2H + hcol + cb * 8;
                CP_ASYNC16(sb + LP_AHI + row * PRSZ + cb * 16, flatHi + src);
                CP_ASYNC16(sb + LP_ALO + row * PRSZ + cb * 16, flatLo + src);
            }
            CP_COMMIT(); CP_WAIT(0);
            __syncthreads();

            #pragma unroll 4
            for (int kc = 0; kc < 16; ++kc) {
                const uint32_t colOff = (uint32_t)kc * 32 + (uint32_t)(lane >> 4) * 16;
                uint32_t aHi[2][4], bHi[2][2];
                #pragma unroll
                for (int mt = 0; mt < 2; ++mt) {
                    uint32_t ad = (uint32_t)(mt * 16 + (lane & 15)) * PRSZ + colOff;
                    LDSM_X4(aHi[mt], sb + LP_AHI + ad);
                }
                {
                    uint32_t bd = (uint32_t)(wid * 16 + (lane & 15)) * PRSZ + colOff;
                    uint32_t t[4];
                    LDSM_X4(t, sb + LP_BHI + bd);
                    bHi[0][0] = t[0]; bHi[0][1] = t[2];
                    bHi[1][0] = t[1]; bHi[1][1] = t[3];
                }
                #pragma unroll
                for (int mt = 0; mt < 2; ++mt)
                    #pragma unroll
                    for (int nt = 0; nt < 2; ++nt)
                        MMA_BF16(acc[mt][nt], aHi[mt], bHi[nt]);
                {
                    uint32_t aLo[2][4];
                    #pragma unroll
                    for (int mt = 0; mt < 2; ++mt) {
                        uint32_t ad = (uint32_t)(mt * 16 + (lane & 15)) * PRSZ + colOff;
                        LDSM_X4(aLo[mt], sb + LP_ALO + ad);
                    }
                    #pragma unroll
                    for (int mt = 0; mt < 2; ++mt)
                        #pragma unroll
                        for (int nt = 0; nt < 2; ++nt)
                            MMA_BF16(acc[mt][nt], aLo[mt], bHi[nt]);
                }
                {
                    uint32_t bLo[2][2];
                    uint32_t bd = (uint32_t)(wid * 16 + (lane & 15)) * PRSZ + colOff;
                    uint32_t t[4];
                    LDSM_X4(t, sb + LP_BLO + bd);
                    bLo[0][0] = t[0]; bLo[0][1] = t[2];
                    bLo[1][0] = t[1]; bLo[1][1] = t[3];
                    #pragma unroll
                    for (int mt = 0; mt < 2; ++mt)
                        #pragma unroll
                        for (int nt = 0; nt < 2; ++nt)
                            MMA_BF16(acc[mt][nt], aHi[mt], bLo[nt]);
                }
            }
        }

        #pragma unroll
        for (int mt = 0; mt < 2; ++mt) {
            #pragma unroll
            for (int nt = 0; nt < 2; ++nt) {
                int prow = p0 + mt * 16 + rr;
                int col = c0 + wid * 16 + nt * 8 + cc2;
                int j = col >> 2;
                size_t n0i = (size_t)tcur * PP + prow;
                size_t n1i = n0i + 8;
                float2 g0 = *(const float2*)&Gx[n0i * G4 + col];
                float2 g1 = *(const float2*)&Gx[n1i * G4 + col];
                float v0 = acc[mt][nt][0] + g0.x;
                float v1 = acc[mt][nt][1] + g0.y;
                float v2 = acc[mt][nt][2] + g1.x;
                float v3 = acc[mt][nt][3] + g1.y;
                float w0 = __shfl_xor_sync(0xffffffffu, v0, 1);
                float w1 = __shfl_xor_sync(0xffffffffu, v1, 1);
                float w2 = __shfl_xor_sync(0xffffffffu, v2, 1);
                float w3 = __shfl_xor_sync(0xffffffffu, v3, 1);
                float I, F, G, O;
                int p;
                if (evenT) { I = v0; F = v1; G = w0; O = w1; p = prow; }
                else       { I = w2; F = w3; G = v2; O = v3; p = prow + 8; }
                float cold = creg[mt][nt];
                float cn = sigmoidf_(F) * cold + sigmoidf_(I) * tanhf(G);
                float h = sigmoidf_(O) * tanhf(cn);
                creg[mt][nt] = cn;
                size_t nn = (size_t)tcur * PP + p;
                __nv_bfloat16 hh, hl; splitbf(h, hh, hl);
                flatHi[nn * D2H + hcol + j] = hh;
                flatLo[nn * D2H + hcol + j] = hl;
            }
        }
        __syncthreads();
    }
}

// ---------------------------------------------------------------------------
// Finalize kernels
// ---------------------------------------------------------------------------
__global__ __launch_bounds__(256)
void pair_final_kernel(const unsigned* __restrict__ keys,
                       const float* __restrict__ hb,
                       const float* __restrict__ backoff,
                       const float* __restrict__ oW,
                       const float* __restrict__ ob,
                       float* __restrict__ pv, float* __restrict__ out) {
    const int b = blockIdx.x;
    const int k = b >> 14;
    const unsigned* src = keys + (size_t)b * D2H;
    float partial = 0.0f;
    #pragma unroll
    for (int it = 0; it < 2; ++it) {
        int c = threadIdx.x + it * 256;
        unsigned u = src[c];
        float val = u ? (funmap(u) + hb[k * D2H + c]) : backoff[k * D2H + c];
        float t = tanhf(val);
        pv[(size_t)b * D2H + c] = t;
        partial += t * oW[k * D2H + c];
    }
    float tot = blockReduceSum256(partial);
    if (threadIdx.x == 0) out[CC + b] = tot + ob[k];
}

__global__ __launch_bounds__(256)
void tri_final_kernel(const unsigned* __restrict__ keys,
                      const float* __restrict__ hb,
                      const float* __restrict__ backoff,
                      float* __restrict__ tv) {
    const int s = blockIdx.x;
    const unsigned* src = keys + (size_t)s * D2H;
    #pragma unroll
    for (int it = 0; it < 2; ++it) {
        int c = threadIdx.x + it * 256;
        unsigned u = src[c];
        float val = u ? (funmap(u) + hb[c]) : backoff[c];
        tv[(size_t)s * D2H + c] = tanhf(val);
    }
}

__global__ void gather_feats_kernel(const float* __restrict__ pv,
                                    const float* __restrict__ tv,
                                    const int* __restrict__ tpi,
                                    __nv_bfloat16* __restrict__ fhi,
                                    __nv_bfloat16* __restrict__ flo) {
    const int s = blockIdx.x;
    const int i0 = tpi[s * 3 + 0];
    const int i1 = tpi[s * 3 + 1];
    const int i2 = tpi[s * 3 + 2];
    for (int j = threadIdx.x; j < 2048; j += blockDim.x) {
        int q = j >> 9, c = j & 511;
        float v;
        if (q == 0)      v = pv[((size_t)2 * CC + i0) * D2H + c];
        else if (q == 1) v = pv[((size_t)1 * CC + i1) * D2H + c];
        else if (q == 2) v = pv[(size_t)i2 * D2H + c];
        else             v = tv[(size_t)s * D2H + c];
        __nv_bfloat16 h, l; splitbf(v, h, l);
        fhi[(size_t)s * 2048 + j] = h;
        flo[(size_t)s * 2048 + j] = l;
    }
}

__global__ __launch_bounds__(256)
void triple_logit_kernel(const float* __restrict__ fin,
                         const float* __restrict__ tW,
                         const float* __restrict__ tb,
                         float* __restrict__ out) {
    const int s = blockIdx.x;
    float partial = 0.0f;
    #pragma unroll
    for (int it = 0; it < 2; ++it) {
        int c = threadIdx.x + it * 256;
        float v = fin[(size_t)s * D2H + c];
        v = v > 0.0f ? v : 0.0f;
        partial += v * tW[c];
    }
    float tot = blockReduceSum256(partial);
    if (threadIdx.x == 0) out[s] = tot + tb[0];
}

// ---------------------------------------------------------------------------
// Launcher
// ---------------------------------------------------------------------------
extern "C" void kernel_launch(void* const* d_in, const int* in_sizes, int n_in,
                              void* d_out, int out_size) {
    const float* x        = (const float*)d_in[0];
    const float* wih_f    = (const float*)d_in[1];
    const float* whh_f    = (const float*)d_in[2];
    const float* b_f      = (const float*)d_in[3];
    const float* wih_b    = (const float*)d_in[4];
    const float* whh_b    = (const float*)d_in[5];
    const float* b_b      = (const float*)d_in[6];
    const float* pair_hW  = (const float*)d_in[7];
    const float* pair_hb  = (const float*)d_in[8];
    const float* pair_oW  = (const float*)d_in[9];
    const float* pair_ob  = (const float*)d_in[10];
    const float* pair_bo  = (const float*)d_in[11];
    const float* tri_hW   = (const float*)d_in[12];
    const float* tri_hb   = (const float*)d_in[13];
    const float* tri_bo   = (const float*)d_in[14];
    const float* all_hW   = (const float*)d_in[15];
    const float* all_hb   = (const float*)d_in[16];
    const float* out_tW   = (const float*)d_in[17];
    const float* out_tb   = (const float*)d_in[18];
    const int*   occ1     = (const int*)d_in[19];
    const int*   occ2     = (const int*)d_in[20];
    const int*   seg      = (const int*)d_in[21];
    const int*   tri_o1   = (const int*)d_in[22];
    const int*   tri_o2   = (const int*)d_in[23];
    const int*   tri_o3   = (const int*)d_in[24];
    const int*   tri_seg  = (const int*)d_in[25];
    const int*   tri_pi   = (const int*)d_in[26];
    float* out = (float*)d_out;

    float *GxF, *GxB, *pv, *tv, *fin, *pbF, *pbB;
    unsigned *pk, *tk;
    __nv_bfloat16 *xHi, *xLo, *wHiF, *wLoF, *wHiB, *wLoB, *flHi, *flLo;
    __nv_bfloat16 *whF, *wlF, *whB, *wlB;
    __nv_bfloat16 *pwHi, *pwLo, *twHi, *twLo, *awHi, *awLo, *ftHi, *ftLo;
    cudaGetSymbolAddress((void**)&GxF,  g_GxF);
    cudaGetSymbolAddress((void**)&GxB,  g_GxB);
    cudaGetSymbolAddress((void**)&pk,   g_pairKeys);
    cudaGetSymbolAddress((void**)&tk,   g_triKeys);
    cudaGetSymbolAddress((void**)&pv,   g_pv);
    cudaGetSymbolAddress((void**)&tv,   g_tv);
    cudaGetSymbolAddress((void**)&fin,  g_final);
    cudaGetSymbolAddress((void**)&pbF,  g_pbF);
    cudaGetSymbolAddress((void**)&pbB,  g_pbB);
    cudaGetSymbolAddress((void**)&xHi,  g_xHi);
    cudaGetSymbolAddress((void**)&xLo,  g_xLo);
    cudaGetSymbolAddress((void**)&wHiF, g_wHiF);
    cudaGetSymbolAddress((void**)&wLoF, g_wLoF);
    cudaGetSymbolAddress((void**)&wHiB, g_wHiB);
    cudaGetSymbolAddress((void**)&wLoB, g_wLoB);
    cudaGetSymbolAddress((void**)&whF,  g_whhHiF);
    cudaGetSymbolAddress((void**)&wlF,  g_whhLoF);
    cudaGetSymbolAddress((void**)&whB,  g_whhHiB);
    cudaGetSymbolAddress((void**)&wlB,  g_whhLoB);
    cudaGetSymbolAddress((void**)&flHi, g_flatHi);
    cudaGetSymbolAddress((void**)&flLo, g_flatLo);
    cudaGetSymbolAddress((void**)&pwHi, g_pwHi);
    cudaGetSymbolAddress((void**)&pwLo, g_pwLo);
    cudaGetSymbolAddress((void**)&twHi, g_twHi);
    cudaGetSymbolAddress((void**)&twLo, g_twLo);
    cudaGetSymbolAddress((void**)&awHi, g_aWHi);
    cudaGetSymbolAddress((void**)&awLo, g_aWLo);
    cudaGetSymbolAddress((void**)&ftHi, g_ftHi);
    cudaGetSymbolAddress((void**)&ftLo, g_ftLo);

    cudaFuncSetAttribute(gemm_bf16x3_kernel,
                         cudaFuncAttributeMaxDynamicSharedMemorySize, SMEM_GEMM);
    cudaFuncSetAttribute(gemm_gsc_kernel,
                         cudaFuncAttributeMaxDynamicSharedMemorySize, SMEM_GEMM);
    cudaFuncSetAttribute(lstm_persist_kernel,
                         cudaFuncAttributeMaxDynamicSharedMemorySize, SMEM_LSTMP);

    // 1) split/pack operands
    split_pad_kernel<<<4096, 256>>>(x, xHi, xLo, NPOS, EE, EP);
    pack_wih_kernel<<<512, 256>>>(wih_f, b_f, wHiF, wLoF, pbF);
    pack_wih_kernel<<<512, 256>>>(wih_b, b_b, wHiB, wLoB, pbB);
    pack_whh_kernel<<<512, 256>>>(whh_f, whF, wlF);
    pack_whh_kernel<<<512, 256>>>(whh_b, whB, wlB);
    pack_pairWT_kernel<<<3072, 256>>>(pair_hW, pwHi, pwLo);
    pack_triWT_kernel<<<1536, 256>>>(tri_hW, twHi, twLo);
    pack_allWT_kernel<<<1024, 256>>>(all_hW, awHi, awLo);

    // 2) input projections (gate-permuted cols)
    gemm_bf16x3_kernel<<<dim3(8, 512), 256, SMEM_GEMM>>>(xHi, xLo, wHiF, wLoF, pbF, GxF, EP);
    gemm_bf16x3_kernel<<<dim3(8, 512), 256, SMEM_GEMM>>>(xHi, xLo, wHiB, wLoB, pbB, GxB, EP);

    // 3) zero segment-max keys
    zero_keys_kernel<<<32768, 256>>>(pk, tk);

    // 4) BiLSTM recurrence: persistent HMMA kernel
    lstm_persist_kernel<<<dim3(8, 8, 2), 256, SMEM_LSTMP>>>(
        GxF, GxB, whF, wlF, whB, wlB, flHi, flLo);

    // 5) gather-GEMM-scatter: pair types + triples (replaces Feat + scatters)
    for (int k = 0; k < 3; ++k)
        gemm_gsc_kernel<<<dim3(4, MTILES), 256, SMEM_GEMM>>>(
            flHi, flLo,
            pwHi + (size_t)k * D2H * G4, pwLo + (size_t)k * D2H * G4,
            occ1 + k * MM, occ2 + k * MM, occ1 + k * MM,
            seg + k * MM, pk + (size_t)k * CC * D2H, G4);
    gemm_gsc_kernel<<<dim3(4, MTILES), 256, SMEM_GEMM>>>(
        flHi, flLo, twHi, twLo, tri_o1, tri_o2, tri_o3, tri_seg, tk, 1536);

    // 6) finalize pooled vectors (+ pair logits)
    pair_final_kernel<<<3 * CC, 256>>>(pk, pair_hb, pair_bo, pair_oW, pair_ob, pv, out);
    tri_final_kernel<<<CC, 256>>>(tk, tri_hb, tri_bo, tv);

    // 7) final MLP + triple logits
    gather_feats_kernel<<<CC, 256>>>(pv, tv, tri_pi, ftHi, ftLo);
    gemm_bf16x3_kernel<<<dim3(D2H / 128, CC / 128), 256, SMEM_GEMM>>>(
        ftHi, ftLo, awHi, awLo, all_hb, fin, 2048);
    triple_logit_kernel<<<CC, 256>>>(fin, out_tW, out_tb, out);
}

// round 9
// speedup vs baseline: 2.1087x; 1.2164x over previous
#include <cuda_runtime.h>
#include <cuda_fp16.h>
#include <math.h>
#include <stdint.h>

// ---------------------------------------------------------------------------
// Problem constants
// ---------------------------------------------------------------------------
#define TT   256
#define PP   256
#define EE   300
#define HH   256
#define NPOS 65536            // T*P
#define G4   1024             // 4H
#define D2H  512              // 2H
#define MM   50000
#define CC   16384
#define EP   320              // E padded to multiple of 32
#define MTILES ((MM + 127) / 128)   // 391

// ---------------------------------------------------------------------------
// Device scratch (static allocations only)
// ---------------------------------------------------------------------------
__device__ float    g_GxF[(size_t)NPOS * G4];          // 268 MB (cols j*4+g)
__device__ float    g_GxB[(size_t)NPOS * G4];          // 268 MB
__device__ unsigned g_pairKeys[(size_t)3 * CC * D2H];  // 100 MB
__device__ unsigned g_triKeys[(size_t)CC * D2H];       // 33 MB
__device__ float    g_pv[(size_t)3 * CC * D2H];        // 100 MB
__device__ float    g_tv[(size_t)CC * D2H];            // 33 MB
__device__ float    g_final[(size_t)CC * D2H];         // 33 MB
__device__ float    g_pbF[G4];                         // permuted biases
__device__ float    g_pbB[G4];
__device__ unsigned g_barCnt[2];                       // global barrier state
__device__ unsigned g_barGen[2];

// fp16 split operand buffers
__device__ __half g_xHi[(size_t)NPOS * EP];            // 42 MB
__device__ __half g_xLo[(size_t)NPOS * EP];
__device__ __half g_wHiF[(size_t)G4 * EP];             // packed rows j*4+g (hi only)
__device__ __half g_wHiB[(size_t)G4 * EP];
__device__ __half g_whhHiF[(size_t)G4 * HH];           // packed rows j*4+g
__device__ __half g_whhLoF[(size_t)G4 * HH];
__device__ __half g_whhHiB[(size_t)G4 * HH];
__device__ __half g_whhLoB[(size_t)G4 * HH];
__device__ __half g_flatHi[(size_t)NPOS * D2H];        // 67 MB
__device__ __half g_flatLo[(size_t)NPOS * D2H];
__device__ __half g_pwHi[(size_t)3 * D2H * G4];        // pairWT [3][512][1024]
__device__ __half g_twHi[(size_t)D2H * 1536];          // triWT [512][1536]
__device__ __half g_aWHi[(size_t)D2H * 2048];
__device__ __half g_ftHi[(size_t)CC * 2048];           // 67 MB
__device__ __half g_ftLo[(size_t)CC * 2048];

// ---------------------------------------------------------------------------
// Helpers
// ---------------------------------------------------------------------------
__device__ __forceinline__ uint32_t smem_u32(const void* p) {
    uint32_t a;
    asm("{ .reg .u64 t; cvta.to.shared.u64 t, %1; cvt.u32.u64 %0, t; }"
        : "=r"(a) : "l"(p));
    return a;
}

#define LDSM_X4(r, addr) \
    asm volatile("ldmatrix.sync.aligned.m8n8.x4.shared.b16 {%0,%1,%2,%3}, [%4];" \
        : "=r"((r)[0]), "=r"((r)[1]), "=r"((r)[2]), "=r"((r)[3]) : "r"(addr))

#define MMA_FP16(d, a, b) \
    asm volatile("mma.sync.aligned.m16n8k16.row.col.f32.f16.f16.f32 " \
        "{%0,%1,%2,%3}, {%4,%5,%6,%7}, {%8,%9}, {%0,%1,%2,%3};" \
        : "+f"((d)[0]), "+f"((d)[1]), "+f"((d)[2]), "+f"((d)[3]) \
        : "r"((a)[0]), "r"((a)[1]), "r"((a)[2]), "r"((a)[3]), \
          "r"((b)[0]), "r"((b)[1]))

#define CP_ASYNC16(dst, src) \
    asm volatile("cp.async.cg.shared.global [%0], [%1], 16;" \
                 :: "r"(dst), "l"(src))
#define CP_COMMIT() asm volatile("cp.async.commit_group;" ::: "memory")
#define CP_WAIT(n)  asm volatile("cp.async.wait_group %0;" :: "n"(n) : "memory")

__device__ __forceinline__ float sigmoidf_(float x) { return 1.0f / (1.0f + expf(-x)); }

__device__ __forceinline__ unsigned fmap(float f) {
    unsigned b = __float_as_uint(f);
    return (b & 0x80000000u) ? ~b : (b | 0x80000000u);
}
__device__ __forceinline__ float funmap(unsigned u) {
    return (u & 0x80000000u) ? __uint_as_float(u & 0x7FFFFFFFu)
                             : __uint_as_float(~u);
}
__device__ __forceinline__ float warpReduceSum(float v) {
    #pragma unroll
    for (int o = 16; o > 0; o >>= 1) v += __shfl_down_sync(0xffffffffu, v, o);
    return v;
}
__device__ __forceinline__ float blockReduceSum256(float v) {
    __shared__ float sh[8];
    int lane = threadIdx.x & 31, wid = threadIdx.x >> 5;
    v = warpReduceSum(v);
    if (lane == 0) sh[wid] = v;
    __syncthreads();
    v = (threadIdx.x < 8) ? sh[threadIdx.x] : 0.0f;
    if (wid == 0) v = warpReduceSum(v);
    return v;
}
__device__ __forceinline__ void splith(float f, __half& h, __half& l) {
    h = __float2half(f);
    l = __float2half(f - __half2float(h));
}

// per-direction grid barrier
__device__ __forceinline__ void dir_barrier(int dir, int tid, unsigned nCTA) {
    __syncthreads();
    if (tid == 0) {
        __threadfence();
        unsigned gen = atomicAdd(&g_barGen[dir], 0u);
        unsigned prev = atomicAdd(&g_barCnt[dir], 1u);
        if (prev == nCTA - 1u) {
            atomicExch(&g_barCnt[dir], 0u);
            __threadfence();
            atomicAdd(&g_barGen[dir], 1u);
        } else {
            while (atomicAdd(&g_barGen[dir], 0u) == gen) { __nanosleep(32); }
        }
        __threadfence();
    }
    __syncthreads();
}

// ---------------------------------------------------------------------------
// fp16 2-term split GEMM: C[M,N] = (Ahi+Alo)[M,K] @ Bhi[N,K]^T + bias
// CTA tile 128x128, 256 threads (8 warps: 2 M x 4 N; warp tile 64x32).
// 2-stage cp.async pipeline, K-chunk = 32. RSZ=80 (conflict-free ldmatrix).
// ---------------------------------------------------------------------------
#define RSZ   80
#define TILEB (128 * RSZ)       // 10240
#define STAGE3 (3 * TILEB)      // 30720 (Ahi, Alo, Bhi)
#define SMEM_GEMM (2 * STAGE3)  // 61440

__global__ __launch_bounds__(256, 2)
void gemm_fp16x2_kernel(const __half* __restrict__ Ahi,
                        const __half* __restrict__ Alo,
                        const __half* __restrict__ Bhi,
                        const float* __restrict__ bias,
                        float* __restrict__ C, int K) {
    extern __shared__ char smem[];
    const uint32_t sb = smem_u32(smem);
    const int tid = threadIdx.x, lane = tid & 31, wid = tid >> 5;
    const int m0 = blockIdx.y * 128, n0 = blockIdx.x * 128;
    const int ldc = gridDim.x * 128;
    const int wm = wid & 1, wn = wid >> 1;

    float acc[4][4][4];
    #pragma unroll
    for (int i = 0; i < 4; ++i)
        #pragma unroll
        for (int j = 0; j < 4; ++j)
            #pragma unroll
            for (int q = 0; q < 4; ++q) acc[i][j][q] = 0.0f;

    const int nch = K >> 5;
    const int r0c = (2 * tid) >> 2, ch0 = (2 * tid) & 3;
    const int r1c = (2 * tid + 1) >> 2, ch1 = (2 * tid + 1) & 3;
    const int rA = lane & 15;
    const int cA = lane >> 4;

    #define LOAD_STAGE(cc)                                                      \
    do {                                                                        \
        const int kb = (cc) << 5;                                               \
        const uint32_t dst = sb + ((cc) & 1) * STAGE3;                          \
        CP_ASYNC16(dst + 0 * TILEB + r0c * RSZ + ch0 * 16,                      \
                   Ahi + (size_t)(m0 + r0c) * K + kb + ch0 * 8);                \
        CP_ASYNC16(dst + 0 * TILEB + r1c * RSZ + ch1 * 16,                      \
                   Ahi + (size_t)(m0 + r1c) * K + kb + ch1 * 8);                \
        CP_ASYNC16(dst + 1 * TILEB + r0c * RSZ + ch0 * 16,                      \
                   Alo + (size_t)(m0 + r0c) * K + kb + ch0 * 8);                \
        CP_ASYNC16(dst + 1 * TILEB + r1c * RSZ + ch1 * 16,                      \
                   Alo + (size_t)(m0 + r1c) * K + kb + ch1 * 8);                \
        CP_ASYNC16(dst + 2 * TILEB + r0c * RSZ + ch0 * 16,                      \
                   Bhi + (size_t)(n0 + r0c) * K + kb + ch0 * 8);                \
        CP_ASYNC16(dst + 2 * TILEB + r1c * RSZ + ch1 * 16,                      \
                   Bhi + (size_t)(n0 + r1c) * K + kb + ch1 * 8);                \
        CP_COMMIT();                                                            \
    } while (0)

    LOAD_STAGE(0);

    for (int c = 0; c < nch; ++c) {
        if (c + 1 < nch) { LOAD_STAGE(c + 1); CP_WAIT(1); }
        else             { CP_WAIT(0); }
        __syncthreads();

        const uint32_t s = sb + (c & 1) * STAGE3;
        const uint32_t aHiB = s, aLoB = s + TILEB, bHiB = s + 2 * TILEB;

        #pragma unroll
        for (int ks = 0; ks < 2; ++ks) {
            const uint32_t colOff = (uint32_t)(ks * 2 + cA) * 16;
            uint32_t aHi[4][4], bHi[4][2];
            #pragma unroll
            for (int mt = 0; mt < 4; ++mt) {
                uint32_t ad = (uint32_t)(wm * 64 + mt * 16 + rA) * RSZ + colOff;
                LDSM_X4(aHi[mt], aHiB + ad);
            }
            #pragma unroll
            for (int nh = 0; nh < 2; ++nh) {
                uint32_t bd = (uint32_t)(wn * 32 + nh * 16 + rA) * RSZ + colOff;
                uint32_t t[4];
                LDSM_X4(t, bHiB + bd);
                bHi[nh * 2 + 0][0] = t[0]; bHi[nh * 2 + 0][1] = t[2];
                bHi[nh * 2 + 1][0] = t[1]; bHi[nh * 2 + 1][1] = t[3];
            }
            #pragma unroll
            for (int mt = 0; mt < 4; ++mt)
                #pragma unroll
                for (int nt = 0; nt < 4; ++nt)
                    MMA_FP16(acc[mt][nt], aHi[mt], bHi[nt]);
            {
                uint32_t aLo[4][4];
                #pragma unroll
                for (int mt = 0; mt < 4; ++mt) {
                    uint32_t ad = (uint32_t)(wm * 64 + mt * 16 + rA) * RSZ + colOff;
                    LDSM_X4(aLo[mt], aLoB + ad);
                }
                #pragma unroll
                for (int mt = 0; mt < 4; ++mt)
                    #pragma unroll
                    for (int nt = 0; nt < 4; ++nt)
                        MMA_FP16(acc[mt][nt], aLo[mt], bHi[nt]);
            }
        }
        __syncthreads();
    }

    const int rr = lane >> 2, cc2 = (lane & 3) * 2;
    #pragma unroll
    for (int mt = 0; mt < 4; ++mt) {
        #pragma unroll
        for (int nt = 0; nt < 4; ++nt) {
            int row = m0 + wm * 64 + mt * 16 + rr;
            int col = n0 + wn * 32 + nt * 8 + cc2;
            float b0 = 0.f, b1 = 0.f;
            if (bias) { b0 = bias[col]; b1 = bias[col + 1]; }
            float2 v0 = make_float2(acc[mt][nt][0] + b0, acc[mt][nt][1] + b1);
            float2 v1 = make_float2(acc[mt][nt][2] + b0, acc[mt][nt][3] + b1);
            *(float2*)&C[(size_t)row * ldc + col] = v0;
            *(float2*)&C[(size_t)(row + 8) * ldc + col] = v1;
        }
    }
    #undef LOAD_STAGE
}

// ---------------------------------------------------------------------------
// Gather-GEMM-scatter (fp16 2-term): rep[m] = concat(flat[occ..]) @ Bhi^T,
// then atomicMax into keys[seg[m]] (fmap-encoded).
// ---------------------------------------------------------------------------
__global__ __launch_bounds__(256, 2)
void gemm_gsc_kernel(const __half* __restrict__ flatHi,
                     const __half* __restrict__ flatLo,
                     const __half* __restrict__ Bhi,
                     const int* __restrict__ occ1,
                     const int* __restrict__ occ2,
                     const int* __restrict__ occ3,
                     const int* __restrict__ seg,
                     unsigned* __restrict__ keys, int K) {
    extern __shared__ char smem[];
    const uint32_t sb = smem_u32(smem);
    const int tid = threadIdx.x, lane = tid & 31, wid = tid >> 5;
    const int m0 = blockIdx.y * 128, n0 = blockIdx.x * 128;
    const int wm = wid & 1, wn = wid >> 1;

    float acc[4][4][4];
    #pragma unroll
    for (int i = 0; i < 4; ++i)
        #pragma unroll
        for (int j = 0; j < 4; ++j)
            #pragma unroll
            for (int q = 0; q < 4; ++q) acc[i][j][q] = 0.0f;

    const int nch = K >> 5;
    const int r0c = (2 * tid) >> 2, ch0 = (2 * tid) & 3;
    const int r1c = (2 * tid + 1) >> 2, ch1 = (2 * tid + 1) & 3;
    const int rA = lane & 15;
    const int cA = lane >> 4;

    const int mC0 = (m0 + r0c < MM) ? (m0 + r0c) : (MM - 1);
    const int mC1 = (m0 + r1c < MM) ? (m0 + r1c) : (MM - 1);
    int ia0[3], ia1[3];
    ia0[0] = occ1[mC0]; ia1[0] = occ1[mC1];
    ia0[1] = occ2[mC0]; ia1[1] = occ2[mC1];
    ia0[2] = (K > 1024) ? occ3[mC0] : 0;
    ia1[2] = (K > 1024) ? occ3[mC1] : 0;

    #define LOAD_STAGE_G(cc)                                                    \
    do {                                                                        \
        const int kb = (cc) << 5;                                               \
        const int sg_ = kb >> 9;                                                \
        const int ck = kb & 511;                                                \
        const uint32_t dst = sb + ((cc) & 1) * STAGE3;                          \
        CP_ASYNC16(dst + 0 * TILEB + r0c * RSZ + ch0 * 16,                      \
                   flatHi + (size_t)ia0[sg_] * D2H + ck + ch0 * 8);             \
        CP_ASYNC16(dst + 0 * TILEB + r1c * RSZ + ch1 * 16,                      \
                   flatHi + (size_t)ia1[sg_] * D2H + ck + ch1 * 8);             \
        CP_ASYNC16(dst + 1 * TILEB + r0c * RSZ + ch0 * 16,                      \
                   flatLo + (size_t)ia0[sg_] * D2H + ck + ch0 * 8);             \
        CP_ASYNC16(dst + 1 * TILEB + r1c * RSZ + ch1 * 16,                      \
                   flatLo + (size_t)ia1[sg_] * D2H + ck + ch1 * 8);             \
        CP_ASYNC16(dst + 2 * TILEB + r0c * RSZ + ch0 * 16,                      \
                   Bhi + (size_t)(n0 + r0c) * K + kb + ch0 * 8);                \
        CP_ASYNC16(dst + 2 * TILEB + r1c * RSZ + ch1 * 16,                      \
                   Bhi + (size_t)(n0 + r1c) * K + kb + ch1 * 8);                \
        CP_COMMIT();                                                            \
    } while (0)

    LOAD_STAGE_G(0);

    for (int c = 0; c < nch; ++c) {
        if (c + 1 < nch) { LOAD_STAGE_G(c + 1); CP_WAIT(1); }
        else             { CP_WAIT(0); }
        __syncthreads();

        const uint32_t s = sb + (c & 1) * STAGE3;
        const uint32_t aHiB = s, aLoB = s + TILEB, bHiB = s + 2 * TILEB;

        #pragma unroll
        for (int ks = 0; ks < 2; ++ks) {
            const uint32_t colOff = (uint32_t)(ks * 2 + cA) * 16;
            uint32_t aHi[4][4], bHi[4][2];
            #pragma unroll
            for (int mt = 0; mt < 4; ++mt) {
                uint32_t ad = (uint32_t)(wm * 64 + mt * 16 + rA) * RSZ + colOff;
                LDSM_X4(aHi[mt], aHiB + ad);
            }
            #pragma unroll
            for (int nh = 0; nh < 2; ++nh) {
                uint32_t bd = (uint32_t)(wn * 32 + nh * 16 + rA) * RSZ + colOff;
                uint32_t t[4];
                LDSM_X4(t, bHiB + bd);
                bHi[nh * 2 + 0][0] = t[0]; bHi[nh * 2 + 0][1] = t[2];
                bHi[nh * 2 + 1][0] = t[1]; bHi[nh * 2 + 1][1] = t[3];
            }
            #pragma unroll
            for (int mt = 0; mt < 4; ++mt)
                #pragma unroll
                for (int nt = 0; nt < 4; ++nt)
                    MMA_FP16(acc[mt][nt], aHi[mt], bHi[nt]);
            {
                uint32_t aLo[4][4];
                #pragma unroll
                for (int mt = 0; mt < 4; ++mt) {
                    uint32_t ad = (uint32_t)(wm * 64 + mt * 16 + rA) * RSZ + colOff;
                    LDSM_X4(aLo[mt], aLoB + ad);
                }
                #pragma unroll
                for (int mt = 0; mt < 4; ++mt)
                    #pragma unroll
                    for (int nt = 0; nt < 4; ++nt)
                        MMA_FP16(acc[mt][nt], aLo[mt], bHi[nt]);
            }
        }
        __syncthreads();
    }

    // ---- epilogue: fmap + atomicMax scatter into segment keys ----
    const int rr = lane >> 2, cc2 = (lane & 3) * 2;
    #pragma unroll
    for (int mt = 0; mt < 4; ++mt) {
        int rowL = wm * 64 + mt * 16 + rr;
        int mA = m0 + rowL, mB = mA + 8;
        int sgA = (mA < MM) ? seg[mA] : -1;
        int sgB = (mB < MM) ? seg[mB] : -1;
        #pragma unroll
        for (int nt = 0; nt < 4; ++nt) {
            int col = n0 + wn * 32 + nt * 8 + cc2;
            if (sgA >= 0) {
                unsigned* d = keys + (size_t)sgA * D2H + col;
                atomicMax(d,     fmap(acc[mt][nt][0]));
                atomicMax(d + 1, fmap(acc[mt][nt][1]));
            }
            if (sgB >= 0) {
                unsigned* d = keys + (size_t)sgB * D2H + col;
                atomicMax(d,     fmap(acc[mt][nt][2]));
                atomicMax(d + 1, fmap(acc[mt][nt][3]));
            }
        }
    }
    #undef LOAD_STAGE_G
}

// ---------------------------------------------------------------------------
// Pack kernels
// ---------------------------------------------------------------------------
__global__ void split_pad_kernel(const float* __restrict__ src,
                                 __half* __restrict__ hi,
                                 __half* __restrict__ lo,
                                 int rows, int sk, int dk) {
    size_t total = (size_t)rows * dk;
    for (size_t idx = blockIdx.x * (size_t)blockDim.x + threadIdx.x; idx < total;
         idx += (size_t)gridDim.x * blockDim.x) {
        int r = (int)(idx / dk), c = (int)(idx % dk);
        float f = (c < sk) ? src[(size_t)r * sk + c] : 0.0f;
        __half h, l; splith(f, h, l);
        hi[idx] = h; lo[idx] = l;
    }
}

// wih: src row g*256+j -> dst row j*4+g, pad K to EP; hi only + permuted bias
__global__ void pack_wih_kernel(const float* __restrict__ wih,
                                const float* __restrict__ b,
                                __half* __restrict__ hi,
                                float* __restrict__ pb) {
    const int total = G4 * EP;
    for (int idx = blockIdx.x * blockDim.x + threadIdx.x; idx < total;
         idx += gridDim.x * blockDim.x) {
        int rp = idx / EP, k = idx % EP;
        int j = rp >> 2, g = rp & 3;
        float f = (k < EE) ? wih[(size_t)(g * 256 + j) * EE + k] : 0.0f;
        hi[idx] = __float2half(f);
        if (k == 0) pb[rp] = b[g * 256 + j];
    }
}

// whh: src row g*256+j -> dst row j*4+g, K=256; hi + lo (3-term recurrence)
__global__ void pack_whh_kernel(const float* __restrict__ whh,
                                __half* __restrict__ hi,
                                __half* __restrict__ lo) {
    const int total = G4 * HH;
    for (int idx = blockIdx.x * blockDim.x + threadIdx.x; idx < total;
         idx += gridDim.x * blockDim.x) {
        int rp = idx >> 8, k = idx & 255;
        int j = rp >> 2, g = rp & 3;
        float v = whh[(size_t)(g * 256 + j) * HH + k];
        __half h, l; splith(v, h, l);
        hi[idx] = h; lo[idx] = l;
    }
}

// pairWT [3][512 n][1024 kk] = pair_hW[k][kk][n]  (hi only)
__global__ void pack_pairWT_kernel(const float* __restrict__ pair_hW,
                                   __half* __restrict__ hi) {
    const int total = 3 * D2H * G4;
    for (int idx = blockIdx.x * blockDim.x + threadIdx.x; idx < total;
         idx += gridDim.x * blockDim.x) {
        int k = idx / (D2H * G4);
        int rem = idx - k * (D2H * G4);
        int n = rem >> 10, kk = rem & 1023;
        hi[idx] = __float2half(pair_hW[(size_t)k * (G4 * D2H) + (size_t)kk * D2H + n]);
    }
}

// triWT [512 n][1536 kk] = tri_hW[kk][n]  (hi only)
__global__ void pack_triWT_kernel(const float* __restrict__ tri_hW,
                                  __half* __restrict__ hi) {
    const int total = D2H * 1536;
    for (int idx = blockIdx.x * blockDim.x + threadIdx.x; idx < total;
         idx += gridDim.x * blockDim.x) {
        int n = idx / 1536, kk = idx % 1536;
        hi[idx] = __float2half(tri_hW[(size_t)kk * D2H + n]);
    }
}

// allWT [512 n][2048 k] = all_hW[k][n]  (hi only)
__global__ void pack_allWT_kernel(const float* __restrict__ all_hW,
                                  __half* __restrict__ hi) {
    const int total = D2H * 2048;
    for (int idx = blockIdx.x * blockDim.x + threadIdx.x; idx < total;
         idx += gridDim.x * blockDim.x) {
        int n = idx >> 11, k = idx & 2047;
        hi[idx] = __float2half(all_hW[(size_t)k * D2H + n]);
    }
}

__global__ void zero_keys_kernel(unsigned* __restrict__ pk, unsigned* __restrict__ tk) {
    const size_t np = (size_t)3 * CC * D2H;
    const size_t nt = (size_t)CC * D2H;
    for (size_t i = blockIdx.x * (size_t)blockDim.x + threadIdx.x; i < np + nt;
         i += (size_t)gridDim.x * blockDim.x) {
        if (i < np) pk[i] = 0u; else tk[i - np] = 0u;
    }
}

// ---------------------------------------------------------------------------
// Persistent HMMA BiLSTM recurrence (fp16 3-term; structure = R7 winner)
// ---------------------------------------------------------------------------
#define PRSZ   528
#define LP_AHI 0
#define LP_ALO 16896
#define LP_BHI 33792
#define LP_BLO 101376
#define SMEM_LSTMP 168960

__global__ __launch_bounds__(256, 1)
void lstm_persist_kernel(const float* __restrict__ GxF,
                         const float* __restrict__ GxB,
                         const __half* __restrict__ whhHiF,
                         const __half* __restrict__ whhLoF,
                         const __half* __restrict__ whhHiB,
                         const __half* __restrict__ whhLoB,
                         __half* __restrict__ flatHi,
                         __half* __restrict__ flatLo) {
    extern __shared__ char smem[];
    const uint32_t sb = smem_u32(smem);
    const int tid = threadIdx.x, lane = tid & 31, wid = tid >> 5;
    const int dir = blockIdx.z;
    const int p0 = blockIdx.x * 32;
    const int c0 = blockIdx.y * 128;
    const int hcol = dir * HH;
    const float* Gx = dir ? GxB : GxF;
    const __half* Whi = dir ? whhHiB : whhHiF;
    const __half* Wlo = dir ? whhLoB : whhLoF;

    for (int ch = tid; ch < 128 * 32; ch += 256) {
        int row = ch >> 5, cb = ch & 31;
        size_t src = (size_t)(c0 + row) * HH + cb * 8;
        CP_ASYNC16(sb + LP_BHI + row * PRSZ + cb * 16, Whi + src);
        CP_ASYNC16(sb + LP_BLO + row * PRSZ + cb * 16, Wlo + src);
    }
    CP_COMMIT(); CP_WAIT(0);
    __syncthreads();

    float creg[2][2] = {{0.f, 0.f}, {0.f, 0.f}};
    const int rr = lane >> 2, cc2 = (lane & 3) * 2;
    const bool evenT = ((lane & 1) == 0);

    for (int s = 0; s < TT; ++s) {
        const int tcur = dir ? (TT - 1 - s) : s;

        float acc[2][2][4];
        #pragma unroll
        for (int i = 0; i < 2; ++i)
            #pragma unroll
            for (int j = 0; j < 2; ++j)
                #pragma unroll
                for (int q = 0; q < 4; ++q) acc[i][j][q] = 0.0f;

        if (s > 0) {
            dir_barrier(dir, tid, 64u);

            const int nprev = dir ? (tcur + 1) : (tcur - 1);
            for (int ch = tid; ch < 32 * 32; ch += 256) {
                int row = ch >> 5, cb = ch & 31;
                size_t src = (size_t)(nprev * PP + p0 + row) * D2H + hcol + cb * 8;
                CP_ASYNC16(sb + LP_AHI + row * PRSZ + cb * 16, flatHi + src);
                CP_ASYNC16(sb + LP_ALO + row * PRSZ + cb * 16, flatLo + src);
            }
            CP_COMMIT(); CP_WAIT(0);
            __syncthreads();

            #pragma unroll 4
            for (int kc = 0; kc < 16; ++kc) {
                const uint32_t colOff = (uint32_t)kc * 32 + (uint32_t)(lane >> 4) * 16;
                uint32_t aHi[2][4], bHi[2][2];
                #pragma unroll
                for (int mt = 0; mt < 2; ++mt) {
                    uint32_t ad = (uint32_t)(mt * 16 + (lane & 15)) * PRSZ + colOff;
                    LDSM_X4(aHi[mt], sb + LP_AHI + ad);
                }
                {
                    uint32_t bd = (uint32_t)(wid * 16 + (lane & 15)) * PRSZ + colOff;
                    uint32_t t[4];
                    LDSM_X4(t, sb + LP_BHI + bd);
                    bHi[0][0] = t[0]; bHi[0][1] = t[2];
                    bHi[1][0] = t[1]; bHi[1][1] = t[3];
                }
                #pragma unroll
                for (int mt = 0; mt < 2; ++mt)
                    #pragma unroll
                    for (int nt = 0; nt < 2; ++nt)
                        MMA_FP16(acc[mt][nt], aHi[mt], bHi[nt]);
                {
                    uint32_t aLo[2][4];
                    #pragma unroll
                    for (int mt = 0; mt < 2; ++mt) {
                        uint32_t ad = (uint32_t)(mt * 16 + (lane & 15)) * PRSZ + colOff;
                        LDSM_X4(aLo[mt], sb + LP_ALO + ad);
                    }
                    #pragma unroll
                    for (int mt = 0; mt < 2; ++mt)
                        #pragma unroll
                        for (int nt = 0; nt < 2; ++nt)
                            MMA_FP16(acc[mt][nt], aLo[mt], bHi[nt]);
                }
                {
                    uint32_t bLo[2][2];
                    uint32_t bd = (uint32_t)(wid * 16 + (lane & 15)) * PRSZ + colOff;
                    uint32_t t[4];
                    LDSM_X4(t, sb + LP_BLO + bd);
                    bLo[0][0] = t[0]; bLo[0][1] = t[2];
                    bLo[1][0] = t[1]; bLo[1][1] = t[3];
                    #pragma unroll
                    for (int mt = 0; mt < 2; ++mt)
                        #pragma unroll
                        for (int nt = 0; nt < 2; ++nt)
                            MMA_FP16(acc[mt][nt], aHi[mt], bLo[nt]);
                }
            }
        }

        #pragma unroll
        for (int mt = 0; mt < 2; ++mt) {
            #pragma unroll
            for (int nt = 0; nt < 2; ++nt) {
                int prow = p0 + mt * 16 + rr;
                int col = c0 + wid * 16 + nt * 8 + cc2;
                int j = col >> 2;
                size_t n0i = (size_t)tcur * PP + prow;
                size_t n1i = n0i + 8;
                float2 g0 = *(const float2*)&Gx[n0i * G4 + col];
                float2 g1 = *(const float2*)&Gx[n1i * G4 + col];
                float v0 = acc[mt][nt][0] + g0.x;
                float v1 = acc[mt][nt][1] + g0.y;
                float v2 = acc[mt][nt][2] + g1.x;
                float v3 = acc[mt][nt][3] + g1.y;
                float w0 = __shfl_xor_sync(0xffffffffu, v0, 1);
                float w1 = __shfl_xor_sync(0xffffffffu, v1, 1);
                float w2 = __shfl_xor_sync(0xffffffffu, v2, 1);
                float w3 = __shfl_xor_sync(0xffffffffu, v3, 1);
                float I, F, G, O;
                int p;
                if (evenT) { I = v0; F = v1; G = w0; O = w1; p = prow; }
                else       { I = w2; F = w3; G = v2; O = v3; p = prow + 8; }
                float cold = creg[mt][nt];
                float cn = sigmoidf_(F) * cold + sigmoidf_(I) * tanhf(G);
                float h = sigmoidf_(O) * tanhf(cn);
                creg[mt][nt] = cn;
                size_t nn = (size_t)tcur * PP + p;
                __half hh, hl; splith(h, hh, hl);
                flatHi[nn * D2H + hcol + j] = hh;
                flatLo[nn * D2H + hcol + j] = hl;
            }
        }
        __syncthreads();
    }
}

// ---------------------------------------------------------------------------
// Finalize kernels
// ---------------------------------------------------------------------------
__global__ __launch_bounds__(256)
void pair_final_kernel(const unsigned* __restrict__ keys,
                       const float* __restrict__ hb,
                       const float* __restrict__ backoff,
                       const float* __restrict__ oW,
                       const float* __restrict__ ob,
                       float* __restrict__ pv, float* __restrict__ out) {
    const int b = blockIdx.x;
    const int k = b >> 14;
    const unsigned* src = keys + (size_t)b * D2H;
    float partial = 0.0f;
    #pragma unroll
    for (int it = 0; it < 2; ++it) {
        int c = threadIdx.x + it * 256;
        unsigned u = src[c];
        float val = u ? (funmap(u) + hb[k * D2H + c]) : backoff[k * D2H + c];
        float t = tanhf(val);
        pv[(size_t)b * D2H + c] = t;
        partial += t * oW[k * D2H + c];
    }
    float tot = blockReduceSum256(partial);
    if (threadIdx.x == 0) out[CC + b] = tot + ob[k];
}

__global__ __launch_bounds__(256)
void tri_final_kernel(const unsigned* __restrict__ keys,
                      const float* __restrict__ hb,
                      const float* __restrict__ backoff,
                      float* __restrict__ tv) {
    const int s = blockIdx.x;
    const unsigned* src = keys + (size_t)s * D2H;
    #pragma unroll
    for (int it = 0; it < 2; ++it) {
        int c = threadIdx.x + it * 256;
        unsigned u = src[c];
        float val = u ? (funmap(u) + hb[c]) : backoff[c];
        tv[(size_t)s * D2H + c] = tanhf(val);
    }
}

__global__ void gather_feats_kernel(const float* __restrict__ pv,
                                    const float* __restrict__ tv,
                                    const int* __restrict__ tpi,
                                    __half* __restrict__ fhi,
                                    __half* __restrict__ flo) {
    const int s = blockIdx.x;
    const int i0 = tpi[s * 3 + 0];
    const int i1 = tpi[s * 3 + 1];
    const int i2 = tpi[s * 3 + 2];
    for (int j = threadIdx.x; j < 2048; j += blockDim.x) {
        int q = j >> 9, c = j & 511;
        float v;
        if (q == 0)      v = pv[((size_t)2 * CC + i0) * D2H + c];
        else if (q == 1) v = pv[((size_t)1 * CC + i1) * D2H + c];
        else if (q == 2) v = pv[(size_t)i2 * D2H + c];
        else             v = tv[(size_t)s * D2H + c];
        __half h, l; splith(v, h, l);
        fhi[(size_t)s * 2048 + j] = h;
        flo[(size_t)s * 2048 + j] = l;
    }
}

__global__ __launch_bounds__(256)
void triple_logit_kernel(const float* __restrict__ fin,
                         const float* __restrict__ tW,
                         const float* __restrict__ tb,
                         float* __restrict__ out) {
    const int s = blockIdx.x;
    float partial = 0.0f;
    #pragma unroll
    for (int it = 0; it < 2; ++it) {
        int c = threadIdx.x + it * 256;
        float v = fin[(size_t)s * D2H + c];
        v = v > 0.0f ? v : 0.0f;
        partial += v * tW[c];
    }
    float tot = blockReduceSum256(partial);
    if (threadIdx.x == 0) out[s] = tot + tb[0];
}

// ---------------------------------------------------------------------------
// Launcher
// ---------------------------------------------------------------------------
extern "C" void kernel_launch(void* const* d_in, const int* in_sizes, int n_in,
                              void* d_out, int out_size) {
    const float* x        = (const float*)d_in[0];
    const float* wih_f    = (const float*)d_in[1];
    const float* whh_f    = (const float*)d_in[2];
    const float* b_f      = (const float*)d_in[3];
    const float* wih_b    = (const float*)d_in[4];
    const float* whh_b    = (const float*)d_in[5];
    const float* b_b      = (const float*)d_in[6];
    const float* pair_hW  = (const float*)d_in[7];
    const float* pair_hb  = (const float*)d_in[8];
    const float* pair_oW  = (const float*)d_in[9];
    const float* pair_ob  = (const float*)d_in[10];
    const float* pair_bo  = (const float*)d_in[11];
    const float* tri_hW   = (const float*)d_in[12];
    const float* tri_hb   = (const float*)d_in[13];
    const float* tri_bo   = (const float*)d_in[14];
    const float* all_hW   = (const float*)d_in[15];
    const float* all_hb   = (const float*)d_in[16];
    const float* out_tW   = (const float*)d_in[17];
    const float* out_tb   = (const float*)d_in[18];
    const int*   occ1     = (const int*)d_in[19];
    const int*   occ2     = (const int*)d_in[20];
    const int*   seg      = (const int*)d_in[21];
    const int*   tri_o1   = (const int*)d_in[22];
    const int*   tri_o2   = (const int*)d_in[23];
    const int*   tri_o3   = (const int*)d_in[24];
    const int*   tri_seg  = (const int*)d_in[25];
    const int*   tri_pi   = (const int*)d_in[26];
    float* out = (float*)d_out;

    float *GxF, *GxB, *pv, *tv, *fin, *pbF, *pbB;
    unsigned *pk, *tk;
    __half *xHi, *xLo, *wHiF, *wHiB, *flHi, *flLo;
    __half *whF, *wlF, *whB, *wlB;
    __half *pwHi, *twHi, *awHi, *ftHi, *ftLo;
    cudaGetSymbolAddress((void**)&GxF,  g_GxF);
    cudaGetSymbolAddress((void**)&GxB,  g_GxB);
    cudaGetSymbolAddress((void**)&pk,   g_pairKeys);
    cudaGetSymbolAddress((void**)&tk,   g_triKeys);
    cudaGetSymbolAddress((void**)&pv,   g_pv);
    cudaGetSymbolAddress((void**)&tv,   g_tv);
    cudaGetSymbolAddress((void**)&fin,  g_final);
    cudaGetSymbolAddress((void**)&pbF,  g_pbF);
    cudaGetSymbolAddress((void**)&pbB,  g_pbB);
    cudaGetSymbolAddress((void**)&xHi,  g_xHi);
    cudaGetSymbolAddress((void**)&xLo,  g_xLo);
    cudaGetSymbolAddress((void**)&wHiF, g_wHiF);
    cudaGetSymbolAddress((void**)&wHiB, g_wHiB);
    cudaGetSymbolAddress((void**)&whF,  g_whhHiF);
    cudaGetSymbolAddress((void**)&wlF,  g_whhLoF);
    cudaGetSymbolAddress((void**)&whB,  g_whhHiB);
    cudaGetSymbolAddress((void**)&wlB,  g_whhLoB);
    cudaGetSymbolAddress((void**)&flHi, g_flatHi);
    cudaGetSymbolAddress((void**)&flLo, g_flatLo);
    cudaGetSymbolAddress((void**)&pwHi, g_pwHi);
    cudaGetSymbolAddress((void**)&twHi, g_twHi);
    cudaGetSymbolAddress((void**)&awHi, g_aWHi);
    cudaGetSymbolAddress((void**)&ftHi, g_ftHi);
    cudaGetSymbolAddress((void**)&ftLo, g_ftLo);

    cudaFuncSetAttribute(gemm_fp16x2_kernel,
                         cudaFuncAttributeMaxDynamicSharedMemorySize, SMEM_GEMM);
    cudaFuncSetAttribute(gemm_gsc_kernel,
                         cudaFuncAttributeMaxDynamicSharedMemorySize, SMEM_GEMM);
    cudaFuncSetAttribute(lstm_persist_kernel,
                         cudaFuncAttributeMaxDynamicSharedMemorySize, SMEM_LSTMP);

    // 1) split/pack operands (fp16)
    split_pad_kernel<<<4096, 256>>>(x, xHi, xLo, NPOS, EE, EP);
    pack_wih_kernel<<<512, 256>>>(wih_f, b_f, wHiF, pbF);
    pack_wih_kernel<<<512, 256>>>(wih_b, b_b, wHiB, pbB);
    pack_whh_kernel<<<512, 256>>>(whh_f, whF, wlF);
    pack_whh_kernel<<<512, 256>>>(whh_b, whB, wlB);
    pack_pairWT_kernel<<<3072, 256>>>(pair_hW, pwHi);
    pack_triWT_kernel<<<1536, 256>>>(tri_hW, twHi);
    pack_allWT_kernel<<<1024, 256>>>(all_hW, awHi);

    // 2) input projections (gate-permuted cols): Gx = (xHi+xLo) @ wihHi^T + pb
    gemm_fp16x2_kernel<<<dim3(8, 512), 256, SMEM_GEMM>>>(xHi, xLo, wHiF, pbF, GxF, EP);
    gemm_fp16x2_kernel<<<dim3(8, 512), 256, SMEM_GEMM>>>(xHi, xLo, wHiB, pbB, GxB, EP);

    // 3) zero segment-max keys
    zero_keys_kernel<<<32768, 256>>>(pk, tk);

    // 4) BiLSTM recurrence: persistent HMMA kernel (fp16 3-term)
    lstm_persist_kernel<<<dim3(8, 8, 2), 256, SMEM_LSTMP>>>(
        GxF, GxB, whF, wlF, whB, wlB, flHi, flLo);

    // 5) gather-GEMM-scatter: pair types + triples (fp16 2-term)
    for (int k = 0; k < 3; ++k)
        gemm_gsc_kernel<<<dim3(4, MTILES), 256, SMEM_GEMM>>>(
            flHi, flLo, pwHi + (size_t)k * D2H * G4,
            occ1 + k * MM, occ2 + k * MM, occ1 + k * MM,
            seg + k * MM, pk + (size_t)k * CC * D2H, G4);
    gemm_gsc_kernel<<<dim3(4, MTILES), 256, SMEM_GEMM>>>(
        flHi, flLo, twHi, tri_o1, tri_o2, tri_o3, tri_seg, tk, 1536);

    // 6) finalize pooled vectors (+ pair logits)
    pair_final_kernel<<<3 * CC, 256>>>(pk, pair_hb, pair_bo, pair_oW, pair_ob, pv, out);
    tri_final_kernel<<<CC, 256>>>(tk, tri_hb, tri_bo, tv);

    // 7) final MLP + triple logits (fp16 2-term)
    gather_feats_kernel<<<CC, 256>>>(pv, tv, tri_pi, ftHi, ftLo);
    gemm_fp16x2_kernel<<<dim3(D2H / 128, CC / 128), 256, SMEM_GEMM>>>(
        ftHi, ftLo, awHi, all_hb, fin, 2048);
    triple_logit_kernel<<<CC, 256>>>(fin, out_tW, out_tb, out);
}

// round 10
// speedup vs baseline: 2.4421x; 1.1581x over previous
#include <cuda_runtime.h>
#include <cuda_fp16.h>
#include <math.h>
#include <stdint.h>

// ---------------------------------------------------------------------------
// Problem constants
// ---------------------------------------------------------------------------
#define TT   256
#define PP   256
#define EE   300
#define HH   256
#define NPOS 65536            // T*P
#define G4   1024             // 4H
#define D2H  512              // 2H
#define MM   50000
#define CC   16384
#define EP   320              // E padded to multiple of 32
#define MTILES ((MM + 127) / 128)   // 391

// ---------------------------------------------------------------------------
// Device scratch (static allocations only)
// ---------------------------------------------------------------------------
__device__ float    g_GxF[(size_t)NPOS * G4];          // 268 MB (cols j*4+g)
__device__ float    g_GxB[(size_t)NPOS * G4];          // 268 MB
__device__ unsigned g_pairKeys[(size_t)3 * CC * D2H];  // 100 MB
__device__ unsigned g_triKeys[(size_t)CC * D2H];       // 33 MB
__device__ float    g_pv[(size_t)3 * CC * D2H];        // 100 MB
__device__ float    g_tv[(size_t)CC * D2H];            // 33 MB
__device__ float    g_final[(size_t)CC * D2H];         // 33 MB
__device__ float    g_pbF[G4];                         // permuted biases
__device__ float    g_pbB[G4];
__device__ unsigned g_barCnt[2];                       // global barrier state
__device__ unsigned g_barGen[2];

// fp16 split operand buffers
__device__ __half g_xHi[(size_t)NPOS * EP];            // 42 MB
__device__ __half g_xLo[(size_t)NPOS * EP];
__device__ __half g_wHiF[(size_t)G4 * EP];             // packed rows j*4+g (hi only)
__device__ __half g_wHiB[(size_t)G4 * EP];
__device__ __half g_whhHiF[(size_t)G4 * HH];           // packed rows j*4+g
__device__ __half g_whhLoF[(size_t)G4 * HH];
__device__ __half g_whhHiB[(size_t)G4 * HH];
__device__ __half g_whhLoB[(size_t)G4 * HH];
__device__ __half g_flatHi[(size_t)NPOS * D2H];        // 67 MB
__device__ __half g_flatLo[(size_t)NPOS * D2H];        // used by LSTM only
__device__ __half g_pwHi[(size_t)3 * D2H * G4];        // pairWT [3][512][1024]
__device__ __half g_twHi[(size_t)D2H * 1536];          // triWT [512][1536]
__device__ __half g_aWHi[(size_t)D2H * 2048];
__device__ __half g_ftHi[(size_t)CC * 2048];           // 67 MB
__device__ __half g_ftLo[(size_t)CC * 2048];

// ---------------------------------------------------------------------------
// Helpers
// ---------------------------------------------------------------------------
__device__ __forceinline__ uint32_t smem_u32(const void* p) {
    uint32_t a;
    asm("{ .reg .u64 t; cvta.to.shared.u64 t, %1; cvt.u32.u64 %0, t; }"
        : "=r"(a) : "l"(p));
    return a;
}

#define LDSM_X4(r, addr) \
    asm volatile("ldmatrix.sync.aligned.m8n8.x4.shared.b16 {%0,%1,%2,%3}, [%4];" \
        : "=r"((r)[0]), "=r"((r)[1]), "=r"((r)[2]), "=r"((r)[3]) : "r"(addr))

#define MMA_FP16(d, a, b) \
    asm volatile("mma.sync.aligned.m16n8k16.row.col.f32.f16.f16.f32 " \
        "{%0,%1,%2,%3}, {%4,%5,%6,%7}, {%8,%9}, {%0,%1,%2,%3};" \
        : "+f"((d)[0]), "+f"((d)[1]), "+f"((d)[2]), "+f"((d)[3]) \
        : "r"((a)[0]), "r"((a)[1]), "r"((a)[2]), "r"((a)[3]), \
          "r"((b)[0]), "r"((b)[1]))

#define CP_ASYNC16(dst, src) \
    asm volatile("cp.async.cg.shared.global [%0], [%1], 16;" \
                 :: "r"(dst), "l"(src))
#define CP_COMMIT() asm volatile("cp.async.commit_group;" ::: "memory")
#define CP_WAIT(n)  asm volatile("cp.async.wait_group %0;" :: "n"(n) : "memory")

__device__ __forceinline__ float sigmoidf_(float x) { return 1.0f / (1.0f + expf(-x)); }

__device__ __forceinline__ unsigned fmap(float f) {
    unsigned b = __float_as_uint(f);
    return (b & 0x80000000u) ? ~b : (b | 0x80000000u);
}
__device__ __forceinline__ float funmap(unsigned u) {
    return (u & 0x80000000u) ? __uint_as_float(u & 0x7FFFFFFFu)
                             : __uint_as_float(~u);
}
__device__ __forceinline__ float warpReduceSum(float v) {
    #pragma unroll
    for (int o = 16; o > 0; o >>= 1) v += __shfl_down_sync(0xffffffffu, v, o);
    return v;
}
__device__ __forceinline__ float blockReduceSum256(float v) {
    __shared__ float sh[8];
    int lane = threadIdx.x & 31, wid = threadIdx.x >> 5;
    v = warpReduceSum(v);
    if (lane == 0) sh[wid] = v;
    __syncthreads();
    v = (threadIdx.x < 8) ? sh[threadIdx.x] : 0.0f;
    if (wid == 0) v = warpReduceSum(v);
    return v;
}
__device__ __forceinline__ void splith(float f, __half& h, __half& l) {
    h = __float2half(f);
    l = __float2half(f - __half2float(h));
}

// per-direction grid barrier
__device__ __forceinline__ void dir_barrier(int dir, int tid, unsigned nCTA) {
    __syncthreads();
    if (tid == 0) {
        __threadfence();
        unsigned gen = atomicAdd(&g_barGen[dir], 0u);
        unsigned prev = atomicAdd(&g_barCnt[dir], 1u);
        if (prev == nCTA - 1u) {
            atomicExch(&g_barCnt[dir], 0u);
            __threadfence();
            atomicAdd(&g_barGen[dir], 1u);
        } else {
            while (atomicAdd(&g_barGen[dir], 0u) == gen) { __nanosleep(32); }
        }
        __threadfence();
    }
    __syncthreads();
}

// ---------------------------------------------------------------------------
// fp16 2-term split GEMM: C[M,N] = (Ahi+Alo)[M,K] @ Bhi[N,K]^T + bias
// CTA tile 128x128, 256 threads (8 warps: 2 M x 4 N; warp tile 64x32).
// ---------------------------------------------------------------------------
#define RSZ   80
#define TILEB (128 * RSZ)       // 10240
#define STAGE3 (3 * TILEB)      // 30720 (Ahi, Alo, Bhi)
#define SMEM_GEMM (2 * STAGE3)  // 61440

__global__ __launch_bounds__(256, 2)
void gemm_fp16x2_kernel(const __half* __restrict__ Ahi,
                        const __half* __restrict__ Alo,
                        const __half* __restrict__ Bhi,
                        const float* __restrict__ bias,
                        float* __restrict__ C, int K) {
    extern __shared__ char smem[];
    const uint32_t sb = smem_u32(smem);
    const int tid = threadIdx.x, lane = tid & 31, wid = tid >> 5;
    const int m0 = blockIdx.y * 128, n0 = blockIdx.x * 128;
    const int ldc = gridDim.x * 128;
    const int wm = wid & 1, wn = wid >> 1;

    float acc[4][4][4];
    #pragma unroll
    for (int i = 0; i < 4; ++i)
        #pragma unroll
        for (int j = 0; j < 4; ++j)
            #pragma unroll
            for (int q = 0; q < 4; ++q) acc[i][j][q] = 0.0f;

    const int nch = K >> 5;
    const int r0c = (2 * tid) >> 2, ch0 = (2 * tid) & 3;
    const int r1c = (2 * tid + 1) >> 2, ch1 = (2 * tid + 1) & 3;
    const int rA = lane & 15;
    const int cA = lane >> 4;

    #define LOAD_STAGE(cc)                                                      \
    do {                                                                        \
        const int kb = (cc) << 5;                                               \
        const uint32_t dst = sb + ((cc) & 1) * STAGE3;                          \
        CP_ASYNC16(dst + 0 * TILEB + r0c * RSZ + ch0 * 16,                      \
                   Ahi + (size_t)(m0 + r0c) * K + kb + ch0 * 8);                \
        CP_ASYNC16(dst + 0 * TILEB + r1c * RSZ + ch1 * 16,                      \
                   Ahi + (size_t)(m0 + r1c) * K + kb + ch1 * 8);                \
        CP_ASYNC16(dst + 1 * TILEB + r0c * RSZ + ch0 * 16,                      \
                   Alo + (size_t)(m0 + r0c) * K + kb + ch0 * 8);                \
        CP_ASYNC16(dst + 1 * TILEB + r1c * RSZ + ch1 * 16,                      \
                   Alo + (size_t)(m0 + r1c) * K + kb + ch1 * 8);                \
        CP_ASYNC16(dst + 2 * TILEB + r0c * RSZ + ch0 * 16,                      \
                   Bhi + (size_t)(n0 + r0c) * K + kb + ch0 * 8);                \
        CP_ASYNC16(dst + 2 * TILEB + r1c * RSZ + ch1 * 16,                      \
                   Bhi + (size_t)(n0 + r1c) * K + kb + ch1 * 8);                \
        CP_COMMIT();                                                            \
    } while (0)

    LOAD_STAGE(0);

    for (int c = 0; c < nch; ++c) {
        if (c + 1 < nch) { LOAD_STAGE(c + 1); CP_WAIT(1); }
        else             { CP_WAIT(0); }
        __syncthreads();

        const uint32_t s = sb + (c & 1) * STAGE3;
        const uint32_t aHiB = s, aLoB = s + TILEB, bHiB = s + 2 * TILEB;

        #pragma unroll
        for (int ks = 0; ks < 2; ++ks) {
            const uint32_t colOff = (uint32_t)(ks * 2 + cA) * 16;
            uint32_t aHi[4][4], bHi[4][2];
            #pragma unroll
            for (int mt = 0; mt < 4; ++mt) {
                uint32_t ad = (uint32_t)(wm * 64 + mt * 16 + rA) * RSZ + colOff;
                LDSM_X4(aHi[mt], aHiB + ad);
            }
            #pragma unroll
            for (int nh = 0; nh < 2; ++nh) {
                uint32_t bd = (uint32_t)(wn * 32 + nh * 16 + rA) * RSZ + colOff;
                uint32_t t[4];
                LDSM_X4(t, bHiB + bd);
                bHi[nh * 2 + 0][0] = t[0]; bHi[nh * 2 + 0][1] = t[2];
                bHi[nh * 2 + 1][0] = t[1]; bHi[nh * 2 + 1][1] = t[3];
            }
            #pragma unroll
            for (int mt = 0; mt < 4; ++mt)
                #pragma unroll
                for (int nt = 0; nt < 4; ++nt)
                    MMA_FP16(acc[mt][nt], aHi[mt], bHi[nt]);
            {
                uint32_t aLo[4][4];
                #pragma unroll
                for (int mt = 0; mt < 4; ++mt) {
                    uint32_t ad = (uint32_t)(wm * 64 + mt * 16 + rA) * RSZ + colOff;
                    LDSM_X4(aLo[mt], aLoB + ad);
                }
                #pragma unroll
                for (int mt = 0; mt < 4; ++mt)
                    #pragma unroll
                    for (int nt = 0; nt < 4; ++nt)
                        MMA_FP16(acc[mt][nt], aLo[mt], bHi[nt]);
            }
        }
        __syncthreads();
    }

    const int rr = lane >> 2, cc2 = (lane & 3) * 2;
    #pragma unroll
    for (int mt = 0; mt < 4; ++mt) {
        #pragma unroll
        for (int nt = 0; nt < 4; ++nt) {
            int row = m0 + wm * 64 + mt * 16 + rr;
            int col = n0 + wn * 32 + nt * 8 + cc2;
            float b0 = 0.f, b1 = 0.f;
            if (bias) { b0 = bias[col]; b1 = bias[col + 1]; }
            float2 v0 = make_float2(acc[mt][nt][0] + b0, acc[mt][nt][1] + b1);
            float2 v1 = make_float2(acc[mt][nt][2] + b0, acc[mt][nt][3] + b1);
            *(float2*)&C[(size_t)row * ldc + col] = v0;
            *(float2*)&C[(size_t)(row + 8) * ldc + col] = v1;
        }
    }
    #undef LOAD_STAGE
}

// ---------------------------------------------------------------------------
// Gather-GEMM-scatter (fp16 1-term): rep[m] = concat(flatHi[occ..]) @ Bhi^T,
// then atomicMax into keys[seg[m]] (fmap-encoded). A & B hi-only.
// ---------------------------------------------------------------------------
#define STAGE2 (2 * TILEB)      // 20480 (Ahi, Bhi)
#define SMEM_GSC (2 * STAGE2)   // 40960

__global__ __launch_bounds__(256, 2)
void gemm_gsc_kernel(const __half* __restrict__ flatHi,
                     const __half* __restrict__ Bhi,
                     const int* __restrict__ occ1,
                     const int* __restrict__ occ2,
                     const int* __restrict__ occ3,
                     const int* __restrict__ seg,
                     unsigned* __restrict__ keys, int K) {
    extern __shared__ char smem[];
    const uint32_t sb = smem_u32(smem);
    const int tid = threadIdx.x, lane = tid & 31, wid = tid >> 5;
    const int m0 = blockIdx.y * 128, n0 = blockIdx.x * 128;
    const int wm = wid & 1, wn = wid >> 1;

    float acc[4][4][4];
    #pragma unroll
    for (int i = 0; i < 4; ++i)
        #pragma unroll
        for (int j = 0; j < 4; ++j)
            #pragma unroll
            for (int q = 0; q < 4; ++q) acc[i][j][q] = 0.0f;

    const int nch = K >> 5;
    const int r0c = (2 * tid) >> 2, ch0 = (2 * tid) & 3;
    const int r1c = (2 * tid + 1) >> 2, ch1 = (2 * tid + 1) & 3;
    const int rA = lane & 15;
    const int cA = lane >> 4;

    const int mC0 = (m0 + r0c < MM) ? (m0 + r0c) : (MM - 1);
    const int mC1 = (m0 + r1c < MM) ? (m0 + r1c) : (MM - 1);
    int ia0[3], ia1[3];
    ia0[0] = occ1[mC0]; ia1[0] = occ1[mC1];
    ia0[1] = occ2[mC0]; ia1[1] = occ2[mC1];
    ia0[2] = (K > 1024) ? occ3[mC0] : 0;
    ia1[2] = (K > 1024) ? occ3[mC1] : 0;

    #define LOAD_STAGE_G(cc)                                                    \
    do {                                                                        \
        const int kb = (cc) << 5;                                               \
        const int sg_ = kb >> 9;                                                \
        const int ck = kb & 511;                                                \
        const uint32_t dst = sb + ((cc) & 1) * STAGE2;                          \
        CP_ASYNC16(dst + 0 * TILEB + r0c * RSZ + ch0 * 16,                      \
                   flatHi + (size_t)ia0[sg_] * D2H + ck + ch0 * 8);             \
        CP_ASYNC16(dst + 0 * TILEB + r1c * RSZ + ch1 * 16,                      \
                   flatHi + (size_t)ia1[sg_] * D2H + ck + ch1 * 8);             \
        CP_ASYNC16(dst + 1 * TILEB + r0c * RSZ + ch0 * 16,                      \
                   Bhi + (size_t)(n0 + r0c) * K + kb + ch0 * 8);                \
        CP_ASYNC16(dst + 1 * TILEB + r1c * RSZ + ch1 * 16,                      \
                   Bhi + (size_t)(n0 + r1c) * K + kb + ch1 * 8);                \
        CP_COMMIT();                                                            \
    } while (0)

    LOAD_STAGE_G(0);

    for (int c = 0; c < nch; ++c) {
        if (c + 1 < nch) { LOAD_STAGE_G(c + 1); CP_WAIT(1); }
        else             { CP_WAIT(0); }
        __syncthreads();

        const uint32_t s = sb + (c & 1) * STAGE2;
        const uint32_t aHiB = s, bHiB = s + TILEB;

        #pragma unroll
        for (int ks = 0; ks < 2; ++ks) {
            const uint32_t colOff = (uint32_t)(ks * 2 + cA) * 16;
            uint32_t aHi[4][4], bHi[4][2];
            #pragma unroll
            for (int mt = 0; mt < 4; ++mt) {
                uint32_t ad = (uint32_t)(wm * 64 + mt * 16 + rA) * RSZ + colOff;
                LDSM_X4(aHi[mt], aHiB + ad);
            }
            #pragma unroll
            for (int nh = 0; nh < 2; ++nh) {
                uint32_t bd = (uint32_t)(wn * 32 + nh * 16 + rA) * RSZ + colOff;
                uint32_t t[4];
                LDSM_X4(t, bHiB + bd);
                bHi[nh * 2 + 0][0] = t[0]; bHi[nh * 2 + 0][1] = t[2];
                bHi[nh * 2 + 1][0] = t[1]; bHi[nh * 2 + 1][1] = t[3];
            }
            #pragma unroll
            for (int mt = 0; mt < 4; ++mt)
                #pragma unroll
                for (int nt = 0; nt < 4; ++nt)
                    MMA_FP16(acc[mt][nt], aHi[mt], bHi[nt]);
        }
        __syncthreads();
    }

    // ---- epilogue: fmap + atomicMax scatter into segment keys ----
    const int rr = lane >> 2, cc2 = (lane & 3) * 2;
    #pragma unroll
    for (int mt = 0; mt < 4; ++mt) {
        int rowL = wm * 64 + mt * 16 + rr;
        int mA = m0 + rowL, mB = mA + 8;
        int sgA = (mA < MM) ? seg[mA] : -1;
        int sgB = (mB < MM) ? seg[mB] : -1;
        #pragma unroll
        for (int nt = 0; nt < 4; ++nt) {
            int col = n0 + wn * 32 + nt * 8 + cc2;
            if (sgA >= 0) {
                unsigned* d = keys + (size_t)sgA * D2H + col;
                atomicMax(d,     fmap(acc[mt][nt][0]));
                atomicMax(d + 1, fmap(acc[mt][nt][1]));
            }
            if (sgB >= 0) {
                unsigned* d = keys + (size_t)sgB * D2H + col;
                atomicMax(d,     fmap(acc[mt][nt][2]));
                atomicMax(d + 1, fmap(acc[mt][nt][3]));
            }
        }
    }
    #undef LOAD_STAGE_G
}

// ---------------------------------------------------------------------------
// Pack kernels
// ---------------------------------------------------------------------------
__global__ void split_pad_kernel(const float* __restrict__ src,
                                 __half* __restrict__ hi,
                                 __half* __restrict__ lo,
                                 int rows, int sk, int dk) {
    size_t total = (size_t)rows * dk;
    for (size_t idx = blockIdx.x * (size_t)blockDim.x + threadIdx.x; idx < total;
         idx += (size_t)gridDim.x * blockDim.x) {
        int r = (int)(idx / dk), c = (int)(idx % dk);
        float f = (c < sk) ? src[(size_t)r * sk + c] : 0.0f;
        __half h, l; splith(f, h, l);
        hi[idx] = h; lo[idx] = l;
    }
}

__global__ void pack_wih_kernel(const float* __restrict__ wih,
                                const float* __restrict__ b,
                                __half* __restrict__ hi,
                                float* __restrict__ pb) {
    const int total = G4 * EP;
    for (int idx = blockIdx.x * blockDim.x + threadIdx.x; idx < total;
         idx += gridDim.x * blockDim.x) {
        int rp = idx / EP, k = idx % EP;
        int j = rp >> 2, g = rp & 3;
        float f = (k < EE) ? wih[(size_t)(g * 256 + j) * EE + k] : 0.0f;
        hi[idx] = __float2half(f);
        if (k == 0) pb[rp] = b[g * 256 + j];
    }
}

__global__ void pack_whh_kernel(const float* __restrict__ whh,
                                __half* __restrict__ hi,
                                __half* __restrict__ lo) {
    const int total = G4 * HH;
    for (int idx = blockIdx.x * blockDim.x + threadIdx.x; idx < total;
         idx += gridDim.x * blockDim.x) {
        int rp = idx >> 8, k = idx & 255;
        int j = rp >> 2, g = rp & 3;
        float v = whh[(size_t)(g * 256 + j) * HH + k];
        __half h, l; splith(v, h, l);
        hi[idx] = h; lo[idx] = l;
    }
}

__global__ void pack_pairWT_kernel(const float* __restrict__ pair_hW,
                                   __half* __restrict__ hi) {
    const int total = 3 * D2H * G4;
    for (int idx = blockIdx.x * blockDim.x + threadIdx.x; idx < total;
         idx += gridDim.x * blockDim.x) {
        int k = idx / (D2H * G4);
        int rem = idx - k * (D2H * G4);
        int n = rem >> 10, kk = rem & 1023;
        hi[idx] = __float2half(pair_hW[(size_t)k * (G4 * D2H) + (size_t)kk * D2H + n]);
    }
}

__global__ void pack_triWT_kernel(const float* __restrict__ tri_hW,
                                  __half* __restrict__ hi) {
    const int total = D2H * 1536;
    for (int idx = blockIdx.x * blockDim.x + threadIdx.x; idx < total;
         idx += gridDim.x * blockDim.x) {
        int n = idx / 1536, kk = idx % 1536;
        hi[idx] = __float2half(tri_hW[(size_t)kk * D2H + n]);
    }
}

__global__ void pack_allWT_kernel(const float* __restrict__ all_hW,
                                  __half* __restrict__ hi) {
    const int total = D2H * 2048;
    for (int idx = blockIdx.x * blockDim.x + threadIdx.x; idx < total;
         idx += gridDim.x * blockDim.x) {
        int n = idx >> 11, k = idx & 2047;
        hi[idx] = __float2half(all_hW[(size_t)k * D2H + n]);
    }
}

__global__ void zero_keys_kernel(unsigned* __restrict__ pk, unsigned* __restrict__ tk) {
    const size_t np = (size_t)3 * CC * D2H;
    const size_t nt = (size_t)CC * D2H;
    for (size_t i = blockIdx.x * (size_t)blockDim.x + threadIdx.x; i < np + nt;
         i += (size_t)gridDim.x * blockDim.x) {
        if (i < np) pk[i] = 0u; else tk[i - np] = 0u;
    }
}

// ---------------------------------------------------------------------------
// Persistent HMMA BiLSTM recurrence (fp16 3-term; R7 structure)
// ---------------------------------------------------------------------------
#define PRSZ   528
#define LP_AHI 0
#define LP_ALO 16896
#define LP_BHI 33792
#define LP_BLO 101376
#define SMEM_LSTMP 168960

__global__ __launch_bounds__(256, 1)
void lstm_persist_kernel(const float* __restrict__ GxF,
                         const float* __restrict__ GxB,
                         const __half* __restrict__ whhHiF,
                         const __half* __restrict__ whhLoF,
                         const __half* __restrict__ whhHiB,
                         const __half* __restrict__ whhLoB,
                         __half* __restrict__ flatHi,
                         __half* __restrict__ flatLo) {
    extern __shared__ char smem[];
    const uint32_t sb = smem_u32(smem);
    const int tid = threadIdx.x, lane = tid & 31, wid = tid >> 5;
    const int dir = blockIdx.z;
    const int p0 = blockIdx.x * 32;
    const int c0 = blockIdx.y * 128;
    const int hcol = dir * HH;
    const float* Gx = dir ? GxB : GxF;
    const __half* Whi = dir ? whhHiB : whhHiF;
    const __half* Wlo = dir ? whhLoB : whhLoF;

    for (int ch = tid; ch < 128 * 32; ch += 256) {
        int row = ch >> 5, cb = ch & 31;
        size_t src = (size_t)(c0 + row) * HH + cb * 8;
        CP_ASYNC16(sb + LP_BHI + row * PRSZ + cb * 16, Whi + src);
        CP_ASYNC16(sb + LP_BLO + row * PRSZ + cb * 16, Wlo + src);
    }
    CP_COMMIT(); CP_WAIT(0);
    __syncthreads();

    float creg[2][2] = {{0.f, 0.f}, {0.f, 0.f}};
    const int rr = lane >> 2, cc2 = (lane & 3) * 2;
    const bool evenT = ((lane & 1) == 0);

    for (int s = 0; s < TT; ++s) {
        const int tcur = dir ? (TT - 1 - s) : s;

        float acc[2][2][4];
        #pragma unroll
        for (int i = 0; i < 2; ++i)
            #pragma unroll
            for (int j = 0; j < 2; ++j)
                #pragma unroll
                for (int q = 0; q < 4; ++q) acc[i][j][q] = 0.0f;

        if (s > 0) {
            dir_barrier(dir, tid, 64u);

            const int nprev = dir ? (tcur + 1) : (tcur - 1);
            for (int ch = tid; ch < 32 * 32; ch += 256) {
                int row = ch >> 5, cb = ch & 31;
                size_t src = (size_t)(nprev * PP + p0 + row) * D2H + hcol + cb * 8;
                CP_ASYNC16(sb + LP_AHI + row * PRSZ + cb * 16, flatHi + src);
                CP_ASYNC16(sb + LP_ALO + row * PRSZ + cb * 16, flatLo + src);
            }
            CP_COMMIT(); CP_WAIT(0);
            __syncthreads();

            #pragma unroll 4
            for (int kc = 0; kc < 16; ++kc) {
                const uint32_t colOff = (uint32_t)kc * 32 + (uint32_t)(lane >> 4) * 16;
                uint32_t aHi[2][4], bHi[2][2];
                #pragma unroll
                for (int mt = 0; mt < 2; ++mt) {
                    uint32_t ad = (uint32_t)(mt * 16 + (lane & 15)) * PRSZ + colOff;
                    LDSM_X4(aHi[mt], sb + LP_AHI + ad);
                }
                {
                    uint32_t bd = (uint32_t)(wid * 16 + (lane & 15)) * PRSZ + colOff;
                    uint32_t t[4];
                    LDSM_X4(t, sb + LP_BHI + bd);
                    bHi[0][0] = t[0]; bHi[0][1] = t[2];
                    bHi[1][0] = t[1]; bHi[1][1] = t[3];
                }
                #pragma unroll
                for (int mt = 0; mt < 2; ++mt)
                    #pragma unroll
                    for (int nt = 0; nt < 2; ++nt)
                        MMA_FP16(acc[mt][nt], aHi[mt], bHi[nt]);
                {
                    uint32_t aLo[2][4];
                    #pragma unroll
                    for (int mt = 0; mt < 2; ++mt) {
                        uint32_t ad = (uint32_t)(mt * 16 + (lane & 15)) * PRSZ + colOff;
                        LDSM_X4(aLo[mt], sb + LP_ALO + ad);
                    }
                    #pragma unroll
                    for (int mt = 0; mt < 2; ++mt)
                        #pragma unroll
                        for (int nt = 0; nt < 2; ++nt)
                            MMA_FP16(acc[mt][nt], aLo[mt], bHi[nt]);
                }
                {
                    uint32_t bLo[2][2];
                    uint32_t bd = (uint32_t)(wid * 16 + (lane & 15)) * PRSZ + colOff;
                    uint32_t t[4];
                    LDSM_X4(t, sb + LP_BLO + bd);
                    bLo[0][0] = t[0]; bLo[0][1] = t[2];
                    bLo[1][0] = t[1]; bLo[1][1] = t[3];
                    #pragma unroll
                    for (int mt = 0; mt < 2; ++mt)
                        #pragma unroll
                        for (int nt = 0; nt < 2; ++nt)
                            MMA_FP16(acc[mt][nt], aHi[mt], bLo[nt]);
                }
            }
        }

        #pragma unroll
        for (int mt = 0; mt < 2; ++mt) {
            #pragma unroll
            for (int nt = 0; nt < 2; ++nt) {
                int prow = p0 + mt * 16 + rr;
                int col = c0 + wid * 16 + nt * 8 + cc2;
                int j = col >> 2;
                size_t n0i = (size_t)tcur * PP + prow;
                size_t n1i = n0i + 8;
                float2 g0 = *(const float2*)&Gx[n0i * G4 + col];
                float2 g1 = *(const float2*)&Gx[n1i * G4 + col];
                float v0 = acc[mt][nt][0] + g0.x;
                float v1 = acc[mt][nt][1] + g0.y;
                float v2 = acc[mt][nt][2] + g1.x;
                float v3 = acc[mt][nt][3] + g1.y;
                float w0 = __shfl_xor_sync(0xffffffffu, v0, 1);
                float w1 = __shfl_xor_sync(0xffffffffu, v1, 1);
                float w2 = __shfl_xor_sync(0xffffffffu, v2, 1);
                float w3 = __shfl_xor_sync(0xffffffffu, v3, 1);
                float I, F, G, O;
                int p;
                if (evenT) { I = v0; F = v1; G = w0; O = w1; p = prow; }
                else       { I = w2; F = w3; G = v2; O = v3; p = prow + 8; }
                float cold = creg[mt][nt];
                float cn = sigmoidf_(F) * cold + sigmoidf_(I) * tanhf(G);
                float h = sigmoidf_(O) * tanhf(cn);
                creg[mt][nt] = cn;
                size_t nn = (size_t)tcur * PP + p;
                __half hh, hl; splith(h, hh, hl);
                flatHi[nn * D2H + hcol + j] = hh;
                flatLo[nn * D2H + hcol + j] = hl;
            }
        }
        __syncthreads();
    }
}

// ---------------------------------------------------------------------------
// Finalize kernels
// ---------------------------------------------------------------------------
__global__ __launch_bounds__(256)
void pair_final_kernel(const unsigned* __restrict__ keys,
                       const float* __restrict__ hb,
                       const float* __restrict__ backoff,
                       const float* __restrict__ oW,
                       const float* __restrict__ ob,
                       float* __restrict__ pv, float* __restrict__ out) {
    const int b = blockIdx.x;
    const int k = b >> 14;
    const unsigned* src = keys + (size_t)b * D2H;
    float partial = 0.0f;
    #pragma unroll
    for (int it = 0; it < 2; ++it) {
        int c = threadIdx.x + it * 256;
        unsigned u = src[c];
        float val = u ? (funmap(u) + hb[k * D2H + c]) : backoff[k * D2H + c];
        float t = tanhf(val);
        pv[(size_t)b * D2H + c] = t;
        partial += t * oW[k * D2H + c];
    }
    float tot = blockReduceSum256(partial);
    if (threadIdx.x == 0) out[CC + b] = tot + ob[k];
}

__global__ __launch_bounds__(256)
void tri_final_kernel(const unsigned* __restrict__ keys,
                      const float* __restrict__ hb,
                      const float* __restrict__ backoff,
                      float* __restrict__ tv) {
    const int s = blockIdx.x;
    const unsigned* src = keys + (size_t)s * D2H;
    #pragma unroll
    for (int it = 0; it < 2; ++it) {
        int c = threadIdx.x + it * 256;
        unsigned u = src[c];
        float val = u ? (funmap(u) + hb[c]) : backoff[c];
        tv[(size_t)s * D2H + c] = tanhf(val);
    }
}

__global__ void gather_feats_kernel(const float* __restrict__ pv,
                                    const float* __restrict__ tv,
                                    const int* __restrict__ tpi,
                                    __half* __restrict__ fhi,
                                    __half* __restrict__ flo) {
    const int s = blockIdx.x;
    const int i0 = tpi[s * 3 + 0];
    const int i1 = tpi[s * 3 + 1];
    const int i2 = tpi[s * 3 + 2];
    for (int j = threadIdx.x; j < 2048; j += blockDim.x) {
        int q = j >> 9, c = j & 511;
        float v;
        if (q == 0)      v = pv[((size_t)2 * CC + i0) * D2H + c];
        else if (q == 1) v = pv[((size_t)1 * CC + i1) * D2H + c];
        else if (q == 2) v = pv[(size_t)i2 * D2H + c];
        else             v = tv[(size_t)s * D2H + c];
        __half h, l; splith(v, h, l);
        fhi[(size_t)s * 2048 + j] = h;
        flo[(size_t)s * 2048 + j] = l;
    }
}

__global__ __launch_bounds__(256)
void triple_logit_kernel(const float* __restrict__ fin,
                         const float* __restrict__ tW,
                         const float* __restrict__ tb,
                         float* __restrict__ out) {
    const int s = blockIdx.x;
    float partial = 0.0f;
    #pragma unroll
    for (int it = 0; it < 2; ++it) {
        int c = threadIdx.x + it * 256;
        float v = fin[(size_t)s * D2H + c];
        v = v > 0.0f ? v : 0.0f;
        partial += v * tW[c];
    }
    float tot = blockReduceSum256(partial);
    if (threadIdx.x == 0) out[s] = tot + tb[0];
}

// ---------------------------------------------------------------------------
// Launcher
// ---------------------------------------------------------------------------
extern "C" void kernel_launch(void* const* d_in, const int* in_sizes, int n_in,
                              void* d_out, int out_size) {
    const float* x        = (const float*)d_in[0];
    const float* wih_f    = (const float*)d_in[1];
    const float* whh_f    = (const float*)d_in[2];
    const float* b_f      = (const float*)d_in[3];
    const float* wih_b    = (const float*)d_in[4];
    const float* whh_b    = (const float*)d_in[5];
    const float* b_b      = (const float*)d_in[6];
    const float* pair_hW  = (const float*)d_in[7];
    const float* pair_hb  = (const float*)d_in[8];
    const float* pair_oW  = (const float*)d_in[9];
    const float* pair_ob  = (const float*)d_in[10];
    const float* pair_bo  = (const float*)d_in[11];
    const float* tri_hW   = (const float*)d_in[12];
    const float* tri_hb   = (const float*)d_in[13];
    const float* tri_bo   = (const float*)d_in[14];
    const float* all_hW   = (const float*)d_in[15];
    const float* all_hb   = (const float*)d_in[16];
    const float* out_tW   = (const float*)d_in[17];
    const float* out_tb   = (const float*)d_in[18];
    const int*   occ1     = (const int*)d_in[19];
    const int*   occ2     = (const int*)d_in[20];
    const int*   seg      = (const int*)d_in[21];
    const int*   tri_o1   = (const int*)d_in[22];
    const int*   tri_o2   = (const int*)d_in[23];
    const int*   tri_o3   = (const int*)d_in[24];
    const int*   tri_seg  = (const int*)d_in[25];
    const int*   tri_pi   = (const int*)d_in[26];
    float* out = (float*)d_out;

    float *GxF, *GxB, *pv, *tv, *fin, *pbF, *pbB;
    unsigned *pk, *tk;
    __half *xHi, *xLo, *wHiF, *wHiB, *flHi, *flLo;
    __half *whF, *wlF, *whB, *wlB;
    __half *pwHi, *twHi, *awHi, *ftHi, *ftLo;
    cudaGetSymbolAddress((void**)&GxF,  g_GxF);
    cudaGetSymbolAddress((void**)&GxB,  g_GxB);
    cudaGetSymbolAddress((void**)&pk,   g_pairKeys);
    cudaGetSymbolAddress((void**)&tk,   g_triKeys);
    cudaGetSymbolAddress((void**)&pv,   g_pv);
    cudaGetSymbolAddress((void**)&tv,   g_tv);
    cudaGetSymbolAddress((void**)&fin,  g_final);
    cudaGetSymbolAddress((void**)&pbF,  g_pbF);
    cudaGetSymbolAddress((void**)&pbB,  g_pbB);
    cudaGetSymbolAddress((void**)&xHi,  g_xHi);
    cudaGetSymbolAddress((void**)&xLo,  g_xLo);
    cudaGetSymbolAddress((void**)&wHiF, g_wHiF);
    cudaGetSymbolAddress((void**)&wHiB, g_wHiB);
    cudaGetSymbolAddress((void**)&whF,  g_whhHiF);
    cudaGetSymbolAddress((void**)&wlF,  g_whhLoF);
    cudaGetSymbolAddress((void**)&whB,  g_whhHiB);
    cudaGetSymbolAddress((void**)&wlB,  g_whhLoB);
    cudaGetSymbolAddress((void**)&flHi, g_flatHi);
    cudaGetSymbolAddress((void**)&flLo, g_flatLo);
    cudaGetSymbolAddress((void**)&pwHi, g_pwHi);
    cudaGetSymbolAddress((void**)&twHi, g_twHi);
    cudaGetSymbolAddress((void**)&awHi, g_aWHi);
    cudaGetSymbolAddress((void**)&ftHi, g_ftHi);
    cudaGetSymbolAddress((void**)&ftLo, g_ftLo);

    cudaFuncSetAttribute(gemm_fp16x2_kernel,
                         cudaFuncAttributeMaxDynamicSharedMemorySize, SMEM_GEMM);
    cudaFuncSetAttribute(gemm_gsc_kernel,
                         cudaFuncAttributeMaxDynamicSharedMemorySize, SMEM_GSC);
    cudaFuncSetAttribute(lstm_persist_kernel,
                         cudaFuncAttributeMaxDynamicSharedMemorySize, SMEM_LSTMP);

    // 1) split/pack operands (fp16)
    split_pad_kernel<<<4096, 256>>>(x, xHi, xLo, NPOS, EE, EP);
    pack_wih_kernel<<<512, 256>>>(wih_f, b_f, wHiF, pbF);
    pack_wih_kernel<<<512, 256>>>(wih_b, b_b, wHiB, pbB);
    pack_whh_kernel<<<512, 256>>>(whh_f, whF, wlF);
    pack_whh_kernel<<<512, 256>>>(whh_b, whB, wlB);
    pack_pairWT_kernel<<<3072, 256>>>(pair_hW, pwHi);
    pack_triWT_kernel<<<1536, 256>>>(tri_hW, twHi);
    pack_allWT_kernel<<<1024, 256>>>(all_hW, awHi);

    // 2) input projections (gate-permuted cols): Gx = (xHi+xLo) @ wihHi^T + pb
    gemm_fp16x2_kernel<<<dim3(8, 512), 256, SMEM_GEMM>>>(xHi, xLo, wHiF, pbF, GxF, EP);
    gemm_fp16x2_kernel<<<dim3(8, 512), 256, SMEM_GEMM>>>(xHi, xLo, wHiB, pbB, GxB, EP);

    // 3) zero segment-max keys
    zero_keys_kernel<<<32768, 256>>>(pk, tk);

    // 4) BiLSTM recurrence: persistent HMMA kernel (fp16 3-term)
    lstm_persist_kernel<<<dim3(8, 8, 2), 256, SMEM_LSTMP>>>(
        GxF, GxB, whF, wlF, whB, wlB, flHi, flLo);

    // 5) gather-GEMM-scatter: pair types + triples (fp16 1-term)
    for (int k = 0; k < 3; ++k)
        gemm_gsc_kernel<<<dim3(4, MTILES), 256, SMEM_GSC>>>(
            flHi, pwHi + (size_t)k * D2H * G4,
            occ1 + k * MM, occ2 + k * MM, occ1 + k * MM,
            seg + k * MM, pk + (size_t)k * CC * D2H, G4);
    gemm_gsc_kernel<<<dim3(4, MTILES), 256, SMEM_GSC>>>(
        flHi, twHi, tri_o1, tri_o2, tri_o3, tri_seg, tk, 1536);

    // 6) finalize pooled vectors (+ pair logits)
    pair_final_kernel<<<3 * CC, 256>>>(pk, pair_hb, pair_bo, pair_oW, pair_ob, pv, out);
    tri_final_kernel<<<CC, 256>>>(tk, tri_hb, tri_bo, tv);

    // 7) final MLP + triple logits (fp16 2-term)
    gather_feats_kernel<<<CC, 256>>>(pv, tv, tri_pi, ftHi, ftLo);
    gemm_fp16x2_kernel<<<dim3(D2H / 128, CC / 128), 256, SMEM_GEMM>>>(
        ftHi, ftLo, awHi, all_hb, fin, 2048);
    triple_logit_kernel<<<CC, 256>>>(fin, out_tW, out_tb, out);
}

// round 11
// speedup vs baseline: 2.6860x; 1.0999x over previous
#include <cuda_runtime.h>
#include <cuda_fp16.h>
#include <math.h>
#include <stdint.h>

// ---------------------------------------------------------------------------
// Problem constants
// ---------------------------------------------------------------------------
#define TT   256
#define PP   256
#define EE   300
#define HH   256
#define NPOS 65536            // T*P
#define G4   1024             // 4H
#define D2H  512              // 2H
#define MM   50000
#define CC   16384
#define EP   320              // E padded to multiple of 32
#define MTILES ((MM + 127) / 128)   // 391

// ---------------------------------------------------------------------------
// Device scratch (static allocations only)
// ---------------------------------------------------------------------------
__device__ float    g_GxF[(size_t)NPOS * G4];          // 268 MB (cols j*4+g)
__device__ float    g_GxB[(size_t)NPOS * G4];          // 268 MB
__device__ unsigned g_pairKeys[(size_t)3 * CC * D2H];  // 100 MB
__device__ unsigned g_triKeys[(size_t)CC * D2H];       // 33 MB
__device__ float    g_pv[(size_t)3 * CC * D2H];        // 100 MB
__device__ float    g_tv[(size_t)CC * D2H];            // 33 MB
__device__ float    g_final[(size_t)CC * D2H];         // 33 MB
__device__ float    g_pbF[G4];                         // permuted biases
__device__ float    g_pbB[G4];
__device__ unsigned g_barCnt[16];                      // per (dir,ptile) barrier
__device__ unsigned g_barGen[16];

// fp16 split operand buffers
__device__ __half g_xHi[(size_t)NPOS * EP];            // 42 MB
__device__ __half g_xLo[(size_t)NPOS * EP];
__device__ __half g_wHiF[(size_t)G4 * EP];             // packed rows j*4+g (hi only)
__device__ __half g_wHiB[(size_t)G4 * EP];
__device__ __half g_whhHiF[(size_t)G4 * HH];           // packed rows j*4+g
__device__ __half g_whhLoF[(size_t)G4 * HH];
__device__ __half g_whhHiB[(size_t)G4 * HH];
__device__ __half g_whhLoB[(size_t)G4 * HH];
__device__ __half g_flatHi[(size_t)NPOS * D2H];        // 67 MB
__device__ __half g_flatLo[(size_t)NPOS * D2H];        // used by LSTM only
__device__ __half g_pwHi[(size_t)3 * D2H * G4];        // pairWT [3][512][1024]
__device__ __half g_twHi[(size_t)D2H * 1536];          // triWT [512][1536]
__device__ __half g_aWHi[(size_t)D2H * 2048];
__device__ __half g_ftHi[(size_t)CC * 2048];           // 67 MB
__device__ __half g_ftLo[(size_t)CC * 2048];

// ---------------------------------------------------------------------------
// Helpers
// ---------------------------------------------------------------------------
__device__ __forceinline__ uint32_t smem_u32(const void* p) {
    uint32_t a;
    asm("{ .reg .u64 t; cvta.to.shared.u64 t, %1; cvt.u32.u64 %0, t; }"
        : "=r"(a) : "l"(p));
    return a;
}

#define LDSM_X4(r, addr) \
    asm volatile("ldmatrix.sync.aligned.m8n8.x4.shared.b16 {%0,%1,%2,%3}, [%4];" \
        : "=r"((r)[0]), "=r"((r)[1]), "=r"((r)[2]), "=r"((r)[3]) : "r"(addr))

#define MMA_FP16(d, a, b) \
    asm volatile("mma.sync.aligned.m16n8k16.row.col.f32.f16.f16.f32 " \
        "{%0,%1,%2,%3}, {%4,%5,%6,%7}, {%8,%9}, {%0,%1,%2,%3};" \
        : "+f"((d)[0]), "+f"((d)[1]), "+f"((d)[2]), "+f"((d)[3]) \
        : "r"((a)[0]), "r"((a)[1]), "r"((a)[2]), "r"((a)[3]), \
          "r"((b)[0]), "r"((b)[1]))

#define CP_ASYNC16(dst, src) \
    asm volatile("cp.async.cg.shared.global [%0], [%1], 16;" \
                 :: "r"(dst), "l"(src))
#define CP_COMMIT() asm volatile("cp.async.commit_group;" ::: "memory")
#define CP_WAIT(n)  asm volatile("cp.async.wait_group %0;" :: "n"(n) : "memory")

__device__ __forceinline__ float sigmoidf_(float x) { return 1.0f / (1.0f + expf(-x)); }

__device__ __forceinline__ unsigned fmap(float f) {
    unsigned b = __float_as_uint(f);
    return (b & 0x80000000u) ? ~b : (b | 0x80000000u);
}
__device__ __forceinline__ float funmap(unsigned u) {
    return (u & 0x80000000u) ? __uint_as_float(u & 0x7FFFFFFFu)
                             : __uint_as_float(~u);
}
__device__ __forceinline__ float warpReduceSum(float v) {
    #pragma unroll
    for (int o = 16; o > 0; o >>= 1) v += __shfl_down_sync(0xffffffffu, v, o);
    return v;
}
__device__ __forceinline__ float blockReduceSum256(float v) {
    __shared__ float sh[8];
    int lane = threadIdx.x & 31, wid = threadIdx.x >> 5;
    v = warpReduceSum(v);
    if (lane == 0) sh[wid] = v;
    __syncthreads();
    v = (threadIdx.x < 8) ? sh[threadIdx.x] : 0.0f;
    if (wid == 0) v = warpReduceSum(v);
    return v;
}
__device__ __forceinline__ void splith(float f, __half& h, __half& l) {
    h = __float2half(f);
    l = __float2half(f - __half2float(h));
}

// per-(dir,ptile) group barrier: only the 8 CTAs sharing (dir, ptile) must
// sync (they produce exactly the h-rows this group's A tiles consume).
__device__ __forceinline__ void group_barrier(int bidx, int tid, unsigned nCTA) {
    __syncthreads();
    if (tid == 0) {
        __threadfence();
        unsigned gen = atomicAdd(&g_barGen[bidx], 0u);
        unsigned prev = atomicAdd(&g_barCnt[bidx], 1u);
        if (prev == nCTA - 1u) {
            atomicExch(&g_barCnt[bidx], 0u);
            __threadfence();
            atomicAdd(&g_barGen[bidx], 1u);
        } else {
            while (atomicAdd(&g_barGen[bidx], 0u) == gen) { __nanosleep(32); }
        }
        __threadfence();
    }
    __syncthreads();
}

// ---------------------------------------------------------------------------
// fp16 2-term split GEMM: C[M,N] = (Ahi+Alo)[M,K] @ Bhi[N,K]^T + bias
// CTA tile 128x128, 256 threads (8 warps: 2 M x 4 N; warp tile 64x32).
// ---------------------------------------------------------------------------
#define RSZ   80
#define TILEB (128 * RSZ)       // 10240
#define STAGE3 (3 * TILEB)      // 30720 (Ahi, Alo, Bhi)
#define SMEM_GEMM (2 * STAGE3)  // 61440

__global__ __launch_bounds__(256, 2)
void gemm_fp16x2_kernel(const __half* __restrict__ Ahi,
                        const __half* __restrict__ Alo,
                        const __half* __restrict__ Bhi,
                        const float* __restrict__ bias,
                        float* __restrict__ C, int K) {
    extern __shared__ char smem[];
    const uint32_t sb = smem_u32(smem);
    const int tid = threadIdx.x, lane = tid & 31, wid = tid >> 5;
    const int m0 = blockIdx.y * 128, n0 = blockIdx.x * 128;
    const int ldc = gridDim.x * 128;
    const int wm = wid & 1, wn = wid >> 1;

    float acc[4][4][4];
    #pragma unroll
    for (int i = 0; i < 4; ++i)
        #pragma unroll
        for (int j = 0; j < 4; ++j)
            #pragma unroll
            for (int q = 0; q < 4; ++q) acc[i][j][q] = 0.0f;

    const int nch = K >> 5;
    const int r0c = (2 * tid) >> 2, ch0 = (2 * tid) & 3;
    const int r1c = (2 * tid + 1) >> 2, ch1 = (2 * tid + 1) & 3;
    const int rA = lane & 15;
    const int cA = lane >> 4;

    #define LOAD_STAGE(cc)                                                      \
    do {                                                                        \
        const int kb = (cc) << 5;                                               \
        const uint32_t dst = sb + ((cc) & 1) * STAGE3;                          \
        CP_ASYNC16(dst + 0 * TILEB + r0c * RSZ + ch0 * 16,                      \
                   Ahi + (size_t)(m0 + r0c) * K + kb + ch0 * 8);                \
        CP_ASYNC16(dst + 0 * TILEB + r1c * RSZ + ch1 * 16,                      \
                   Ahi + (size_t)(m0 + r1c) * K + kb + ch1 * 8);                \
        CP_ASYNC16(dst + 1 * TILEB + r0c * RSZ + ch0 * 16,                      \
                   Alo + (size_t)(m0 + r0c) * K + kb + ch0 * 8);                \
        CP_ASYNC16(dst + 1 * TILEB + r1c * RSZ + ch1 * 16,                      \
                   Alo + (size_t)(m0 + r1c) * K + kb + ch1 * 8);                \
        CP_ASYNC16(dst + 2 * TILEB + r0c * RSZ + ch0 * 16,                      \
                   Bhi + (size_t)(n0 + r0c) * K + kb + ch0 * 8);                \
        CP_ASYNC16(dst + 2 * TILEB + r1c * RSZ + ch1 * 16,                      \
                   Bhi + (size_t)(n0 + r1c) * K + kb + ch1 * 8);                \
        CP_COMMIT();                                                            \
    } while (0)

    LOAD_STAGE(0);

    for (int c = 0; c < nch; ++c) {
        if (c + 1 < nch) { LOAD_STAGE(c + 1); CP_WAIT(1); }
        else             { CP_WAIT(0); }
        __syncthreads();

        const uint32_t s = sb + (c & 1) * STAGE3;
        const uint32_t aHiB = s, aLoB = s + TILEB, bHiB = s + 2 * TILEB;

        #pragma unroll
        for (int ks = 0; ks < 2; ++ks) {
            const uint32_t colOff = (uint32_t)(ks * 2 + cA) * 16;
            uint32_t aHi[4][4], bHi[4][2];
            #pragma unroll
            for (int mt = 0; mt < 4; ++mt) {
                uint32_t ad = (uint32_t)(wm * 64 + mt * 16 + rA) * RSZ + colOff;
                LDSM_X4(aHi[mt], aHiB + ad);
            }
            #pragma unroll
            for (int nh = 0; nh < 2; ++nh) {
                uint32_t bd = (uint32_t)(wn * 32 + nh * 16 + rA) * RSZ + colOff;
                uint32_t t[4];
                LDSM_X4(t, bHiB + bd);
                bHi[nh * 2 + 0][0] = t[0]; bHi[nh * 2 + 0][1] = t[2];
                bHi[nh * 2 + 1][0] = t[1]; bHi[nh * 2 + 1][1] = t[3];
            }
            #pragma unroll
            for (int mt = 0; mt < 4; ++mt)
                #pragma unroll
                for (int nt = 0; nt < 4; ++nt)
                    MMA_FP16(acc[mt][nt], aHi[mt], bHi[nt]);
            {
                uint32_t aLo[4][4];
                #pragma unroll
                for (int mt = 0; mt < 4; ++mt) {
                    uint32_t ad = (uint32_t)(wm * 64 + mt * 16 + rA) * RSZ + colOff;
                    LDSM_X4(aLo[mt], aLoB + ad);
                }
                #pragma unroll
                for (int mt = 0; mt < 4; ++mt)
                    #pragma unroll
                    for (int nt = 0; nt < 4; ++nt)
                        MMA_FP16(acc[mt][nt], aLo[mt], bHi[nt]);
            }
        }
        __syncthreads();
    }

    const int rr = lane >> 2, cc2 = (lane & 3) * 2;
    #pragma unroll
    for (int mt = 0; mt < 4; ++mt) {
        #pragma unroll
        for (int nt = 0; nt < 4; ++nt) {
            int row = m0 + wm * 64 + mt * 16 + rr;
            int col = n0 + wn * 32 + nt * 8 + cc2;
            float b0 = 0.f, b1 = 0.f;
            if (bias) { b0 = bias[col]; b1 = bias[col + 1]; }
            float2 v0 = make_float2(acc[mt][nt][0] + b0, acc[mt][nt][1] + b1);
            float2 v1 = make_float2(acc[mt][nt][2] + b0, acc[mt][nt][3] + b1);
            *(float2*)&C[(size_t)row * ldc + col] = v0;
            *(float2*)&C[(size_t)(row + 8) * ldc + col] = v1;
        }
    }
    #undef LOAD_STAGE
}

// ---------------------------------------------------------------------------
// Gather-GEMM-scatter (fp16 1-term): rep[m] = concat(flatHi[occ..]) @ Bhi^T,
// then atomicMax into keys[seg[m]] (fmap-encoded). A & B hi-only.
// ---------------------------------------------------------------------------
#define STAGE2 (2 * TILEB)      // 20480 (Ahi, Bhi)
#define SMEM_GSC (2 * STAGE2)   // 40960

__global__ __launch_bounds__(256, 2)
void gemm_gsc_kernel(const __half* __restrict__ flatHi,
                     const __half* __restrict__ Bhi,
                     const int* __restrict__ occ1,
                     const int* __restrict__ occ2,
                     const int* __restrict__ occ3,
                     const int* __restrict__ seg,
                     unsigned* __restrict__ keys, int K) {
    extern __shared__ char smem[];
    const uint32_t sb = smem_u32(smem);
    const int tid = threadIdx.x, lane = tid & 31, wid = tid >> 5;
    const int m0 = blockIdx.y * 128, n0 = blockIdx.x * 128;
    const int wm = wid & 1, wn = wid >> 1;

    float acc[4][4][4];
    #pragma unroll
    for (int i = 0; i < 4; ++i)
        #pragma unroll
        for (int j = 0; j < 4; ++j)
            #pragma unroll
            for (int q = 0; q < 4; ++q) acc[i][j][q] = 0.0f;

    const int nch = K >> 5;
    const int r0c = (2 * tid) >> 2, ch0 = (2 * tid) & 3;
    const int r1c = (2 * tid + 1) >> 2, ch1 = (2 * tid + 1) & 3;
    const int rA = lane & 15;
    const int cA = lane >> 4;

    const int mC0 = (m0 + r0c < MM) ? (m0 + r0c) : (MM - 1);
    const int mC1 = (m0 + r1c < MM) ? (m0 + r1c) : (MM - 1);
    int ia0[3], ia1[3];
    ia0[0] = occ1[mC0]; ia1[0] = occ1[mC1];
    ia0[1] = occ2[mC0]; ia1[1] = occ2[mC1];
    ia0[2] = (K > 1024) ? occ3[mC0] : 0;
    ia1[2] = (K > 1024) ? occ3[mC1] : 0;

    #define LOAD_STAGE_G(cc)                                                    \
    do {                                                                        \
        const int kb = (cc) << 5;                                               \
        const int sg_ = kb >> 9;                                                \
        const int ck = kb & 511;                                                \
        const uint32_t dst = sb + ((cc) & 1) * STAGE2;                          \
        CP_ASYNC16(dst + 0 * TILEB + r0c * RSZ + ch0 * 16,                      \
                   flatHi + (size_t)ia0[sg_] * D2H + ck + ch0 * 8);             \
        CP_ASYNC16(dst + 0 * TILEB + r1c * RSZ + ch1 * 16,                      \
                   flatHi + (size_t)ia1[sg_] * D2H + ck + ch1 * 8);             \
        CP_ASYNC16(dst + 1 * TILEB + r0c * RSZ + ch0 * 16,                      \
                   Bhi + (size_t)(n0 + r0c) * K + kb + ch0 * 8);                \
        CP_ASYNC16(dst + 1 * TILEB + r1c * RSZ + ch1 * 16,                      \
                   Bhi + (size_t)(n0 + r1c) * K + kb + ch1 * 8);                \
        CP_COMMIT();                                                            \
    } while (0)

    LOAD_STAGE_G(0);

    for (int c = 0; c < nch; ++c) {
        if (c + 1 < nch) { LOAD_STAGE_G(c + 1); CP_WAIT(1); }
        else             { CP_WAIT(0); }
        __syncthreads();

        const uint32_t s = sb + (c & 1) * STAGE2;
        const uint32_t aHiB = s, bHiB = s + TILEB;

        #pragma unroll
        for (int ks = 0; ks < 2; ++ks) {
            const uint32_t colOff = (uint32_t)(ks * 2 + cA) * 16;
            uint32_t aHi[4][4], bHi[4][2];
            #pragma unroll
            for (int mt = 0; mt < 4; ++mt) {
                uint32_t ad = (uint32_t)(wm * 64 + mt * 16 + rA) * RSZ + colOff;
                LDSM_X4(aHi[mt], aHiB + ad);
            }
            #pragma unroll
            for (int nh = 0; nh < 2; ++nh) {
                uint32_t bd = (uint32_t)(wn * 32 + nh * 16 + rA) * RSZ + colOff;
                uint32_t t[4];
                LDSM_X4(t, bHiB + bd);
                bHi[nh * 2 + 0][0] = t[0]; bHi[nh * 2 + 0][1] = t[2];
                bHi[nh * 2 + 1][0] = t[1]; bHi[nh * 2 + 1][1] = t[3];
            }
            #pragma unroll
            for (int mt = 0; mt < 4; ++mt)
                #pragma unroll
                for (int nt = 0; nt < 4; ++nt)
                    MMA_FP16(acc[mt][nt], aHi[mt], bHi[nt]);
        }
        __syncthreads();
    }

    // ---- epilogue: fmap + atomicMax scatter into segment keys ----
    const int rr = lane >> 2, cc2 = (lane & 3) * 2;
    #pragma unroll
    for (int mt = 0; mt < 4; ++mt) {
        int rowL = wm * 64 + mt * 16 + rr;
        int mA = m0 + rowL, mB = mA + 8;
        int sgA = (mA < MM) ? seg[mA] : -1;
        int sgB = (mB < MM) ? seg[mB] : -1;
        #pragma unroll
        for (int nt = 0; nt < 4; ++nt) {
            int col = n0 + wn * 32 + nt * 8 + cc2;
            if (sgA >= 0) {
                unsigned* d = keys + (size_t)sgA * D2H + col;
                atomicMax(d,     fmap(acc[mt][nt][0]));
                atomicMax(d + 1, fmap(acc[mt][nt][1]));
            }
            if (sgB >= 0) {
                unsigned* d = keys + (size_t)sgB * D2H + col;
                atomicMax(d,     fmap(acc[mt][nt][2]));
                atomicMax(d + 1, fmap(acc[mt][nt][3]));
            }
        }
    }
    #undef LOAD_STAGE_G
}

// ---------------------------------------------------------------------------
// Pack kernels
// ---------------------------------------------------------------------------
__global__ void split_pad_kernel(const float* __restrict__ src,
                                 __half* __restrict__ hi,
                                 __half* __restrict__ lo,
                                 int rows, int sk, int dk) {
    size_t total = (size_t)rows * dk;
    for (size_t idx = blockIdx.x * (size_t)blockDim.x + threadIdx.x; idx < total;
         idx += (size_t)gridDim.x * blockDim.x) {
        int r = (int)(idx / dk), c = (int)(idx % dk);
        float f = (c < sk) ? src[(size_t)r * sk + c] : 0.0f;
        __half h, l; splith(f, h, l);
        hi[idx] = h; lo[idx] = l;
    }
}

__global__ void pack_wih_kernel(const float* __restrict__ wih,
                                const float* __restrict__ b,
                                __half* __restrict__ hi,
                                float* __restrict__ pb) {
    const int total = G4 * EP;
    for (int idx = blockIdx.x * blockDim.x + threadIdx.x; idx < total;
         idx += gridDim.x * blockDim.x) {
        int rp = idx / EP, k = idx % EP;
        int j = rp >> 2, g = rp & 3;
        float f = (k < EE) ? wih[(size_t)(g * 256 + j) * EE + k] : 0.0f;
        hi[idx] = __float2half(f);
        if (k == 0) pb[rp] = b[g * 256 + j];
    }
}

__global__ void pack_whh_kernel(const float* __restrict__ whh,
                                __half* __restrict__ hi,
                                __half* __restrict__ lo) {
    const int total = G4 * HH;
    for (int idx = blockIdx.x * blockDim.x + threadIdx.x; idx < total;
         idx += gridDim.x * blockDim.x) {
        int rp = idx >> 8, k = idx & 255;
        int j = rp >> 2, g = rp & 3;
        float v = whh[(size_t)(g * 256 + j) * HH + k];
        __half h, l; splith(v, h, l);
        hi[idx] = h; lo[idx] = l;
    }
}

__global__ void pack_pairWT_kernel(const float* __restrict__ pair_hW,
                                   __half* __restrict__ hi) {
    const int total = 3 * D2H * G4;
    for (int idx = blockIdx.x * blockDim.x + threadIdx.x; idx < total;
         idx += gridDim.x * blockDim.x) {
        int k = idx / (D2H * G4);
        int rem = idx - k * (D2H * G4);
        int n = rem >> 10, kk = rem & 1023;
        hi[idx] = __float2half(pair_hW[(size_t)k * (G4 * D2H) + (size_t)kk * D2H + n]);
    }
}

__global__ void pack_triWT_kernel(const float* __restrict__ tri_hW,
                                  __half* __restrict__ hi) {
    const int total = D2H * 1536;
    for (int idx = blockIdx.x * blockDim.x + threadIdx.x; idx < total;
         idx += gridDim.x * blockDim.x) {
        int n = idx / 1536, kk = idx % 1536;
        hi[idx] = __float2half(tri_hW[(size_t)kk * D2H + n]);
    }
}

__global__ void pack_allWT_kernel(const float* __restrict__ all_hW,
                                  __half* __restrict__ hi) {
    const int total = D2H * 2048;
    for (int idx = blockIdx.x * blockDim.x + threadIdx.x; idx < total;
         idx += gridDim.x * blockDim.x) {
        int n = idx >> 11, k = idx & 2047;
        hi[idx] = __float2half(all_hW[(size_t)k * D2H + n]);
    }
}

__global__ void zero_keys_kernel(unsigned* __restrict__ pk, unsigned* __restrict__ tk) {
    const size_t np = (size_t)3 * CC * D2H;
    const size_t nt = (size_t)CC * D2H;
    for (size_t i = blockIdx.x * (size_t)blockDim.x + threadIdx.x; i < np + nt;
         i += (size_t)gridDim.x * blockDim.x) {
        if (i < np) pk[i] = 0u; else tk[i - np] = 0u;
    }
}

// ---------------------------------------------------------------------------
// Persistent HMMA BiLSTM recurrence (fp16 3-term; 8-CTA group barriers,
// Gx prefetched at step start).
// ---------------------------------------------------------------------------
#define PRSZ   528
#define LP_AHI 0
#define LP_ALO 16896
#define LP_BHI 33792
#define LP_BLO 101376
#define SMEM_LSTMP 168960

__global__ __launch_bounds__(256, 1)
void lstm_persist_kernel(const float* __restrict__ GxF,
                         const float* __restrict__ GxB,
                         const __half* __restrict__ whhHiF,
                         const __half* __restrict__ whhLoF,
                         const __half* __restrict__ whhHiB,
                         const __half* __restrict__ whhLoB,
                         __half* __restrict__ flatHi,
                         __half* __restrict__ flatLo) {
    extern __shared__ char smem[];
    const uint32_t sb = smem_u32(smem);
    const int tid = threadIdx.x, lane = tid & 31, wid = tid >> 5;
    const int dir = blockIdx.z;
    const int p0 = blockIdx.x * 32;
    const int c0 = blockIdx.y * 128;
    const int hcol = dir * HH;
    const int bidx = dir * 8 + blockIdx.x;   // barrier group (dir, ptile)
    const float* Gx = dir ? GxB : GxF;
    const __half* Whi = dir ? whhHiB : whhHiF;
    const __half* Wlo = dir ? whhLoB : whhLoF;

    for (int ch = tid; ch < 128 * 32; ch += 256) {
        int row = ch >> 5, cb = ch & 31;
        size_t src = (size_t)(c0 + row) * HH + cb * 8;
        CP_ASYNC16(sb + LP_BHI + row * PRSZ + cb * 16, Whi + src);
        CP_ASYNC16(sb + LP_BLO + row * PRSZ + cb * 16, Wlo + src);
    }
    CP_COMMIT(); CP_WAIT(0);
    __syncthreads();

    float creg[2][2] = {{0.f, 0.f}, {0.f, 0.f}};
    const int rr = lane >> 2, cc2 = (lane & 3) * 2;
    const bool evenT = ((lane & 1) == 0);

    for (int s = 0; s < TT; ++s) {
        const int tcur = dir ? (TT - 1 - s) : s;

        // ---- prefetch Gx for this step (independent of h; hides DRAM lat)
        float2 gpre[2][2][2];
        #pragma unroll
        for (int mt = 0; mt < 2; ++mt) {
            #pragma unroll
            for (int nt = 0; nt < 2; ++nt) {
                int prow = p0 + mt * 16 + rr;
                int col = c0 + wid * 16 + nt * 8 + cc2;
                size_t n0i = (size_t)tcur * PP + prow;
                gpre[mt][nt][0] = *(const float2*)&Gx[n0i * G4 + col];
                gpre[mt][nt][1] = *(const float2*)&Gx[(n0i + 8) * G4 + col];
            }
        }

        float acc[2][2][4];
        #pragma unroll
        for (int i = 0; i < 2; ++i)
            #pragma unroll
            for (int j = 0; j < 2; ++j)
                #pragma unroll
                for (int q = 0; q < 4; ++q) acc[i][j][q] = 0.0f;

        if (s > 0) {
            group_barrier(bidx, tid, 8u);

            const int nprev = dir ? (tcur + 1) : (tcur - 1);
            for (int ch = tid; ch < 32 * 32; ch += 256) {
                int row = ch >> 5, cb = ch & 31;
                size_t src = (size_t)(nprev * PP + p0 + row) * D2H + hcol + cb * 8;
                CP_ASYNC16(sb + LP_AHI + row * PRSZ + cb * 16, flatHi + src);
                CP_ASYNC16(sb + LP_ALO + row * PRSZ + cb * 16, flatLo + src);
            }
            CP_COMMIT(); CP_WAIT(0);
            __syncthreads();

            #pragma unroll 4
            for (int kc = 0; kc < 16; ++kc) {
                const uint32_t colOff = (uint32_t)kc * 32 + (uint32_t)(lane >> 4) * 16;
                uint32_t aHi[2][4], bHi[2][2];
                #pragma unroll
                for (int mt = 0; mt < 2; ++mt) {
                    uint32_t ad = (uint32_t)(mt * 16 + (lane & 15)) * PRSZ + colOff;
                    LDSM_X4(aHi[mt], sb + LP_AHI + ad);
                }
                {
                    uint32_t bd = (uint32_t)(wid * 16 + (lane & 15)) * PRSZ + colOff;
                    uint32_t t[4];
                    LDSM_X4(t, sb + LP_BHI + bd);
                    bHi[0][0] = t[0]; bHi[0][1] = t[2];
                    bHi[1][0] = t[1]; bHi[1][1] = t[3];
                }
                #pragma unroll
                for (int mt = 0; mt < 2; ++mt)
                    #pragma unroll
                    for (int nt = 0; nt < 2; ++nt)
                        MMA_FP16(acc[mt][nt], aHi[mt], bHi[nt]);
                {
                    uint32_t aLo[2][4];
                    #pragma unroll
                    for (int mt = 0; mt < 2; ++mt) {
                        uint32_t ad = (uint32_t)(mt * 16 + (lane & 15)) * PRSZ + colOff;
                        LDSM_X4(aLo[mt], sb + LP_ALO + ad);
                    }
                    #pragma unroll
                    for (int mt = 0; mt < 2; ++mt)
                        #pragma unroll
                        for (int nt = 0; nt < 2; ++nt)
                            MMA_FP16(acc[mt][nt], aLo[mt], bHi[nt]);
                }
                {
                    uint32_t bLo[2][2];
                    uint32_t bd = (uint32_t)(wid * 16 + (lane & 15)) * PRSZ + colOff;
                    uint32_t t[4];
                    LDSM_X4(t, sb + LP_BLO + bd);
                    bLo[0][0] = t[0]; bLo[0][1] = t[2];
                    bLo[1][0] = t[1]; bLo[1][1] = t[3];
                    #pragma unroll
                    for (int mt = 0; mt < 2; ++mt)
                        #pragma unroll
                        for (int nt = 0; nt < 2; ++nt)
                            MMA_FP16(acc[mt][nt], aHi[mt], bLo[nt]);
                }
            }
        }

        #pragma unroll
        for (int mt = 0; mt < 2; ++mt) {
            #pragma unroll
            for (int nt = 0; nt < 2; ++nt) {
                int prow = p0 + mt * 16 + rr;
                int col = c0 + wid * 16 + nt * 8 + cc2;
                int j = col >> 2;
                float2 g0 = gpre[mt][nt][0];
                float2 g1 = gpre[mt][nt][1];
                float v0 = acc[mt][nt][0] + g0.x;
                float v1 = acc[mt][nt][1] + g0.y;
                float v2 = acc[mt][nt][2] + g1.x;
                float v3 = acc[mt][nt][3] + g1.y;
                float w0 = __shfl_xor_sync(0xffffffffu, v0, 1);
                float w1 = __shfl_xor_sync(0xffffffffu, v1, 1);
                float w2 = __shfl_xor_sync(0xffffffffu, v2, 1);
                float w3 = __shfl_xor_sync(0xffffffffu, v3, 1);
                float I, F, G, O;
                int p;
                if (evenT) { I = v0; F = v1; G = w0; O = w1; p = prow; }
                else       { I = w2; F = w3; G = v2; O = v3; p = prow + 8; }
                float cold = creg[mt][nt];
                float cn = sigmoidf_(F) * cold + sigmoidf_(I) * tanhf(G);
                float h = sigmoidf_(O) * tanhf(cn);
                creg[mt][nt] = cn;
                size_t nn = (size_t)tcur * PP + p;
                __half hh, hl; splith(h, hh, hl);
                flatHi[nn * D2H + hcol + j] = hh;
                flatLo[nn * D2H + hcol + j] = hl;
            }
        }
        __syncthreads();
    }
}

// ---------------------------------------------------------------------------
// Finalize kernels
// ---------------------------------------------------------------------------
__global__ __launch_bounds__(256)
void pair_final_kernel(const unsigned* __restrict__ keys,
                       const float* __restrict__ hb,
                       const float* __restrict__ backoff,
                       const float* __restrict__ oW,
                       const float* __restrict__ ob,
                       float* __restrict__ pv, float* __restrict__ out) {
    const int b = blockIdx.x;
    const int k = b >> 14;
    const unsigned* src = keys + (size_t)b * D2H;
    float partial = 0.0f;
    #pragma unroll
    for (int it = 0; it < 2; ++it) {
        int c = threadIdx.x + it * 256;
        unsigned u = src[c];
        float val = u ? (funmap(u) + hb[k * D2H + c]) : backoff[k * D2H + c];
        float t = tanhf(val);
        pv[(size_t)b * D2H + c] = t;
        partial += t * oW[k * D2H + c];
    }
    float tot = blockReduceSum256(partial);
    if (threadIdx.x == 0) out[CC + b] = tot + ob[k];
}

__global__ __launch_bounds__(256)
void tri_final_kernel(const unsigned* __restrict__ keys,
                      const float* __restrict__ hb,
                      const float* __restrict__ backoff,
                      float* __restrict__ tv) {
    const int s = blockIdx.x;
    const unsigned* src = keys + (size_t)s * D2H;
    #pragma unroll
    for (int it = 0; it < 2; ++it) {
        int c = threadIdx.x + it * 256;
        unsigned u = src[c];
        float val = u ? (funmap(u) + hb[c]) : backoff[c];
        tv[(size_t)s * D2H + c] = tanhf(val);
    }
}

__global__ void gather_feats_kernel(const float* __restrict__ pv,
                                    const float* __restrict__ tv,
                                    const int* __restrict__ tpi,
                                    __half* __restrict__ fhi,
                                    __half* __restrict__ flo) {
    const int s = blockIdx.x;
    const int i0 = tpi[s * 3 + 0];
    const int i1 = tpi[s * 3 + 1];
    const int i2 = tpi[s * 3 + 2];
    for (int j = threadIdx.x; j < 2048; j += blockDim.x) {
        int q = j >> 9, c = j & 511;
        float v;
        if (q == 0)      v = pv[((size_t)2 * CC + i0) * D2H + c];
        else if (q == 1) v = pv[((size_t)1 * CC + i1) * D2H + c];
        else if (q == 2) v = pv[(size_t)i2 * D2H + c];
        else             v = tv[(size_t)s * D2H + c];
        __half h, l; splith(v, h, l);
        fhi[(size_t)s * 2048 + j] = h;
        flo[(size_t)s * 2048 + j] = l;
    }
}

__global__ __launch_bounds__(256)
void triple_logit_kernel(const float* __restrict__ fin,
                         const float* __restrict__ tW,
                         const float* __restrict__ tb,
                         float* __restrict__ out) {
    const int s = blockIdx.x;
    float partial = 0.0f;
    #pragma unroll
    for (int it = 0; it < 2; ++it) {
        int c = threadIdx.x + it * 256;
        float v = fin[(size_t)s * D2H + c];
        v = v > 0.0f ? v : 0.0f;
        partial += v * tW[c];
    }
    float tot = blockReduceSum256(partial);
    if (threadIdx.x == 0) out[s] = tot + tb[0];
}

// ---------------------------------------------------------------------------
// Launcher
// ---------------------------------------------------------------------------
extern "C" void kernel_launch(void* const* d_in, const int* in_sizes, int n_in,
                              void* d_out, int out_size) {
    const float* x        = (const float*)d_in[0];
    const float* wih_f    = (const float*)d_in[1];
    const float* whh_f    = (const float*)d_in[2];
    const float* b_f      = (const float*)d_in[3];
    const float* wih_b    = (const float*)d_in[4];
    const float* whh_b    = (const float*)d_in[5];
    const float* b_b      = (const float*)d_in[6];
    const float* pair_hW  = (const float*)d_in[7];
    const float* pair_hb  = (const float*)d_in[8];
    const float* pair_oW  = (const float*)d_in[9];
    const float* pair_ob  = (const float*)d_in[10];
    const float* pair_bo  = (const float*)d_in[11];
    const float* tri_hW   = (const float*)d_in[12];
    const float* tri_hb   = (const float*)d_in[13];
    const float* tri_bo   = (const float*)d_in[14];
    const float* all_hW   = (const float*)d_in[15];
    const float* all_hb   = (const float*)d_in[16];
    const float* out_tW   = (const float*)d_in[17];
    const float* out_tb   = (const float*)d_in[18];
    const int*   occ1     = (const int*)d_in[19];
    const int*   occ2     = (const int*)d_in[20];
    const int*   seg      = (const int*)d_in[21];
    const int*   tri_o1   = (const int*)d_in[22];
    const int*   tri_o2   = (const int*)d_in[23];
    const int*   tri_o3   = (const int*)d_in[24];
    const int*   tri_seg  = (const int*)d_in[25];
    const int*   tri_pi   = (const int*)d_in[26];
    float* out = (float*)d_out;

    float *GxF, *GxB, *pv, *tv, *fin, *pbF, *pbB;
    unsigned *pk, *tk;
    __half *xHi, *xLo, *wHiF, *wHiB, *flHi, *flLo;
    __half *whF, *wlF, *whB, *wlB;
    __half *pwHi, *twHi, *awHi, *ftHi, *ftLo;
    cudaGetSymbolAddress((void**)&GxF,  g_GxF);
    cudaGetSymbolAddress((void**)&GxB,  g_GxB);
    cudaGetSymbolAddress((void**)&pk,   g_pairKeys);
    cudaGetSymbolAddress((void**)&tk,   g_triKeys);
    cudaGetSymbolAddress((void**)&pv,   g_pv);
    cudaGetSymbolAddress((void**)&tv,   g_tv);
    cudaGetSymbolAddress((void**)&fin,  g_final);
    cudaGetSymbolAddress((void**)&pbF,  g_pbF);
    cudaGetSymbolAddress((void**)&pbB,  g_pbB);
    cudaGetSymbolAddress((void**)&xHi,  g_xHi);
    cudaGetSymbolAddress((void**)&xLo,  g_xLo);
    cudaGetSymbolAddress((void**)&wHiF, g_wHiF);
    cudaGetSymbolAddress((void**)&wHiB, g_wHiB);
    cudaGetSymbolAddress((void**)&whF,  g_whhHiF);
    cudaGetSymbolAddress((void**)&wlF,  g_whhLoF);
    cudaGetSymbolAddress((void**)&whB,  g_whhHiB);
    cudaGetSymbolAddress((void**)&wlB,  g_whhLoB);
    cudaGetSymbolAddress((void**)&flHi, g_flatHi);
    cudaGetSymbolAddress((void**)&flLo, g_flatLo);
    cudaGetSymbolAddress((void**)&pwHi, g_pwHi);
    cudaGetSymbolAddress((void**)&twHi, g_twHi);
    cudaGetSymbolAddress((void**)&awHi, g_aWHi);
    cudaGetSymbolAddress((void**)&ftHi, g_ftHi);
    cudaGetSymbolAddress((void**)&ftLo, g_ftLo);

    cudaFuncSetAttribute(gemm_fp16x2_kernel,
                         cudaFuncAttributeMaxDynamicSharedMemorySize, SMEM_GEMM);
    cudaFuncSetAttribute(gemm_gsc_kernel,
                         cudaFuncAttributeMaxDynamicSharedMemorySize, SMEM_GSC);
    cudaFuncSetAttribute(lstm_persist_kernel,
                         cudaFuncAttributeMaxDynamicSharedMemorySize, SMEM_LSTMP);

    // 1) split/pack operands (fp16)
    split_pad_kernel<<<4096, 256>>>(x, xHi, xLo, NPOS, EE, EP);
    pack_wih_kernel<<<512, 256>>>(wih_f, b_f, wHiF, pbF);
    pack_wih_kernel<<<512, 256>>>(wih_b, b_b, wHiB, pbB);
    pack_whh_kernel<<<512, 256>>>(whh_f, whF, wlF);
    pack_whh_kernel<<<512, 256>>>(whh_b, whB, wlB);
    pack_pairWT_kernel<<<3072, 256>>>(pair_hW, pwHi);
    pack_triWT_kernel<<<1536, 256>>>(tri_hW, twHi);
    pack_allWT_kernel<<<1024, 256>>>(all_hW, awHi);

    // 2) input projections (gate-permuted cols): Gx = (xHi+xLo) @ wihHi^T + pb
    gemm_fp16x2_kernel<<<dim3(8, 512), 256, SMEM_GEMM>>>(xHi, xLo, wHiF, pbF, GxF, EP);
    gemm_fp16x2_kernel<<<dim3(8, 512), 256, SMEM_GEMM>>>(xHi, xLo, wHiB, pbB, GxB, EP);

    // 3) zero segment-max keys
    zero_keys_kernel<<<32768, 256>>>(pk, tk);

    // 4) BiLSTM recurrence: persistent HMMA kernel (fp16 3-term)
    lstm_persist_kernel<<<dim3(8, 8, 2), 256, SMEM_LSTMP>>>(
        GxF, GxB, whF, wlF, whB, wlB, flHi, flLo);

    // 5) gather-GEMM-scatter: pair types + triples (fp16 1-term)
    for (int k = 0; k < 3; ++k)
        gemm_gsc_kernel<<<dim3(4, MTILES), 256, SMEM_GSC>>>(
            flHi, pwHi + (size_t)k * D2H * G4,
            occ1 + k * MM, occ2 + k * MM, occ1 + k * MM,
            seg + k * MM, pk + (size_t)k * CC * D2H, G4);
    gemm_gsc_kernel<<<dim3(4, MTILES), 256, SMEM_GSC>>>(
        flHi, twHi, tri_o1, tri_o2, tri_o3, tri_seg, tk, 1536);

    // 6) finalize pooled vectors (+ pair logits)
    pair_final_kernel<<<3 * CC, 256>>>(pk, pair_hb, pair_bo, pair_oW, pair_ob, pv, out);
    tri_final_kernel<<<CC, 256>>>(tk, tri_hb, tri_bo, tv);

    // 7) final MLP + triple logits (fp16 2-term)
    gather_feats_kernel<<<CC, 256>>>(pv, tv, tri_pi, ftHi, ftLo);
    gemm_fp16x2_kernel<<<dim3(D2H / 128, CC / 128), 256, SMEM_GEMM>>>(
        ftHi, ftLo, awHi, all_hb, fin, 2048);
    triple_logit_kernel<<<CC, 256>>>(fin, out_tW, out_tb, out);
}

// round 12
// speedup vs baseline: 2.9642x; 1.1036x over previous
#include <cuda_runtime.h>
#include <cuda_fp16.h>
#include <math.h>
#include <stdint.h>

// ---------------------------------------------------------------------------
// Problem constants
// ---------------------------------------------------------------------------
#define TT   256
#define PP   256
#define EE   300
#define HH   256
#define NPOS 65536            // T*P
#define G4   1024             // 4H
#define D2H  512              // 2H
#define MM   50000
#define CC   16384
#define EP   320              // E padded to multiple of 32
#define MTILES ((MM + 127) / 128)   // 391

// ---------------------------------------------------------------------------
// Device scratch (static allocations only)
// ---------------------------------------------------------------------------
__device__ float    g_GxF[(size_t)NPOS * G4];          // 268 MB (cols j*4+g)
__device__ float    g_GxB[(size_t)NPOS * G4];          // 268 MB
__device__ unsigned g_pairKeys[(size_t)3 * CC * D2H];  // 100 MB
__device__ unsigned g_triKeys[(size_t)CC * D2H];       // 33 MB
__device__ float    g_pv[(size_t)3 * CC * D2H];        // 100 MB
__device__ float    g_tv[(size_t)CC * D2H];            // 33 MB
__device__ float    g_final[(size_t)CC * D2H];         // 33 MB
__device__ float    g_pbF[G4];                         // permuted biases
__device__ float    g_pbB[G4];
__device__ unsigned g_barCnt[16];                      // per (dir,ptile) barrier
__device__ unsigned g_barGen[16];

// fp16 operand buffers
__device__ __half g_xHi[(size_t)NPOS * EP];            // 42 MB (hi only)
__device__ __half g_wHiF[(size_t)G4 * EP];             // packed rows j*4+g
__device__ __half g_wHiB[(size_t)G4 * EP];
__device__ __half g_whhHiF[(size_t)G4 * HH];           // packed rows j*4+g
__device__ __half g_whhLoF[(size_t)G4 * HH];
__device__ __half g_whhHiB[(size_t)G4 * HH];
__device__ __half g_whhLoB[(size_t)G4 * HH];
__device__ __half g_flatHi[(size_t)NPOS * D2H];        // 67 MB
__device__ __half g_flatLo[(size_t)NPOS * D2H];        // used by LSTM only
__device__ __half g_pwHi[(size_t)3 * D2H * G4];        // pairWT [3][512][1024]
__device__ __half g_twHi[(size_t)D2H * 1536];          // triWT [512][1536]
__device__ __half g_aWHi[(size_t)D2H * 2048];
__device__ __half g_ftHi[(size_t)CC * 2048];           // 67 MB (hi only)

// ---------------------------------------------------------------------------
// Helpers
// ---------------------------------------------------------------------------
__device__ __forceinline__ uint32_t smem_u32(const void* p) {
    uint32_t a;
    asm("{ .reg .u64 t; cvta.to.shared.u64 t, %1; cvt.u32.u64 %0, t; }"
        : "=r"(a) : "l"(p));
    return a;
}

#define LDSM_X4(r, addr) \
    asm volatile("ldmatrix.sync.aligned.m8n8.x4.shared.b16 {%0,%1,%2,%3}, [%4];" \
        : "=r"((r)[0]), "=r"((r)[1]), "=r"((r)[2]), "=r"((r)[3]) : "r"(addr))

#define MMA_FP16(d, a, b) \
    asm volatile("mma.sync.aligned.m16n8k16.row.col.f32.f16.f16.f32 " \
        "{%0,%1,%2,%3}, {%4,%5,%6,%7}, {%8,%9}, {%0,%1,%2,%3};" \
        : "+f"((d)[0]), "+f"((d)[1]), "+f"((d)[2]), "+f"((d)[3]) \
        : "r"((a)[0]), "r"((a)[1]), "r"((a)[2]), "r"((a)[3]), \
          "r"((b)[0]), "r"((b)[1]))

#define CP_ASYNC16(dst, src) \
    asm volatile("cp.async.cg.shared.global [%0], [%1], 16;" \
                 :: "r"(dst), "l"(src))
#define CP_COMMIT() asm volatile("cp.async.commit_group;" ::: "memory")
#define CP_WAIT(n)  asm volatile("cp.async.wait_group %0;" :: "n"(n) : "memory")

__device__ __forceinline__ float sigmoidf_(float x) { return 1.0f / (1.0f + expf(-x)); }

__device__ __forceinline__ unsigned fmap(float f) {
    unsigned b = __float_as_uint(f);
    return (b & 0x80000000u) ? ~b : (b | 0x80000000u);
}
__device__ __forceinline__ float funmap(unsigned u) {
    return (u & 0x80000000u) ? __uint_as_float(u & 0x7FFFFFFFu)
                             : __uint_as_float(~u);
}
__device__ __forceinline__ float warpReduceSum(float v) {
    #pragma unroll
    for (int o = 16; o > 0; o >>= 1) v += __shfl_down_sync(0xffffffffu, v, o);
    return v;
}
__device__ __forceinline__ float blockReduceSum256(float v) {
    __shared__ float sh[8];
    int lane = threadIdx.x & 31, wid = threadIdx.x >> 5;
    v = warpReduceSum(v);
    if (lane == 0) sh[wid] = v;
    __syncthreads();
    v = (threadIdx.x < 8) ? sh[threadIdx.x] : 0.0f;
    if (wid == 0) v = warpReduceSum(v);
    return v;
}
__device__ __forceinline__ void splith(float f, __half& h, __half& l) {
    h = __float2half(f);
    l = __float2half(f - __half2float(h));
}

// per-(dir,ptile) group barrier
__device__ __forceinline__ void group_barrier(int bidx, int tid, unsigned nCTA) {
    __syncthreads();
    if (tid == 0) {
        __threadfence();
        unsigned gen = atomicAdd(&g_barGen[bidx], 0u);
        unsigned prev = atomicAdd(&g_barCnt[bidx], 1u);
        if (prev == nCTA - 1u) {
            atomicExch(&g_barCnt[bidx], 0u);
            __threadfence();
            atomicAdd(&g_barGen[bidx], 1u);
        } else {
            while (atomicAdd(&g_barGen[bidx], 0u) == gen) { __nanosleep(32); }
        }
        __threadfence();
    }
    __syncthreads();
}

// ---------------------------------------------------------------------------
// fp16 1-term GEMM: C[M,N] = Ahi[M,K] @ Bhi[N,K]^T + bias
// CTA tile 128x128, 256 threads (8 warps: 2 M x 4 N; warp tile 64x32).
// 2-stage cp.async pipeline, K-chunk = 32. RSZ=80 (conflict-free ldmatrix).
// ---------------------------------------------------------------------------
#define RSZ   80
#define TILEB (128 * RSZ)       // 10240
#define STAGE2 (2 * TILEB)      // 20480 (Ahi, Bhi)
#define SMEM_G1 (2 * STAGE2)    // 40960

__global__ __launch_bounds__(256, 2)
void gemm_fp16x1_kernel(const __half* __restrict__ Ahi,
                        const __half* __restrict__ Bhi,
                        const float* __restrict__ bias,
                        float* __restrict__ C, int K) {
    extern __shared__ char smem[];
    const uint32_t sb = smem_u32(smem);
    const int tid = threadIdx.x, lane = tid & 31, wid = tid >> 5;
    const int m0 = blockIdx.y * 128, n0 = blockIdx.x * 128;
    const int ldc = gridDim.x * 128;
    const int wm = wid & 1, wn = wid >> 1;

    float acc[4][4][4];
    #pragma unroll
    for (int i = 0; i < 4; ++i)
        #pragma unroll
        for (int j = 0; j < 4; ++j)
            #pragma unroll
            for (int q = 0; q < 4; ++q) acc[i][j][q] = 0.0f;

    const int nch = K >> 5;
    const int r0c = (2 * tid) >> 2, ch0 = (2 * tid) & 3;
    const int r1c = (2 * tid + 1) >> 2, ch1 = (2 * tid + 1) & 3;
    const int rA = lane & 15;
    const int cA = lane >> 4;

    #define LOAD_STAGE(cc)                                                      \
    do {                                                                        \
        const int kb = (cc) << 5;                                               \
        const uint32_t dst = sb + ((cc) & 1) * STAGE2;                          \
        CP_ASYNC16(dst + 0 * TILEB + r0c * RSZ + ch0 * 16,                      \
                   Ahi + (size_t)(m0 + r0c) * K + kb + ch0 * 8);                \
        CP_ASYNC16(dst + 0 * TILEB + r1c * RSZ + ch1 * 16,                      \
                   Ahi + (size_t)(m0 + r1c) * K + kb + ch1 * 8);                \
        CP_ASYNC16(dst + 1 * TILEB + r0c * RSZ + ch0 * 16,                      \
                   Bhi + (size_t)(n0 + r0c) * K + kb + ch0 * 8);                \
        CP_ASYNC16(dst + 1 * TILEB + r1c * RSZ + ch1 * 16,                      \
                   Bhi + (size_t)(n0 + r1c) * K + kb + ch1 * 8);                \
        CP_COMMIT();                                                            \
    } while (0)

    LOAD_STAGE(0);

    for (int c = 0; c < nch; ++c) {
        if (c + 1 < nch) { LOAD_STAGE(c + 1); CP_WAIT(1); }
        else             { CP_WAIT(0); }
        __syncthreads();

        const uint32_t s = sb + (c & 1) * STAGE2;
        const uint32_t aHiB = s, bHiB = s + TILEB;

        #pragma unroll
        for (int ks = 0; ks < 2; ++ks) {
            const uint32_t colOff = (uint32_t)(ks * 2 + cA) * 16;
            uint32_t aHi[4][4], bHi[4][2];
            #pragma unroll
            for (int mt = 0; mt < 4; ++mt) {
                uint32_t ad = (uint32_t)(wm * 64 + mt * 16 + rA) * RSZ + colOff;
                LDSM_X4(aHi[mt], aHiB + ad);
            }
            #pragma unroll
            for (int nh = 0; nh < 2; ++nh) {
                uint32_t bd = (uint32_t)(wn * 32 + nh * 16 + rA) * RSZ + colOff;
                uint32_t t[4];
                LDSM_X4(t, bHiB + bd);
                bHi[nh * 2 + 0][0] = t[0]; bHi[nh * 2 + 0][1] = t[2];
                bHi[nh * 2 + 1][0] = t[1]; bHi[nh * 2 + 1][1] = t[3];
            }
            #pragma unroll
            for (int mt = 0; mt < 4; ++mt)
                #pragma unroll
                for (int nt = 0; nt < 4; ++nt)
                    MMA_FP16(acc[mt][nt], aHi[mt], bHi[nt]);
        }
        __syncthreads();
    }

    const int rr = lane >> 2, cc2 = (lane & 3) * 2;
    #pragma unroll
    for (int mt = 0; mt < 4; ++mt) {
        #pragma unroll
        for (int nt = 0; nt < 4; ++nt) {
            int row = m0 + wm * 64 + mt * 16 + rr;
            int col = n0 + wn * 32 + nt * 8 + cc2;
            float b0 = 0.f, b1 = 0.f;
            if (bias) { b0 = bias[col]; b1 = bias[col + 1]; }
            float2 v0 = make_float2(acc[mt][nt][0] + b0, acc[mt][nt][1] + b1);
            float2 v1 = make_float2(acc[mt][nt][2] + b0, acc[mt][nt][3] + b1);
            *(float2*)&C[(size_t)row * ldc + col] = v0;
            *(float2*)&C[(size_t)(row + 8) * ldc + col] = v1;
        }
    }
    #undef LOAD_STAGE
}

// ---------------------------------------------------------------------------
// Gather-GEMM-scatter (fp16 1-term): rep[m] = concat(flatHi[occ..]) @ Bhi^T,
// then atomicMax into keys[seg[m]] (fmap-encoded).
// ---------------------------------------------------------------------------
__global__ __launch_bounds__(256, 2)
void gemm_gsc_kernel(const __half* __restrict__ flatHi,
                     const __half* __restrict__ Bhi,
                     const int* __restrict__ occ1,
                     const int* __restrict__ occ2,
                     const int* __restrict__ occ3,
                     const int* __restrict__ seg,
                     unsigned* __restrict__ keys, int K) {
    extern __shared__ char smem[];
    const uint32_t sb = smem_u32(smem);
    const int tid = threadIdx.x, lane = tid & 31, wid = tid >> 5;
    const int m0 = blockIdx.y * 128, n0 = blockIdx.x * 128;
    const int wm = wid & 1, wn = wid >> 1;

    float acc[4][4][4];
    #pragma unroll
    for (int i = 0; i < 4; ++i)
        #pragma unroll
        for (int j = 0; j < 4; ++j)
            #pragma unroll
            for (int q = 0; q < 4; ++q) acc[i][j][q] = 0.0f;

    const int nch = K >> 5;
    const int r0c = (2 * tid) >> 2, ch0 = (2 * tid) & 3;
    const int r1c = (2 * tid + 1) >> 2, ch1 = (2 * tid + 1) & 3;
    const int rA = lane & 15;
    const int cA = lane >> 4;

    const int mC0 = (m0 + r0c < MM) ? (m0 + r0c) : (MM - 1);
    const int mC1 = (m0 + r1c < MM) ? (m0 + r1c) : (MM - 1);
    int ia0[3], ia1[3];
    ia0[0] = occ1[mC0]; ia1[0] = occ1[mC1];
    ia0[1] = occ2[mC0]; ia1[1] = occ2[mC1];
    ia0[2] = (K > 1024) ? occ3[mC0] : 0;
    ia1[2] = (K > 1024) ? occ3[mC1] : 0;

    #define LOAD_STAGE_G(cc)                                                    \
    do {                                                                        \
        const int kb = (cc) << 5;                                               \
        const int sg_ = kb >> 9;                                                \
        const int ck = kb & 511;                                                \
        const uint32_t dst = sb + ((cc) & 1) * STAGE2;                          \
        CP_ASYNC16(dst + 0 * TILEB + r0c * RSZ + ch0 * 16,                      \
                   flatHi + (size_t)ia0[sg_] * D2H + ck + ch0 * 8);             \
        CP_ASYNC16(dst + 0 * TILEB + r1c * RSZ + ch1 * 16,                      \
                   flatHi + (size_t)ia1[sg_] * D2H + ck + ch1 * 8);             \
        CP_ASYNC16(dst + 1 * TILEB + r0c * RSZ + ch0 * 16,                      \
                   Bhi + (size_t)(n0 + r0c) * K + kb + ch0 * 8);                \
        CP_ASYNC16(dst + 1 * TILEB + r1c * RSZ + ch1 * 16,                      \
                   Bhi + (size_t)(n0 + r1c) * K + kb + ch1 * 8);                \
        CP_COMMIT();                                                            \
    } while (0)

    LOAD_STAGE_G(0);

    for (int c = 0; c < nch; ++c) {
        if (c + 1 < nch) { LOAD_STAGE_G(c + 1); CP_WAIT(1); }
        else             { CP_WAIT(0); }
        __syncthreads();

        const uint32_t s = sb + (c & 1) * STAGE2;
        const uint32_t aHiB = s, bHiB = s + TILEB;

        #pragma unroll
        for (int ks = 0; ks < 2; ++ks) {
            const uint32_t colOff = (uint32_t)(ks * 2 + cA) * 16;
            uint32_t aHi[4][4], bHi[4][2];
            #pragma unroll
            for (int mt = 0; mt < 4; ++mt) {
                uint32_t ad = (uint32_t)(wm * 64 + mt * 16 + rA) * RSZ + colOff;
                LDSM_X4(aHi[mt], aHiB + ad);
            }
            #pragma unroll
            for (int nh = 0; nh < 2; ++nh) {
                uint32_t bd = (uint32_t)(wn * 32 + nh * 16 + rA) * RSZ + colOff;
                uint32_t t[4];
                LDSM_X4(t, bHiB + bd);
                bHi[nh * 2 + 0][0] = t[0]; bHi[nh * 2 + 0][1] = t[2];
                bHi[nh * 2 + 1][0] = t[1]; bHi[nh * 2 + 1][1] = t[3];
            }
            #pragma unroll
            for (int mt = 0; mt < 4; ++mt)
                #pragma unroll
                for (int nt = 0; nt < 4; ++nt)
                    MMA_FP16(acc[mt][nt], aHi[mt], bHi[nt]);
        }
        __syncthreads();
    }

    // ---- epilogue: fmap + atomicMax scatter into segment keys ----
    const int rr = lane >> 2, cc2 = (lane & 3) * 2;
    #pragma unroll
    for (int mt = 0; mt < 4; ++mt) {
        int rowL = wm * 64 + mt * 16 + rr;
        int mA = m0 + rowL, mB = mA + 8;
        int sgA = (mA < MM) ? seg[mA] : -1;
        int sgB = (mB < MM) ? seg[mB] : -1;
        #pragma unroll
        for (int nt = 0; nt < 4; ++nt) {
            int col = n0 + wn * 32 + nt * 8 + cc2;
            if (sgA >= 0) {
                unsigned* d = keys + (size_t)sgA * D2H + col;
                atomicMax(d,     fmap(acc[mt][nt][0]));
                atomicMax(d + 1, fmap(acc[mt][nt][1]));
            }
            if (sgB >= 0) {
                unsigned* d = keys + (size_t)sgB * D2H + col;
                atomicMax(d,     fmap(acc[mt][nt][2]));
                atomicMax(d + 1, fmap(acc[mt][nt][3]));
            }
        }
    }
    #undef LOAD_STAGE_G
}

// ---------------------------------------------------------------------------
// Pack kernels
// ---------------------------------------------------------------------------
// convert/pad fp32 -> fp16 hi only
__global__ void convert_pad_kernel(const float* __restrict__ src,
                                   __half* __restrict__ hi,
                                   int rows, int sk, int dk) {
    size_t total = (size_t)rows * dk;
    for (size_t idx = blockIdx.x * (size_t)blockDim.x + threadIdx.x; idx < total;
         idx += (size_t)gridDim.x * blockDim.x) {
        int r = (int)(idx / dk), c = (int)(idx % dk);
        float f = (c < sk) ? src[(size_t)r * sk + c] : 0.0f;
        hi[idx] = __float2half(f);
    }
}

__global__ void pack_wih_kernel(const float* __restrict__ wih,
                                const float* __restrict__ b,
                                __half* __restrict__ hi,
                                float* __restrict__ pb) {
    const int total = G4 * EP;
    for (int idx = blockIdx.x * blockDim.x + threadIdx.x; idx < total;
         idx += gridDim.x * blockDim.x) {
        int rp = idx / EP, k = idx % EP;
        int j = rp >> 2, g = rp & 3;
        float f = (k < EE) ? wih[(size_t)(g * 256 + j) * EE + k] : 0.0f;
        hi[idx] = __float2half(f);
        if (k == 0) pb[rp] = b[g * 256 + j];
    }
}

__global__ void pack_whh_kernel(const float* __restrict__ whh,
                                __half* __restrict__ hi,
                                __half* __restrict__ lo) {
    const int total = G4 * HH;
    for (int idx = blockIdx.x * blockDim.x + threadIdx.x; idx < total;
         idx += gridDim.x * blockDim.x) {
        int rp = idx >> 8, k = idx & 255;
        int j = rp >> 2, g = rp & 3;
        float v = whh[(size_t)(g * 256 + j) * HH + k];
        __half h, l; splith(v, h, l);
        hi[idx] = h; lo[idx] = l;
    }
}

__global__ void pack_pairWT_kernel(const float* __restrict__ pair_hW,
                                   __half* __restrict__ hi) {
    const int total = 3 * D2H * G4;
    for (int idx = blockIdx.x * blockDim.x + threadIdx.x; idx < total;
         idx += gridDim.x * blockDim.x) {
        int k = idx / (D2H * G4);
        int rem = idx - k * (D2H * G4);
        int n = rem >> 10, kk = rem & 1023;
        hi[idx] = __float2half(pair_hW[(size_t)k * (G4 * D2H) + (size_t)kk * D2H + n]);
    }
}

__global__ void pack_triWT_kernel(const float* __restrict__ tri_hW,
                                  __half* __restrict__ hi) {
    const int total = D2H * 1536;
    for (int idx = blockIdx.x * blockDim.x + threadIdx.x; idx < total;
         idx += gridDim.x * blockDim.x) {
        int n = idx / 1536, kk = idx % 1536;
        hi[idx] = __float2half(tri_hW[(size_t)kk * D2H + n]);
    }
}

__global__ void pack_allWT_kernel(const float* __restrict__ all_hW,
                                  __half* __restrict__ hi) {
    const int total = D2H * 2048;
    for (int idx = blockIdx.x * blockDim.x + threadIdx.x; idx < total;
         idx += gridDim.x * blockDim.x) {
        int n = idx >> 11, k = idx & 2047;
        hi[idx] = __float2half(all_hW[(size_t)k * D2H + n]);
    }
}

__global__ void zero_keys_kernel(unsigned* __restrict__ pk, unsigned* __restrict__ tk) {
    const size_t np = (size_t)3 * CC * D2H;
    const size_t nt = (size_t)CC * D2H;
    for (size_t i = blockIdx.x * (size_t)blockDim.x + threadIdx.x; i < np + nt;
         i += (size_t)gridDim.x * blockDim.x) {
        if (i < np) pk[i] = 0u; else tk[i - np] = 0u;
    }
}

// ---------------------------------------------------------------------------
// Persistent HMMA BiLSTM recurrence (fp16 3-term; 8-CTA group barriers,
// Gx prefetched at step start).
// ---------------------------------------------------------------------------
#define PRSZ   528
#define LP_AHI 0
#define LP_ALO 16896
#define LP_BHI 33792
#define LP_BLO 101376
#define SMEM_LSTMP 168960

__global__ __launch_bounds__(256, 1)
void lstm_persist_kernel(const float* __restrict__ GxF,
                         const float* __restrict__ GxB,
                         const __half* __restrict__ whhHiF,
                         const __half* __restrict__ whhLoF,
                         const __half* __restrict__ whhHiB,
                         const __half* __restrict__ whhLoB,
                         __half* __restrict__ flatHi,
                         __half* __restrict__ flatLo) {
    extern __shared__ char smem[];
    const uint32_t sb = smem_u32(smem);
    const int tid = threadIdx.x, lane = tid & 31, wid = tid >> 5;
    const int dir = blockIdx.z;
    const int p0 = blockIdx.x * 32;
    const int c0 = blockIdx.y * 128;
    const int hcol = dir * HH;
    const int bidx = dir * 8 + blockIdx.x;
    const float* Gx = dir ? GxB : GxF;
    const __half* Whi = dir ? whhHiB : whhHiF;
    const __half* Wlo = dir ? whhLoB : whhLoF;

    for (int ch = tid; ch < 128 * 32; ch += 256) {
        int row = ch >> 5, cb = ch & 31;
        size_t src = (size_t)(c0 + row) * HH + cb * 8;
        CP_ASYNC16(sb + LP_BHI + row * PRSZ + cb * 16, Whi + src);
        CP_ASYNC16(sb + LP_BLO + row * PRSZ + cb * 16, Wlo + src);
    }
    CP_COMMIT(); CP_WAIT(0);
    __syncthreads();

    float creg[2][2] = {{0.f, 0.f}, {0.f, 0.f}};
    const int rr = lane >> 2, cc2 = (lane & 3) * 2;
    const bool evenT = ((lane & 1) == 0);

    for (int s = 0; s < TT; ++s) {
        const int tcur = dir ? (TT - 1 - s) : s;

        // ---- prefetch Gx for this step (independent of h; hides DRAM lat)
        float2 gpre[2][2][2];
        #pragma unroll
        for (int mt = 0; mt < 2; ++mt) {
            #pragma unroll
            for (int nt = 0; nt < 2; ++nt) {
                int prow = p0 + mt * 16 + rr;
                int col = c0 + wid * 16 + nt * 8 + cc2;
                size_t n0i = (size_t)tcur * PP + prow;
                gpre[mt][nt][0] = *(const float2*)&Gx[n0i * G4 + col];
                gpre[mt][nt][1] = *(const float2*)&Gx[(n0i + 8) * G4 + col];
            }
        }

        float acc[2][2][4];
        #pragma unroll
        for (int i = 0; i < 2; ++i)
            #pragma unroll
            for (int j = 0; j < 2; ++j)
                #pragma unroll
                for (int q = 0; q < 4; ++q) acc[i][j][q] = 0.0f;

        if (s > 0) {
            group_barrier(bidx, tid, 8u);

            const int nprev = dir ? (tcur + 1) : (tcur - 1);
            for (int ch = tid; ch < 32 * 32; ch += 256) {
                int row = ch >> 5, cb = ch & 31;
                size_t src = (size_t)(nprev * PP + p0 + row) * D2H + hcol + cb * 8;
                CP_ASYNC16(sb + LP_AHI + row * PRSZ + cb * 16, flatHi + src);
                CP_ASYNC16(sb + LP_ALO + row * PRSZ + cb * 16, flatLo + src);
            }
            CP_COMMIT(); CP_WAIT(0);
            __syncthreads();

            #pragma unroll 4
            for (int kc = 0; kc < 16; ++kc) {
                const uint32_t colOff = (uint32_t)kc * 32 + (uint32_t)(lane >> 4) * 16;
                uint32_t aHi[2][4], bHi[2][2];
                #pragma unroll
                for (int mt = 0; mt < 2; ++mt) {
                    uint32_t ad = (uint32_t)(mt * 16 + (lane & 15)) * PRSZ + colOff;
                    LDSM_X4(aHi[mt], sb + LP_AHI + ad);
                }
                {
                    uint32_t bd = (uint32_t)(wid * 16 + (lane & 15)) * PRSZ + colOff;
                    uint32_t t[4];
                    LDSM_X4(t, sb + LP_BHI + bd);
                    bHi[0][0] = t[0]; bHi[0][1] = t[2];
                    bHi[1][0] = t[1]; bHi[1][1] = t[3];
                }
                #pragma unroll
                for (int mt = 0; mt < 2; ++mt)
                    #pragma unroll
                    for (int nt = 0; nt < 2; ++nt)
                        MMA_FP16(acc[mt][nt], aHi[mt], bHi[nt]);
                {
                    uint32_t aLo[2][4];
                    #pragma unroll
                    for (int mt = 0; mt < 2; ++mt) {
                        uint32_t ad = (uint32_t)(mt * 16 + (lane & 15)) * PRSZ + colOff;
                        LDSM_X4(aLo[mt], sb + LP_ALO + ad);
                    }
                    #pragma unroll
                    for (int mt = 0; mt < 2; ++mt)
                        #pragma unroll
                        for (int nt = 0; nt < 2; ++nt)
                            MMA_FP16(acc[mt][nt], aLo[mt], bHi[nt]);
                }
                {
                    uint32_t bLo[2][2];
                    uint32_t bd = (uint32_t)(wid * 16 + (lane & 15)) * PRSZ + colOff;
                    uint32_t t[4];
                    LDSM_X4(t, sb + LP_BLO + bd);
                    bLo[0][0] = t[0]; bLo[0][1] = t[2];
                    bLo[1][0] = t[1]; bLo[1][1] = t[3];
                    #pragma unroll
                    for (int mt = 0; mt < 2; ++mt)
                        #pragma unroll
                        for (int nt = 0; nt < 2; ++nt)
                            MMA_FP16(acc[mt][nt], aHi[mt], bLo[nt]);
                }
            }
        }

        #pragma unroll
        for (int mt = 0; mt < 2; ++mt) {
            #pragma unroll
            for (int nt = 0; nt < 2; ++nt) {
                int prow = p0 + mt * 16 + rr;
                int col = c0 + wid * 16 + nt * 8 + cc2;
                int j = col >> 2;
                float2 g0 = gpre[mt][nt][0];
                float2 g1 = gpre[mt][nt][1];
                float v0 = acc[mt][nt][0] + g0.x;
                float v1 = acc[mt][nt][1] + g0.y;
                float v2 = acc[mt][nt][2] + g1.x;
                float v3 = acc[mt][nt][3] + g1.y;
                float w0 = __shfl_xor_sync(0xffffffffu, v0, 1);
                float w1 = __shfl_xor_sync(0xffffffffu, v1, 1);
                float w2 = __shfl_xor_sync(0xffffffffu, v2, 1);
                float w3 = __shfl_xor_sync(0xffffffffu, v3, 1);
                float I, F, G, O;
                int p;
                if (evenT) { I = v0; F = v1; G = w0; O = w1; p = prow; }
                else       { I = w2; F = w3; G = v2; O = v3; p = prow + 8; }
                float cold = creg[mt][nt];
                float cn = sigmoidf_(F) * cold + sigmoidf_(I) * tanhf(G);
                float h = sigmoidf_(O) * tanhf(cn);
                creg[mt][nt] = cn;
                size_t nn = (size_t)tcur * PP + p;
                __half hh, hl; splith(h, hh, hl);
                flatHi[nn * D2H + hcol + j] = hh;
                flatLo[nn * D2H + hcol + j] = hl;
            }
        }
        __syncthreads();
    }
}

// ---------------------------------------------------------------------------
// Finalize kernels
// ---------------------------------------------------------------------------
__global__ __launch_bounds__(256)
void pair_final_kernel(const unsigned* __restrict__ keys,
                       const float* __restrict__ hb,
                       const float* __restrict__ backoff,
                       const float* __restrict__ oW,
                       const float* __restrict__ ob,
                       float* __restrict__ pv, float* __restrict__ out) {
    const int b = blockIdx.x;
    const int k = b >> 14;
    const unsigned* src = keys + (size_t)b * D2H;
    float partial = 0.0f;
    #pragma unroll
    for (int it = 0; it < 2; ++it) {
        int c = threadIdx.x + it * 256;
        unsigned u = src[c];
        float val = u ? (funmap(u) + hb[k * D2H + c]) : backoff[k * D2H + c];
        float t = tanhf(val);
        pv[(size_t)b * D2H + c] = t;
        partial += t * oW[k * D2H + c];
    }
    float tot = blockReduceSum256(partial);
    if (threadIdx.x == 0) out[CC + b] = tot + ob[k];
}

__global__ __launch_bounds__(256)
void tri_final_kernel(const unsigned* __restrict__ keys,
                      const float* __restrict__ hb,
                      const float* __restrict__ backoff,
                      float* __restrict__ tv) {
    const int s = blockIdx.x;
    const unsigned* src = keys + (size_t)s * D2H;
    #pragma unroll
    for (int it = 0; it < 2; ++it) {
        int c = threadIdx.x + it * 256;
        unsigned u = src[c];
        float val = u ? (funmap(u) + hb[c]) : backoff[c];
        tv[(size_t)s * D2H + c] = tanhf(val);
    }
}

// gather 8H features (fp16 hi only)
__global__ void gather_feats_kernel(const float* __restrict__ pv,
                                    const float* __restrict__ tv,
                                    const int* __restrict__ tpi,
                                    __half* __restrict__ fhi) {
    const int s = blockIdx.x;
    const int i0 = tpi[s * 3 + 0];
    const int i1 = tpi[s * 3 + 1];
    const int i2 = tpi[s * 3 + 2];
    for (int j = threadIdx.x; j < 2048; j += blockDim.x) {
        int q = j >> 9, c = j & 511;
        float v;
        if (q == 0)      v = pv[((size_t)2 * CC + i0) * D2H + c];
        else if (q == 1) v = pv[((size_t)1 * CC + i1) * D2H + c];
        else if (q == 2) v = pv[(size_t)i2 * D2H + c];
        else             v = tv[(size_t)s * D2H + c];
        fhi[(size_t)s * 2048 + j] = __float2half(v);
    }
}

__global__ __launch_bounds__(256)
void triple_logit_kernel(const float* __restrict__ fin,
                         const float* __restrict__ tW,
                         const float* __restrict__ tb,
                         float* __restrict__ out) {
    const int s = blockIdx.x;
    float partial = 0.0f;
    #pragma unroll
    for (int it = 0; it < 2; ++it) {
        int c = threadIdx.x + it * 256;
        float v = fin[(size_t)s * D2H + c];
        v = v > 0.0f ? v : 0.0f;
        partial += v * tW[c];
    }
    float tot = blockReduceSum256(partial);
    if (threadIdx.x == 0) out[s] = tot + tb[0];
}

// ---------------------------------------------------------------------------
// Launcher
// ---------------------------------------------------------------------------
extern "C" void kernel_launch(void* const* d_in, const int* in_sizes, int n_in,
                              void* d_out, int out_size) {
    const float* x        = (const float*)d_in[0];
    const float* wih_f    = (const float*)d_in[1];
    const float* whh_f    = (const float*)d_in[2];
    const float* b_f      = (const float*)d_in[3];
    const float* wih_b    = (const float*)d_in[4];
    const float* whh_b    = (const float*)d_in[5];
    const float* b_b      = (const float*)d_in[6];
    const float* pair_hW  = (const float*)d_in[7];
    const float* pair_hb  = (const float*)d_in[8];
    const float* pair_oW  = (const float*)d_in[9];
    const float* pair_ob  = (const float*)d_in[10];
    const float* pair_bo  = (const float*)d_in[11];
    const float* tri_hW   = (const float*)d_in[12];
    const float* tri_hb   = (const float*)d_in[13];
    const float* tri_bo   = (const float*)d_in[14];
    const float* all_hW   = (const float*)d_in[15];
    const float* all_hb   = (const float*)d_in[16];
    const float* out_tW   = (const float*)d_in[17];
    const float* out_tb   = (const float*)d_in[18];
    const int*   occ1     = (const int*)d_in[19];
    const int*   occ2     = (const int*)d_in[20];
    const int*   seg      = (const int*)d_in[21];
    const int*   tri_o1   = (const int*)d_in[22];
    const int*   tri_o2   = (const int*)d_in[23];
    const int*   tri_o3   = (const int*)d_in[24];
    const int*   tri_seg  = (const int*)d_in[25];
    const int*   tri_pi   = (const int*)d_in[26];
    float* out = (float*)d_out;

    float *GxF, *GxB, *pv, *tv, *fin, *pbF, *pbB;
    unsigned *pk, *tk;
    __half *xHi, *wHiF, *wHiB, *flHi, *flLo;
    __half *whF, *wlF, *whB, *wlB;
    __half *pwHi, *twHi, *awHi, *ftHi;
    cudaGetSymbolAddress((void**)&GxF,  g_GxF);
    cudaGetSymbolAddress((void**)&GxB,  g_GxB);
    cudaGetSymbolAddress((void**)&pk,   g_pairKeys);
    cudaGetSymbolAddress((void**)&tk,   g_triKeys);
    cudaGetSymbolAddress((void**)&pv,   g_pv);
    cudaGetSymbolAddress((void**)&tv,   g_tv);
    cudaGetSymbolAddress((void**)&fin,  g_final);
    cudaGetSymbolAddress((void**)&pbF,  g_pbF);
    cudaGetSymbolAddress((void**)&pbB,  g_pbB);
    cudaGetSymbolAddress((void**)&xHi,  g_xHi);
    cudaGetSymbolAddress((void**)&wHiF, g_wHiF);
    cudaGetSymbolAddress((void**)&wHiB, g_wHiB);
    cudaGetSymbolAddress((void**)&whF,  g_whhHiF);
    cudaGetSymbolAddress((void**)&wlF,  g_whhLoF);
    cudaGetSymbolAddress((void**)&whB,  g_whhHiB);
    cudaGetSymbolAddress((void**)&wlB,  g_whhLoB);
    cudaGetSymbolAddress((void**)&flHi, g_flatHi);
    cudaGetSymbolAddress((void**)&flLo, g_flatLo);
    cudaGetSymbolAddress((void**)&pwHi, g_pwHi);
    cudaGetSymbolAddress((void**)&twHi, g_twHi);
    cudaGetSymbolAddress((void**)&awHi, g_aWHi);
    cudaGetSymbolAddress((void**)&ftHi, g_ftHi);

    cudaFuncSetAttribute(gemm_fp16x1_kernel,
                         cudaFuncAttributeMaxDynamicSharedMemorySize, SMEM_G1);
    cudaFuncSetAttribute(gemm_gsc_kernel,
                         cudaFuncAttributeMaxDynamicSharedMemorySize, SMEM_G1);
    cudaFuncSetAttribute(lstm_persist_kernel,
                         cudaFuncAttributeMaxDynamicSharedMemorySize, SMEM_LSTMP);

    // 1) convert/pack operands (fp16)
    convert_pad_kernel<<<4096, 256>>>(x, xHi, NPOS, EE, EP);
    pack_wih_kernel<<<512, 256>>>(wih_f, b_f, wHiF, pbF);
    pack_wih_kernel<<<512, 256>>>(wih_b, b_b, wHiB, pbB);
    pack_whh_kernel<<<512, 256>>>(whh_f, whF, wlF);
    pack_whh_kernel<<<512, 256>>>(whh_b, whB, wlB);
    pack_pairWT_kernel<<<3072, 256>>>(pair_hW, pwHi);
    pack_triWT_kernel<<<1536, 256>>>(tri_hW, twHi);
    pack_allWT_kernel<<<1024, 256>>>(all_hW, awHi);

    // 2) input projections (gate-permuted cols): Gx = xHi @ wihHi^T + pb
    gemm_fp16x1_kernel<<<dim3(8, 512), 256, SMEM_G1>>>(xHi, wHiF, pbF, GxF, EP);
    gemm_fp16x1_kernel<<<dim3(8, 512), 256, SMEM_G1>>>(xHi, wHiB, pbB, GxB, EP);

    // 3) zero segment-max keys
    zero_keys_kernel<<<32768, 256>>>(pk, tk);

    // 4) BiLSTM recurrence: persistent HMMA kernel (fp16 3-term)
    lstm_persist_kernel<<<dim3(8, 8, 2), 256, SMEM_LSTMP>>>(
        GxF, GxB, whF, wlF, whB, wlB, flHi, flLo);

    // 5) gather-GEMM-scatter: pair types + triples (fp16 1-term)
    for (int k = 0; k < 3; ++k)
        gemm_gsc_kernel<<<dim3(4, MTILES), 256, SMEM_G1>>>(
            flHi, pwHi + (size_t)k * D2H * G4,
            occ1 + k * MM, occ2 + k * MM, occ1 + k * MM,
            seg + k * MM, pk + (size_t)k * CC * D2H, G4);
    gemm_gsc_kernel<<<dim3(4, MTILES), 256, SMEM_G1>>>(
        flHi, twHi, tri_o1, tri_o2, tri_o3, tri_seg, tk, 1536);

    // 6) finalize pooled vectors (+ pair logits)
    pair_final_kernel<<<3 * CC, 256>>>(pk, pair_hb, pair_bo, pair_oW, pair_ob, pv, out);
    tri_final_kernel<<<CC, 256>>>(tk, tri_hb, tri_bo, tv);

    // 7) final MLP + triple logits (fp16 1-term)
    gather_feats_kernel<<<CC, 256>>>(pv, tv, tri_pi, ftHi);
    gemm_fp16x1_kernel<<<dim3(D2H / 128, CC / 128), 256, SMEM_G1>>>(
        ftHi, awHi, all_hb, fin, 2048);
    triple_logit_kernel<<<CC, 256>>>(fin, out_tW, out_tb, out);
}